// round 1
// baseline (speedup 1.0000x reference)
#include <cuda_runtime.h>
#include <math.h>

// Problem constants
#define B_  256
#define T_  128
#define DW_ 768
#define DH_ 768
#define G_  3072   // 4*DH

// ---------------- scratch (device globals; no allocation in kernel_launch) ---
__device__ float g_x[(size_t)B_*T_*DW_];      // gathered word embeddings
__device__ float g_tx[B_*DW_];                // gathered target embeddings
__device__ float g_txp[B_*G_];                // tx @ W_ih_bot + b_lstm
__device__ float g_gin[(size_t)B_*T_*G_];     // x @ W_ih_top + txp  (402 MB)
__device__ float g_h[B_*DH_];
__device__ float g_c[B_*DH_];
__device__ float g_gates[B_*G_];
__device__ float g_H[(size_t)B_*T_*DH_];      // hidden states (100 MB)
__device__ float g_scores[B_*T_];
__device__ float g_alpha[B_*T_];
__device__ float g_r[B_*DH_];
__device__ float g_tmp[B_*DH_];
__device__ float g_hstar[B_*DH_];

__device__ __forceinline__ float sigf(float x) { return 1.0f / (1.0f + expf(-x)); }

// ---------------- gather: x = emb[sent], tx = temb[target] ------------------
__global__ void gather_kernel(const int* __restrict__ sent,
                              const int* __restrict__ target,
                              const float* __restrict__ emb,
                              const float* __restrict__ temb) {
    int row = blockIdx.x;
    int tid = threadIdx.x;  // 192 threads, 192 float4 = 768 floats
    const float4* src;
    float4* dst;
    if (row < B_ * T_) {
        src = (const float4*)(emb + (size_t)sent[row] * DW_);
        dst = (float4*)(g_x + (size_t)row * DW_);
    } else {
        int rb = row - B_ * T_;
        src = (const float4*)(temb + (size_t)target[rb] * DW_);
        dst = (float4*)(g_tx + (size_t)rb * DW_);
    }
    dst[tid] = src[tid];
}

__global__ void zero_kernel(float* p, int n) {
    int i = blockIdx.x * blockDim.x + threadIdx.x;
    if (i < n) p[i] = 0.0f;
}

// ---------------- templated SGEMM with fused epilogues -----------------------
// MODE 0: C = acc
// MODE 1: C = acc + aux[col]                       (column bias)
// MODE 2: C = acc + aux[(row>>7)*auxStride + col]  (per-batch gate bias, T=128)
// MODE 3: C = acc + aux[row*auxStride + col]       (per-row matrix add)
// MODE 4: atomicAdd(sc[row], sum_col tanh(acc)*wv[col])  (attention scores)
// MODE 5: C = tanh(acc + aux[row*auxStride + col])
template<int BM, int BN, int BK, int TM, int TN, int MODE>
__global__ void __launch_bounds__(256)
sgemm_k(const float* __restrict__ A, const float* __restrict__ Bm,
        float* __restrict__ C, int M, int N, int K,
        const float* __restrict__ aux, long long auxStride,
        const float* __restrict__ wv, float* __restrict__ sc) {
    __shared__ float As[BK][BM];
    __shared__ float Bs[BK][BN];

    const int tid = threadIdx.x;
    const int tx = tid % (BN / TN);   // 16
    const int ty = tid / (BN / TN);   // 16
    const int m0 = blockIdx.y * BM;
    const int n0 = blockIdx.x * BN;

    float acc[TM][TN];
#pragma unroll
    for (int i = 0; i < TM; i++)
#pragma unroll
        for (int j = 0; j < TN; j++) acc[i][j] = 0.0f;

    const int AQ = (BM * BK) / (4 * 256);   // float4 loads of A per thread
    const int bk = tid / (BN / 4);
    const int bn = tid % (BN / 4);

    for (int k0 = 0; k0 < K; k0 += BK) {
#pragma unroll
        for (int q = 0; q < AQ; q++) {
            int lin = tid + q * 256;
            int row = lin / (BK / 4);
            int kq  = lin % (BK / 4);
            float4 v = *(const float4*)(A + (size_t)(m0 + row) * K + k0 + kq * 4);
            As[kq * 4 + 0][row] = v.x;
            As[kq * 4 + 1][row] = v.y;
            As[kq * 4 + 2][row] = v.z;
            As[kq * 4 + 3][row] = v.w;
        }
        {
            float4 v = *(const float4*)(Bm + (size_t)(k0 + bk) * N + n0 + bn * 4);
            *(float4*)&Bs[bk][bn * 4] = v;
        }
        __syncthreads();
#pragma unroll
        for (int kk = 0; kk < BK; kk++) {
            float a[TM], b[TN];
#pragma unroll
            for (int i = 0; i < TM; i++) a[i] = As[kk][ty * TM + i];
#pragma unroll
            for (int j = 0; j < TN; j++) b[j] = Bs[kk][tx * TN + j];
#pragma unroll
            for (int i = 0; i < TM; i++)
#pragma unroll
                for (int j = 0; j < TN; j++) acc[i][j] += a[i] * b[j];
        }
        __syncthreads();
    }

    if (MODE == 4) {
#pragma unroll
        for (int i = 0; i < TM; i++) {
            float p = 0.0f;
#pragma unroll
            for (int j = 0; j < TN; j++)
                p += tanhf(acc[i][j]) * wv[n0 + tx * TN + j];
            // reduce across the 16 tx lanes (lane = (ty&1)*16 + tx)
#pragma unroll
            for (int off = 8; off > 0; off >>= 1)
                p += __shfl_down_sync(0xffffffffu, p, off, 16);
            if (tx == 0) atomicAdd(&sc[m0 + ty * TM + i], p);
        }
    } else {
#pragma unroll
        for (int i = 0; i < TM; i++) {
            int row = m0 + ty * TM + i;
#pragma unroll
            for (int j = 0; j < TN; j++) {
                int col = n0 + tx * TN + j;
                float v = acc[i][j];
                if (MODE == 1) v += aux[col];
                if (MODE == 2) v += aux[(size_t)(row >> 7) * auxStride + col];
                if (MODE == 3) v += aux[(size_t)row * auxStride + col];
                if (MODE == 5) v = tanhf(v + aux[(size_t)row * auxStride + col]);
                C[(size_t)row * N + col] = v;
            }
        }
    }
}

// ---------------- LSTM pointwise update -------------------------------------
__global__ void lstm_point(const int* __restrict__ lens, int t) {
    int idx = blockIdx.x * blockDim.x + threadIdx.x;
    if (idx >= B_ * DH_) return;
    int b = idx / DH_;
    int j = idx % DH_;
    const float* gr = g_gates + (size_t)b * G_;
    float gi = gr[j];
    float gf = gr[DH_ + j];
    float gg = gr[2 * DH_ + j];
    float go = gr[3 * DH_ + j];
    float cn = sigf(gf) * g_c[idx] + sigf(gi) * tanhf(gg);
    float hn = sigf(go) * tanhf(cn);
    bool valid = (t < lens[b]);
    float hv = valid ? hn : g_h[idx];
    float cv = valid ? cn : g_c[idx];
    g_h[idx] = hv;
    g_c[idx] = cv;
    g_H[((size_t)b * T_ + t) * DH_ + j] = hv;
}

// ---------------- masked softmax over t (per batch row) ----------------------
__global__ void softmax_kernel(const int* __restrict__ lens) {
    int b = blockIdx.x;
    int t = threadIdx.x;  // 128 threads
    int len = lens[b];
    float s = (t < len) ? g_scores[b * T_ + t] : -1e30f;

    // max reduce
    float m = s;
#pragma unroll
    for (int off = 16; off > 0; off >>= 1)
        m = fmaxf(m, __shfl_down_sync(0xffffffffu, m, off));
    __shared__ float sm[4];
    if ((t & 31) == 0) sm[t >> 5] = m;
    __syncthreads();
    if (t == 0) {
        float mm = sm[0];
        mm = fmaxf(mm, sm[1]); mm = fmaxf(mm, sm[2]); mm = fmaxf(mm, sm[3]);
        sm[0] = mm;
    }
    __syncthreads();
    float mx = sm[0];

    float e = (t < len) ? expf(s - mx) : 0.0f;
    float sum = e;
#pragma unroll
    for (int off = 16; off > 0; off >>= 1)
        sum += __shfl_down_sync(0xffffffffu, sum, off);
    __shared__ float ss[4];
    if ((t & 31) == 0) ss[t >> 5] = sum;
    __syncthreads();
    if (t == 0) ss[0] = ss[0] + ss[1] + ss[2] + ss[3];
    __syncthreads();
    g_alpha[b * T_ + t] = e / ss[0];
}

// ---------------- r = sum_t alpha[b,t] * H[b,t,:] ----------------------------
__global__ void rsum_kernel() {
    int b = blockIdx.x;
    int tid = threadIdx.x;  // 256 threads
    __shared__ float al[T_];
    if (tid < T_) al[tid] = g_alpha[b * T_ + tid];
    __syncthreads();
    float a0 = 0.0f, a1 = 0.0f, a2 = 0.0f;
    for (int t = 0; t < T_; t++) {
        float a = al[t];
        const float* Hr = g_H + ((size_t)b * T_ + t) * DH_;
        a0 += a * Hr[tid];
        a1 += a * Hr[tid + 256];
        a2 += a * Hr[tid + 512];
    }
    g_r[b * DH_ + tid] = a0;
    g_r[b * DH_ + tid + 256] = a1;
    g_r[b * DH_ + tid + 512] = a2;
}

// ---------------- logit = h_star @ W_lin + b_lin -----------------------------
__global__ void logit_kernel(const float* __restrict__ Wl,
                             const float* __restrict__ bl,
                             float* __restrict__ out) {
    int b = blockIdx.x;
    int tid = threadIdx.x;  // 128 threads
    float p0 = 0.0f, p1 = 0.0f, p2 = 0.0f;
    for (int j = tid; j < DH_; j += 128) {
        float v = g_hstar[b * DH_ + j];
        p0 += v * Wl[j * 3 + 0];
        p1 += v * Wl[j * 3 + 1];
        p2 += v * Wl[j * 3 + 2];
    }
#pragma unroll
    for (int off = 16; off > 0; off >>= 1) {
        p0 += __shfl_down_sync(0xffffffffu, p0, off);
        p1 += __shfl_down_sync(0xffffffffu, p1, off);
        p2 += __shfl_down_sync(0xffffffffu, p2, off);
    }
    __shared__ float sm[3][4];
    if ((tid & 31) == 0) {
        sm[0][tid >> 5] = p0; sm[1][tid >> 5] = p1; sm[2][tid >> 5] = p2;
    }
    __syncthreads();
    if (tid < 3) {
        float s = sm[tid][0] + sm[tid][1] + sm[tid][2] + sm[tid][3];
        out[b * 3 + tid] = s + bl[tid];
    }
}

// ---------------- launch ------------------------------------------------------
extern "C" void kernel_launch(void* const* d_in, const int* in_sizes, int n_in,
                              void* d_out, int out_size) {
    const int*   sent   = (const int*)d_in[0];
    const int*   target = (const int*)d_in[1];
    const int*   lens   = (const int*)d_in[2];
    const float* emb    = (const float*)d_in[3];
    const float* temb   = (const float*)d_in[4];
    const float* W_ih   = (const float*)d_in[5];   // (1536, 3072)
    const float* W_hh   = (const float*)d_in[6];   // (768, 3072)
    const float* b_lstm = (const float*)d_in[7];   // (3072,)
    const float* Wh     = (const float*)d_in[8];   // (768, 768)
    // d_in[9] = Wv — unused: the aspect score term is constant over t and
    // softmax is shift-invariant per row, so it cancels exactly.
    const float* w_att  = (const float*)d_in[10];  // (1536,), use first 768
    const float* Wp     = (const float*)d_in[11];
    const float* Wx     = (const float*)d_in[12];
    const float* W_lin  = (const float*)d_in[13];  // (768, 3)
    const float* b_lin  = (const float*)d_in[14];
    float* out = (float*)d_out;

    float *px, *ptx, *ptxp, *pgin, *ph, *pc, *pgates, *pH, *pscores, *pr, *ptmp, *phstar;
    cudaGetSymbolAddress((void**)&px,     g_x);
    cudaGetSymbolAddress((void**)&ptx,    g_tx);
    cudaGetSymbolAddress((void**)&ptxp,   g_txp);
    cudaGetSymbolAddress((void**)&pgin,   g_gin);
    cudaGetSymbolAddress((void**)&ph,     g_h);
    cudaGetSymbolAddress((void**)&pc,     g_c);
    cudaGetSymbolAddress((void**)&pgates, g_gates);
    cudaGetSymbolAddress((void**)&pH,     g_H);
    cudaGetSymbolAddress((void**)&pscores,g_scores);
    cudaGetSymbolAddress((void**)&pr,     g_r);
    cudaGetSymbolAddress((void**)&ptmp,   g_tmp);
    cudaGetSymbolAddress((void**)&phstar, g_hstar);

    // 1. gather embeddings
    gather_kernel<<<B_ * T_ + B_, 192>>>(sent, target, emb, temb);

    // 2. zero h, c, scores
    zero_kernel<<<(B_ * DH_ + 255) / 256, 256>>>(ph, B_ * DH_);
    zero_kernel<<<(B_ * DH_ + 255) / 256, 256>>>(pc, B_ * DH_);
    zero_kernel<<<(B_ * T_ + 255) / 256, 256>>>(pscores, B_ * T_);

    // 3. txp = tx @ W_ih[768:,:] + b_lstm      (256 x 3072, K=768)
    sgemm_k<64, 64, 16, 4, 4, 1><<<dim3(G_ / 64, B_ / 64), 256>>>(
        ptx, W_ih + (size_t)768 * G_, ptxp, B_, G_, DW_,
        b_lstm, 0, nullptr, nullptr);

    // 4. gin = x @ W_ih[:768,:] + txp[b]       (32768 x 3072, K=768)
    sgemm_k<128, 64, 16, 8, 4, 2><<<dim3(G_ / 64, (B_ * T_) / 128), 256>>>(
        px, W_ih, pgin, B_ * T_, G_, DW_,
        ptxp, G_, nullptr, nullptr);

    // 5. LSTM recurrence: 128 sequential steps
    for (int t = 0; t < T_; t++) {
        sgemm_k<64, 64, 16, 4, 4, 3><<<dim3(G_ / 64, B_ / 64), 256>>>(
            ph, W_hh, pgates, B_, G_, DH_,
            pgin + (size_t)t * G_, (long long)T_ * G_, nullptr, nullptr);
        lstm_point<<<(B_ * DH_ + 255) / 256, 256>>>(lens, t);
    }

    // 6. attention scores: sc[b,t] += sum_j tanh((H@Wh)[b,t,j]) * w[j]
    sgemm_k<128, 64, 16, 8, 4, 4><<<dim3(DH_ / 64, (B_ * T_) / 128), 256>>>(
        pH, Wh, nullptr, B_ * T_, DH_, DH_,
        nullptr, 0, w_att, pscores);

    // 7. masked softmax
    softmax_kernel<<<B_, T_>>>(lens);

    // 8. r = alpha . H
    rsum_kernel<<<B_, 256>>>();

    // 9. h_star = tanh(r@Wp + h_last@Wx); h_last is the final g_h
    sgemm_k<64, 64, 16, 4, 4, 0><<<dim3(DH_ / 64, B_ / 64), 256>>>(
        pr, Wp, ptmp, B_, DH_, DH_, nullptr, 0, nullptr, nullptr);
    sgemm_k<64, 64, 16, 4, 4, 5><<<dim3(DH_ / 64, B_ / 64), 256>>>(
        ph, Wx, phstar, B_, DH_, DH_, ptmp, DH_, nullptr, nullptr);

    // 10. logits
    logit_kernel<<<B_, 128>>>(W_lin, b_lin, out);
}

// round 2
// speedup vs baseline: 2.4659x; 2.4659x over previous
#include <cuda_runtime.h>
#include <math.h>
#include <stdint.h>

// Problem constants
#define B_  256
#define T_  128
#define DW_ 768
#define DH_ 768
#define G_  3072   // 4*DH

// ---------------- scratch (device globals; no allocation in kernel_launch) ---
__device__ float g_x[(size_t)B_*T_*DW_];      // gathered word embeddings
__device__ float g_tx[B_*DW_];                // gathered target embeddings
__device__ float g_txp[B_*G_];                // tx @ W_ih_bot + b_lstm
__device__ float g_gin[(size_t)B_*T_*G_];     // x @ W_ih_top + txp
__device__ float g_h[B_*DH_];
__device__ float g_c[B_*DH_];
__device__ float g_gates[B_*G_];
__device__ float g_H[(size_t)B_*T_*DH_];      // hidden states
__device__ float g_scores[B_*T_];
__device__ float g_alpha[B_*T_];
__device__ float g_r[B_*DH_];
__device__ float g_tmp[B_*DH_];
__device__ float g_hstar[B_*DH_];

__device__ __forceinline__ float sigf(float x) { return 1.0f / (1.0f + expf(-x)); }

__device__ __forceinline__ uint32_t f2tf32(float f) {
    uint32_t u;
    asm("cvt.rna.tf32.f32 %0, %1;" : "=r"(u) : "f"(f));
    return u;
}

__device__ __forceinline__ void mma_tf32(float* c,
                                         uint32_t a0, uint32_t a1, uint32_t a2, uint32_t a3,
                                         uint32_t b0, uint32_t b1) {
    asm volatile(
        "mma.sync.aligned.m16n8k8.row.col.f32.tf32.tf32.f32 "
        "{%0,%1,%2,%3},{%4,%5,%6,%7},{%8,%9},{%0,%1,%2,%3};"
        : "+f"(c[0]), "+f"(c[1]), "+f"(c[2]), "+f"(c[3])
        : "r"(a0), "r"(a1), "r"(a2), "r"(a3), "r"(b0), "r"(b1));
}

// ---------------- gather: x = emb[sent], tx = temb[target] ------------------
__global__ void gather_kernel(const int* __restrict__ sent,
                              const int* __restrict__ target,
                              const float* __restrict__ emb,
                              const float* __restrict__ temb) {
    int row = blockIdx.x;
    int tid = threadIdx.x;  // 192 threads, 192 float4 = 768 floats
    const float4* src;
    float4* dst;
    if (row < B_ * T_) {
        src = (const float4*)(emb + (size_t)sent[row] * DW_);
        dst = (float4*)(g_x + (size_t)row * DW_);
    } else {
        int rb = row - B_ * T_;
        src = (const float4*)(temb + (size_t)target[rb] * DW_);
        dst = (float4*)(g_tx + (size_t)rb * DW_);
    }
    dst[tid] = src[tid];
}

__global__ void zero_kernel(float* p, int n) {
    int i = blockIdx.x * blockDim.x + threadIdx.x;
    if (i < n) p[i] = 0.0f;
}

// ---------------- tf32 tensor-core GEMM with fused epilogues -----------------
// C[M,N] = A[M,K] @ B[K,N]  (both row-major, fp32 in, tf32 mma, fp32 acc)
// MODE 0: C = acc
// MODE 1: C = acc + aux[col]                        (column bias)
// MODE 2: C = acc + aux[(row>>7)*auxStride + col]   (per-batch gate bias, T=128)
// MODE 3: C = acc + aux[row*auxStride + col]        (per-row matrix add)
// MODE 4: atomicAdd(sc[row], sum_col tanh(acc)*wv[col])  (attention scores)
// MODE 5: C = tanh(acc + aux[row*auxStride + col])
template<int BM, int BN, int WM, int WN, int MODE>
__global__ void __launch_bounds__((BM/WM)*(BN/WN)*32)
mm_k(const float* __restrict__ A, const float* __restrict__ Bm,
     float* __restrict__ C, int M, int N, int K,
     const float* __restrict__ aux, long long auxStride,
     const float* __restrict__ wv, float* __restrict__ sc) {
    constexpr int BK = 16;
    constexpr int NWARP = (BM / WM) * (BN / WN);
    constexpr int NT = NWARP * 32;
    constexpr int SA = BK + 4;       // 20: (m*20+k) distinct mod 32 for frag loads
    constexpr int SB = BN + 8;       // ≡ 8 mod 32: (k*8+n) distinct mod 32
    constexpr int MT = WM / 16;
    constexpr int NL = WN / 8;
    constexpr int AQ = (BM * 4) / NT;   // float4 A loads per thread
    constexpr int BQ = (BN * 4) / NT;   // float4 B loads per thread

    __shared__ __align__(16) uint32_t As[BM][SA];
    __shared__ __align__(16) uint32_t Bs[BK][SB];

    const int tid = threadIdx.x;
    const int lane = tid & 31;
    const int wid = tid >> 5;
    const int wm = wid % (BM / WM);
    const int wn = wid / (BM / WM);
    const int m0 = blockIdx.y * BM;
    const int n0 = blockIdx.x * BN;

    float acc[MT][NL][4];
#pragma unroll
    for (int i = 0; i < MT; i++)
#pragma unroll
        for (int j = 0; j < NL; j++)
#pragma unroll
            for (int q = 0; q < 4; q++) acc[i][j][q] = 0.0f;

    float4 pa[AQ], pb[BQ];
    const int KT = K / BK;

    // prologue: stage tile 0 into registers
#pragma unroll
    for (int q = 0; q < AQ; q++) {
        int idx = tid + q * NT;
        pa[q] = *(const float4*)(A + (size_t)(m0 + (idx >> 2)) * K + ((idx & 3) << 2));
    }
#pragma unroll
    for (int q = 0; q < BQ; q++) {
        int idx = tid + q * NT;
        pb[q] = *(const float4*)(Bm + (size_t)(idx / (BN / 4)) * N + n0 + ((idx % (BN / 4)) << 2));
    }

    for (int kt = 0; kt < KT; kt++) {
        // commit staged tile to smem (with tf32 rounding)
#pragma unroll
        for (int q = 0; q < AQ; q++) {
            int idx = tid + q * NT;
            uint4 v = make_uint4(f2tf32(pa[q].x), f2tf32(pa[q].y),
                                 f2tf32(pa[q].z), f2tf32(pa[q].w));
            *(uint4*)&As[idx >> 2][(idx & 3) << 2] = v;
        }
#pragma unroll
        for (int q = 0; q < BQ; q++) {
            int idx = tid + q * NT;
            uint4 v = make_uint4(f2tf32(pb[q].x), f2tf32(pb[q].y),
                                 f2tf32(pb[q].z), f2tf32(pb[q].w));
            *(uint4*)&Bs[idx / (BN / 4)][(idx % (BN / 4)) << 2] = v;
        }
        __syncthreads();

        // prefetch next tile from global (overlaps with compute below)
        if (kt + 1 < KT) {
            int k0 = (kt + 1) * BK;
#pragma unroll
            for (int q = 0; q < AQ; q++) {
                int idx = tid + q * NT;
                pa[q] = *(const float4*)(A + (size_t)(m0 + (idx >> 2)) * K + k0 + ((idx & 3) << 2));
            }
#pragma unroll
            for (int q = 0; q < BQ; q++) {
                int idx = tid + q * NT;
                pb[q] = *(const float4*)(Bm + (size_t)(k0 + idx / (BN / 4)) * N + n0 + ((idx % (BN / 4)) << 2));
            }
        }

        // compute: 2 k8-steps per smem tile
#pragma unroll
        for (int ks = 0; ks < 2; ks++) {
            uint32_t af[MT][4];
            uint32_t bf[NL][2];
            int kc = ks * 8 + (lane & 3);
#pragma unroll
            for (int mt = 0; mt < MT; mt++) {
                int r = wm * WM + mt * 16 + (lane >> 2);
                af[mt][0] = As[r][kc];
                af[mt][1] = As[r + 8][kc];
                af[mt][2] = As[r][kc + 4];
                af[mt][3] = As[r + 8][kc + 4];
            }
#pragma unroll
            for (int nt = 0; nt < NL; nt++) {
                int n = wn * WN + nt * 8 + (lane >> 2);
                bf[nt][0] = Bs[kc][n];
                bf[nt][1] = Bs[kc + 4][n];
            }
#pragma unroll
            for (int mt = 0; mt < MT; mt++)
#pragma unroll
                for (int nt = 0; nt < NL; nt++)
                    mma_tf32(acc[mt][nt],
                             af[mt][0], af[mt][1], af[mt][2], af[mt][3],
                             bf[nt][0], bf[nt][1]);
        }
        __syncthreads();
    }

    // ---------------- epilogue ----------------
    if (MODE == 4) {
#pragma unroll
        for (int mt = 0; mt < MT; mt++) {
            float pl = 0.0f, ph = 0.0f;
#pragma unroll
            for (int nt = 0; nt < NL; nt++) {
                int col = n0 + wn * WN + nt * 8 + ((lane & 3) << 1);
                float w0 = wv[col], w1 = wv[col + 1];
                pl += tanhf(acc[mt][nt][0]) * w0 + tanhf(acc[mt][nt][1]) * w1;
                ph += tanhf(acc[mt][nt][2]) * w0 + tanhf(acc[mt][nt][3]) * w1;
            }
            pl += __shfl_xor_sync(0xffffffffu, pl, 1);
            pl += __shfl_xor_sync(0xffffffffu, pl, 2);
            ph += __shfl_xor_sync(0xffffffffu, ph, 1);
            ph += __shfl_xor_sync(0xffffffffu, ph, 2);
            if ((lane & 3) == 0) {
                int r = m0 + wm * WM + mt * 16 + (lane >> 2);
                atomicAdd(&sc[r], pl);
                atomicAdd(&sc[r + 8], ph);
            }
        }
    } else {
#pragma unroll
        for (int mt = 0; mt < MT; mt++) {
#pragma unroll
            for (int nt = 0; nt < NL; nt++) {
                int r = m0 + wm * WM + mt * 16 + (lane >> 2);
                int c = n0 + wn * WN + nt * 8 + ((lane & 3) << 1);
                float v0 = acc[mt][nt][0], v1 = acc[mt][nt][1];
                float v2 = acc[mt][nt][2], v3 = acc[mt][nt][3];
                if (MODE == 1) {
                    v0 += aux[c]; v1 += aux[c + 1];
                    v2 += aux[c]; v3 += aux[c + 1];
                }
                if (MODE == 2) {
                    const float* ar = aux + (size_t)(r >> 7) * auxStride;
                    v0 += ar[c]; v1 += ar[c + 1];
                    v2 += ar[c]; v3 += ar[c + 1];   // r+8 in same 128-row batch block
                }
                if (MODE == 3 || MODE == 5) {
                    const float* ar  = aux + (size_t)r * auxStride;
                    const float* ar8 = aux + (size_t)(r + 8) * auxStride;
                    v0 += ar[c];  v1 += ar[c + 1];
                    v2 += ar8[c]; v3 += ar8[c + 1];
                }
                if (MODE == 5) {
                    v0 = tanhf(v0); v1 = tanhf(v1);
                    v2 = tanhf(v2); v3 = tanhf(v3);
                }
                float2 lo = make_float2(v0, v1);
                float2 hi = make_float2(v2, v3);
                *(float2*)&C[(size_t)r * N + c] = lo;
                *(float2*)&C[(size_t)(r + 8) * N + c] = hi;
            }
        }
    }
}

// ---------------- LSTM pointwise update -------------------------------------
__global__ void lstm_point(const int* __restrict__ lens, int t) {
    int idx = blockIdx.x * blockDim.x + threadIdx.x;
    if (idx >= B_ * DH_) return;
    int b = idx / DH_;
    int j = idx % DH_;
    const float* gr = g_gates + (size_t)b * G_;
    float gi = gr[j];
    float gf = gr[DH_ + j];
    float gg = gr[2 * DH_ + j];
    float go = gr[3 * DH_ + j];
    float cn = sigf(gf) * g_c[idx] + sigf(gi) * tanhf(gg);
    float hn = sigf(go) * tanhf(cn);
    bool valid = (t < lens[b]);
    float hv = valid ? hn : g_h[idx];
    float cv = valid ? cn : g_c[idx];
    g_h[idx] = hv;
    g_c[idx] = cv;
    g_H[((size_t)b * T_ + t) * DH_ + j] = hv;
}

// ---------------- masked softmax over t (per batch row) ----------------------
__global__ void softmax_kernel(const int* __restrict__ lens) {
    int b = blockIdx.x;
    int t = threadIdx.x;  // 128 threads
    int len = lens[b];
    float s = (t < len) ? g_scores[b * T_ + t] : -1e30f;

    float m = s;
#pragma unroll
    for (int off = 16; off > 0; off >>= 1)
        m = fmaxf(m, __shfl_down_sync(0xffffffffu, m, off));
    __shared__ float sm[4];
    if ((t & 31) == 0) sm[t >> 5] = m;
    __syncthreads();
    if (t == 0) {
        float mm = sm[0];
        mm = fmaxf(mm, sm[1]); mm = fmaxf(mm, sm[2]); mm = fmaxf(mm, sm[3]);
        sm[0] = mm;
    }
    __syncthreads();
    float mx = sm[0];

    float e = (t < len) ? expf(s - mx) : 0.0f;
    float sum = e;
#pragma unroll
    for (int off = 16; off > 0; off >>= 1)
        sum += __shfl_down_sync(0xffffffffu, sum, off);
    __shared__ float ss[4];
    if ((t & 31) == 0) ss[t >> 5] = sum;
    __syncthreads();
    if (t == 0) ss[0] = ss[0] + ss[1] + ss[2] + ss[3];
    __syncthreads();
    g_alpha[b * T_ + t] = e / ss[0];
}

// ---------------- r = sum_t alpha[b,t] * H[b,t,:] ----------------------------
__global__ void rsum_kernel() {
    int b = blockIdx.x;
    int tid = threadIdx.x;  // 256 threads
    __shared__ float al[T_];
    if (tid < T_) al[tid] = g_alpha[b * T_ + tid];
    __syncthreads();
    float a0 = 0.0f, a1 = 0.0f, a2 = 0.0f;
    for (int t = 0; t < T_; t++) {
        float a = al[t];
        const float* Hr = g_H + ((size_t)b * T_ + t) * DH_;
        a0 += a * Hr[tid];
        a1 += a * Hr[tid + 256];
        a2 += a * Hr[tid + 512];
    }
    g_r[b * DH_ + tid] = a0;
    g_r[b * DH_ + tid + 256] = a1;
    g_r[b * DH_ + tid + 512] = a2;
}

// ---------------- logit = h_star @ W_lin + b_lin -----------------------------
__global__ void logit_kernel(const float* __restrict__ Wl,
                             const float* __restrict__ bl,
                             float* __restrict__ out) {
    int b = blockIdx.x;
    int tid = threadIdx.x;  // 128 threads
    float p0 = 0.0f, p1 = 0.0f, p2 = 0.0f;
    for (int j = tid; j < DH_; j += 128) {
        float v = g_hstar[b * DH_ + j];
        p0 += v * Wl[j * 3 + 0];
        p1 += v * Wl[j * 3 + 1];
        p2 += v * Wl[j * 3 + 2];
    }
#pragma unroll
    for (int off = 16; off > 0; off >>= 1) {
        p0 += __shfl_down_sync(0xffffffffu, p0, off);
        p1 += __shfl_down_sync(0xffffffffu, p1, off);
        p2 += __shfl_down_sync(0xffffffffu, p2, off);
    }
    __shared__ float sm[3][4];
    if ((tid & 31) == 0) {
        sm[0][tid >> 5] = p0; sm[1][tid >> 5] = p1; sm[2][tid >> 5] = p2;
    }
    __syncthreads();
    if (tid < 3) {
        float s = sm[tid][0] + sm[tid][1] + sm[tid][2] + sm[tid][3];
        out[b * 3 + tid] = s + bl[tid];
    }
}

// ---------------- launch ------------------------------------------------------
extern "C" void kernel_launch(void* const* d_in, const int* in_sizes, int n_in,
                              void* d_out, int out_size) {
    const int*   sent   = (const int*)d_in[0];
    const int*   target = (const int*)d_in[1];
    const int*   lens   = (const int*)d_in[2];
    const float* emb    = (const float*)d_in[3];
    const float* temb   = (const float*)d_in[4];
    const float* W_ih   = (const float*)d_in[5];   // (1536, 3072)
    const float* W_hh   = (const float*)d_in[6];   // (768, 3072)
    const float* b_lstm = (const float*)d_in[7];   // (3072,)
    const float* Wh     = (const float*)d_in[8];   // (768, 768)
    // d_in[9] = Wv — unused: the aspect score term is constant over t and
    // softmax is shift-invariant per row, so it cancels exactly.
    const float* w_att  = (const float*)d_in[10];  // (1536,), use first 768
    const float* Wp     = (const float*)d_in[11];
    const float* Wx     = (const float*)d_in[12];
    const float* W_lin  = (const float*)d_in[13];  // (768, 3)
    const float* b_lin  = (const float*)d_in[14];
    float* out = (float*)d_out;

    float *px, *ptx, *ptxp, *pgin, *ph, *pc, *pgates, *pH, *pscores, *pr, *ptmp, *phstar;
    cudaGetSymbolAddress((void**)&px,     g_x);
    cudaGetSymbolAddress((void**)&ptx,    g_tx);
    cudaGetSymbolAddress((void**)&ptxp,   g_txp);
    cudaGetSymbolAddress((void**)&pgin,   g_gin);
    cudaGetSymbolAddress((void**)&ph,     g_h);
    cudaGetSymbolAddress((void**)&pc,     g_c);
    cudaGetSymbolAddress((void**)&pgates, g_gates);
    cudaGetSymbolAddress((void**)&pH,     g_H);
    cudaGetSymbolAddress((void**)&pscores,g_scores);
    cudaGetSymbolAddress((void**)&pr,     g_r);
    cudaGetSymbolAddress((void**)&ptmp,   g_tmp);
    cudaGetSymbolAddress((void**)&phstar, g_hstar);

    // 1. gather embeddings
    gather_kernel<<<B_ * T_ + B_, 192>>>(sent, target, emb, temb);

    // 2. zero h, c, scores
    zero_kernel<<<(B_ * DH_ + 255) / 256, 256>>>(ph, B_ * DH_);
    zero_kernel<<<(B_ * DH_ + 255) / 256, 256>>>(pc, B_ * DH_);
    zero_kernel<<<(B_ * T_ + 255) / 256, 256>>>(pscores, B_ * T_);

    // 3. txp = tx @ W_ih[768:,:] + b_lstm      (256 x 3072, K=768)
    mm_k<64, 64, 32, 32, 1><<<dim3(G_ / 64, B_ / 64), 128>>>(
        ptx, W_ih + (size_t)768 * G_, ptxp, B_, G_, DW_,
        b_lstm, 0, nullptr, nullptr);

    // 4. gin = x @ W_ih[:768,:] + txp[b]       (32768 x 3072, K=768)
    mm_k<128, 128, 32, 64, 2><<<dim3(G_ / 128, (B_ * T_) / 128), 256>>>(
        px, W_ih, pgin, B_ * T_, G_, DW_,
        ptxp, G_, nullptr, nullptr);

    // 5. LSTM recurrence: 128 sequential steps
    for (int t = 0; t < T_; t++) {
        mm_k<64, 64, 32, 32, 3><<<dim3(G_ / 64, B_ / 64), 128>>>(
            ph, W_hh, pgates, B_, G_, DH_,
            pgin + (size_t)t * G_, (long long)T_ * G_, nullptr, nullptr);
        lstm_point<<<(B_ * DH_ + 255) / 256, 256>>>(lens, t);
    }

    // 6. attention scores: sc[b,t] += sum_j tanh((H@Wh)[b,t,j]) * w[j]
    mm_k<128, 128, 32, 64, 4><<<dim3(DH_ / 128, (B_ * T_) / 128), 256>>>(
        pH, Wh, nullptr, B_ * T_, DH_, DH_,
        nullptr, 0, w_att, pscores);

    // 7. masked softmax
    softmax_kernel<<<B_, T_>>>(lens);

    // 8. r = alpha . H
    rsum_kernel<<<B_, 256>>>();

    // 9. h_star = tanh(r@Wp + h_last@Wx); h_last is the final g_h
    mm_k<64, 64, 32, 32, 0><<<dim3(DH_ / 64, B_ / 64), 128>>>(
        pr, Wp, ptmp, B_, DH_, DH_, nullptr, 0, nullptr, nullptr);
    mm_k<64, 64, 32, 32, 5><<<dim3(DH_ / 64, B_ / 64), 128>>>(
        ph, Wx, phstar, B_, DH_, DH_, ptmp, DH_, nullptr, nullptr);

    // 10. logits
    logit_kernel<<<B_, 128>>>(W_lin, b_lin, out);
}

// round 3
// speedup vs baseline: 2.5687x; 1.0417x over previous
#include <cuda_runtime.h>
#include <math.h>
#include <stdint.h>

// Problem constants
#define B_  256
#define T_  128
#define DW_ 768
#define DH_ 768
#define G_  3072   // 4*DH
#define NBLK 96    // persistent LSTM blocks (<=148 SMs, 1 block/SM => co-resident)

// ---------------- scratch (device globals; no allocation in kernel_launch) ---
__device__ float g_x[(size_t)B_*T_*DW_];      // gathered word embeddings
__device__ float g_tx[B_*DW_];                // gathered target embeddings
__device__ float g_txp[B_*G_];                // tx @ W_ih_bot + b_lstm
__device__ float g_gin[(size_t)B_*T_*G_];     // x @ W_ih_top + txp
__device__ float g_hbuf[2][B_*DH_];           // double-buffered h exchange
__device__ float g_H[(size_t)B_*T_*DH_];      // hidden states history
__device__ float g_scores[B_*T_];
__device__ float g_alpha[B_*T_];
__device__ float g_r[B_*DH_];
__device__ float g_tmp[B_*DH_];
__device__ float g_hstar[B_*DH_];
__device__ unsigned g_barcnt;                 // grid barrier (monotonic)

__device__ __forceinline__ float sigf(float x) { return 1.0f / (1.0f + expf(-x)); }

__device__ __forceinline__ uint32_t f2tf32(float f) {
    uint32_t u;
    asm("cvt.rna.tf32.f32 %0, %1;" : "=r"(u) : "f"(f));
    return u;
}

__device__ __forceinline__ void mma_tf32(float* c,
                                         uint32_t a0, uint32_t a1, uint32_t a2, uint32_t a3,
                                         uint32_t b0, uint32_t b1) {
    asm volatile(
        "mma.sync.aligned.m16n8k8.row.col.f32.tf32.tf32.f32 "
        "{%0,%1,%2,%3},{%4,%5,%6,%7},{%8,%9},{%0,%1,%2,%3};"
        : "+f"(c[0]), "+f"(c[1]), "+f"(c[2]), "+f"(c[3])
        : "r"(a0), "r"(a1), "r"(a2), "r"(a3), "r"(b0), "r"(b1));
}

// ---------------- gather: x = emb[sent], tx = temb[target] ------------------
__global__ void gather_kernel(const int* __restrict__ sent,
                              const int* __restrict__ target,
                              const float* __restrict__ emb,
                              const float* __restrict__ temb) {
    int row = blockIdx.x;
    int tid = threadIdx.x;  // 192 threads, 192 float4 = 768 floats
    const float4* src;
    float4* dst;
    if (row < B_ * T_) {
        src = (const float4*)(emb + (size_t)sent[row] * DW_);
        dst = (float4*)(g_x + (size_t)row * DW_);
    } else {
        int rb = row - B_ * T_;
        src = (const float4*)(temb + (size_t)target[rb] * DW_);
        dst = (float4*)(g_tx + (size_t)rb * DW_);
    }
    dst[tid] = src[tid];
}

__global__ void zero_kernel(float* p, int n) {
    int i = blockIdx.x * blockDim.x + threadIdx.x;
    if (i < n) p[i] = 0.0f;
}

// ---------------- tf32 tensor-core GEMM with fused epilogues -----------------
// MODE 0: C = acc
// MODE 1: C = acc + aux[col]
// MODE 2: C = acc + aux[(row>>7)*auxStride + col]
// MODE 4: atomicAdd(sc[row], sum_col tanh(acc)*wv[col])
// MODE 5: C = tanh(acc + aux[row*auxStride + col])
template<int BM, int BN, int WM, int WN, int MODE>
__global__ void __launch_bounds__((BM/WM)*(BN/WN)*32)
mm_k(const float* __restrict__ A, const float* __restrict__ Bm,
     float* __restrict__ C, int M, int N, int K,
     const float* __restrict__ aux, long long auxStride,
     const float* __restrict__ wv, float* __restrict__ sc) {
    constexpr int BK = 16;
    constexpr int NWARP = (BM / WM) * (BN / WN);
    constexpr int NT = NWARP * 32;
    constexpr int SA = BK + 4;
    constexpr int SB = BN + 8;
    constexpr int MT = WM / 16;
    constexpr int NL = WN / 8;
    constexpr int AQ = (BM * 4) / NT;
    constexpr int BQ = (BN * 4) / NT;

    __shared__ __align__(16) uint32_t As[BM][SA];
    __shared__ __align__(16) uint32_t Bs[BK][SB];

    const int tid = threadIdx.x;
    const int lane = tid & 31;
    const int wid = tid >> 5;
    const int wm = wid % (BM / WM);
    const int wn = wid / (BM / WM);
    const int m0 = blockIdx.y * BM;
    const int n0 = blockIdx.x * BN;

    float acc[MT][NL][4];
#pragma unroll
    for (int i = 0; i < MT; i++)
#pragma unroll
        for (int j = 0; j < NL; j++)
#pragma unroll
            for (int q = 0; q < 4; q++) acc[i][j][q] = 0.0f;

    float4 pa[AQ], pb[BQ];
    const int KT = K / BK;

#pragma unroll
    for (int q = 0; q < AQ; q++) {
        int idx = tid + q * NT;
        pa[q] = *(const float4*)(A + (size_t)(m0 + (idx >> 2)) * K + ((idx & 3) << 2));
    }
#pragma unroll
    for (int q = 0; q < BQ; q++) {
        int idx = tid + q * NT;
        pb[q] = *(const float4*)(Bm + (size_t)(idx / (BN / 4)) * N + n0 + ((idx % (BN / 4)) << 2));
    }

    for (int kt = 0; kt < KT; kt++) {
#pragma unroll
        for (int q = 0; q < AQ; q++) {
            int idx = tid + q * NT;
            uint4 v = make_uint4(f2tf32(pa[q].x), f2tf32(pa[q].y),
                                 f2tf32(pa[q].z), f2tf32(pa[q].w));
            *(uint4*)&As[idx >> 2][(idx & 3) << 2] = v;
        }
#pragma unroll
        for (int q = 0; q < BQ; q++) {
            int idx = tid + q * NT;
            uint4 v = make_uint4(f2tf32(pb[q].x), f2tf32(pb[q].y),
                                 f2tf32(pb[q].z), f2tf32(pb[q].w));
            *(uint4*)&Bs[idx / (BN / 4)][(idx % (BN / 4)) << 2] = v;
        }
        __syncthreads();

        if (kt + 1 < KT) {
            int k0 = (kt + 1) * BK;
#pragma unroll
            for (int q = 0; q < AQ; q++) {
                int idx = tid + q * NT;
                pa[q] = *(const float4*)(A + (size_t)(m0 + (idx >> 2)) * K + k0 + ((idx & 3) << 2));
            }
#pragma unroll
            for (int q = 0; q < BQ; q++) {
                int idx = tid + q * NT;
                pb[q] = *(const float4*)(Bm + (size_t)(k0 + idx / (BN / 4)) * N + n0 + ((idx % (BN / 4)) << 2));
            }
        }

#pragma unroll
        for (int ks = 0; ks < 2; ks++) {
            uint32_t af[MT][4];
            uint32_t bf[NL][2];
            int kc = ks * 8 + (lane & 3);
#pragma unroll
            for (int mt = 0; mt < MT; mt++) {
                int r = wm * WM + mt * 16 + (lane >> 2);
                af[mt][0] = As[r][kc];
                af[mt][1] = As[r + 8][kc];
                af[mt][2] = As[r][kc + 4];
                af[mt][3] = As[r + 8][kc + 4];
            }
#pragma unroll
            for (int nt = 0; nt < NL; nt++) {
                int n = wn * WN + nt * 8 + (lane >> 2);
                bf[nt][0] = Bs[kc][n];
                bf[nt][1] = Bs[kc + 4][n];
            }
#pragma unroll
            for (int mt = 0; mt < MT; mt++)
#pragma unroll
                for (int nt = 0; nt < NL; nt++)
                    mma_tf32(acc[mt][nt],
                             af[mt][0], af[mt][1], af[mt][2], af[mt][3],
                             bf[nt][0], bf[nt][1]);
        }
        __syncthreads();
    }

    if (MODE == 4) {
#pragma unroll
        for (int mt = 0; mt < MT; mt++) {
            float pl = 0.0f, ph = 0.0f;
#pragma unroll
            for (int nt = 0; nt < NL; nt++) {
                int col = n0 + wn * WN + nt * 8 + ((lane & 3) << 1);
                float w0 = wv[col], w1 = wv[col + 1];
                pl += tanhf(acc[mt][nt][0]) * w0 + tanhf(acc[mt][nt][1]) * w1;
                ph += tanhf(acc[mt][nt][2]) * w0 + tanhf(acc[mt][nt][3]) * w1;
            }
            pl += __shfl_xor_sync(0xffffffffu, pl, 1);
            pl += __shfl_xor_sync(0xffffffffu, pl, 2);
            ph += __shfl_xor_sync(0xffffffffu, ph, 1);
            ph += __shfl_xor_sync(0xffffffffu, ph, 2);
            if ((lane & 3) == 0) {
                int r = m0 + wm * WM + mt * 16 + (lane >> 2);
                atomicAdd(&sc[r], pl);
                atomicAdd(&sc[r + 8], ph);
            }
        }
    } else {
#pragma unroll
        for (int mt = 0; mt < MT; mt++) {
#pragma unroll
            for (int nt = 0; nt < NL; nt++) {
                int r = m0 + wm * WM + mt * 16 + (lane >> 2);
                int c = n0 + wn * WN + nt * 8 + ((lane & 3) << 1);
                float v0 = acc[mt][nt][0], v1 = acc[mt][nt][1];
                float v2 = acc[mt][nt][2], v3 = acc[mt][nt][3];
                if (MODE == 1) {
                    v0 += aux[c]; v1 += aux[c + 1];
                    v2 += aux[c]; v3 += aux[c + 1];
                }
                if (MODE == 2) {
                    const float* ar = aux + (size_t)(r >> 7) * auxStride;
                    v0 += ar[c]; v1 += ar[c + 1];
                    v2 += ar[c]; v3 += ar[c + 1];
                }
                if (MODE == 5) {
                    const float* ar  = aux + (size_t)r * auxStride;
                    const float* ar8 = aux + (size_t)(r + 8) * auxStride;
                    v0 = tanhf(v0 + ar[c]);  v1 = tanhf(v1 + ar[c + 1]);
                    v2 = tanhf(v2 + ar8[c]); v3 = tanhf(v3 + ar8[c + 1]);
                }
                *(float2*)&C[(size_t)r * N + c] = make_float2(v0, v1);
                *(float2*)&C[(size_t)(r + 8) * N + c] = make_float2(v2, v3);
            }
        }
    }
}

// ---------------- persistent fused LSTM recurrence ---------------------------
// 96 blocks, 256 threads. Block nb owns h-cols [nb*8, nb*8+8) => 32 gate cols
// (4 sections x 8). W_hh slice resident in smem (tf32). h exchanged via
// double-buffered global; c and h state held in registers; gates never leave
// registers. Grid barrier = monotonic atomic counter (all blocks co-resident).
__global__ void __launch_bounds__(256, 1)
lstm_persist(const int* __restrict__ lens, const float* __restrict__ W_hh) {
    extern __shared__ uint32_t sm_[];
    uint32_t* ws = sm_;                      // 768*32 = 24576 words (swizzled W)
    uint32_t* As = sm_ + 24576;              // 2 * 256 * 36 = 18432 words
    int* slens = (int*)(sm_ + 24576 + 18432);

    const int tid = threadIdx.x;
    const int lane = tid & 31;
    const int w = tid >> 5;              // 8 warps, warp w owns rows [w*32, w*32+32)
    const int nb = blockIdx.x;

    // load + swizzle W_hh slice (tf32): ws[nt*6144 + (k>>2)*32 + n*4 + (k&3)]
    for (int idx = tid; idx < 768 * 32; idx += 256) {
        int k = idx >> 5, c5 = idx & 31;
        int nt = c5 >> 3, n = c5 & 7;
        float v = W_hh[(size_t)k * G_ + nt * 768 + nb * 8 + n];
        ws[nt * 6144 + (k >> 2) * 32 + n * 4 + (k & 3)] = f2tf32(v);
    }
    slens[tid] = lens[tid];
    __syncthreads();

    float c_reg[2][4], h_reg[2][4];
#pragma unroll
    for (int i = 0; i < 2; i++)
#pragma unroll
        for (int q = 0; q < 4; q++) { c_reg[i][q] = 0.0f; h_reg[i][q] = 0.0f; }

    const int srow = tid >> 3;           // staging: base row
    const int sf4 = (tid & 7) << 2;      // staging: col offset (floats)
    unsigned epoch = 0;

    for (int t = 0; t < T_; t++) {
        const float* hcur = g_hbuf[t & 1];
        float* hnxt = g_hbuf[(t + 1) & 1];

        float acc[2][4][4];
#pragma unroll
        for (int i = 0; i < 2; i++)
#pragma unroll
            for (int j = 0; j < 4; j++)
#pragma unroll
                for (int q = 0; q < 4; q++) acc[i][j][q] = 0.0f;

        // stage chunk 0 (k = 0..31)
        float4 stg[8];
#pragma unroll
        for (int p = 0; p < 8; p++)
            stg[p] = *(const float4*)&hcur[(srow + p * 32) * DH_ + sf4];
        {
            uint32_t* A0 = As;
#pragma unroll
            for (int p = 0; p < 8; p++) {
                int row = srow + p * 32;
                A0[row * 36 + sf4 + 0] = f2tf32(stg[p].x);
                A0[row * 36 + sf4 + 1] = f2tf32(stg[p].y);
                A0[row * 36 + sf4 + 2] = f2tf32(stg[p].z);
                A0[row * 36 + sf4 + 3] = f2tf32(stg[p].w);
            }
        }
        __syncthreads();

        for (int cch = 0; cch < 24; cch++) {
            const uint32_t* Ac = As + (cch & 1) * 9216;
            // prefetch next chunk
            if (cch < 23) {
                int kb = (cch + 1) * 32;
#pragma unroll
                for (int p = 0; p < 8; p++)
                    stg[p] = *(const float4*)&hcur[(srow + p * 32) * DH_ + kb + sf4];
            }
            // MMA over this chunk (4 k8-steps)
#pragma unroll
            for (int ks = 0; ks < 4; ks++) {
                int kl = ks * 8 + (lane & 3);
                int kg = cch * 32 + kl;
                int kg4 = kg + 4;
                uint32_t af[2][4], bf[4][2];
#pragma unroll
                for (int mt = 0; mt < 2; mt++) {
                    int m = w * 32 + mt * 16 + (lane >> 2);
                    af[mt][0] = Ac[m * 36 + kl];
                    af[mt][1] = Ac[(m + 8) * 36 + kl];
                    af[mt][2] = Ac[m * 36 + kl + 4];
                    af[mt][3] = Ac[(m + 8) * 36 + kl + 4];
                }
#pragma unroll
                for (int nt = 0; nt < 4; nt++) {
                    bf[nt][0] = ws[nt * 6144 + (kg  >> 2) * 32 + (lane >> 2) * 4 + (kg  & 3)];
                    bf[nt][1] = ws[nt * 6144 + (kg4 >> 2) * 32 + (lane >> 2) * 4 + (kg4 & 3)];
                }
#pragma unroll
                for (int mt = 0; mt < 2; mt++)
#pragma unroll
                    for (int nt = 0; nt < 4; nt++)
                        mma_tf32(acc[mt][nt],
                                 af[mt][0], af[mt][1], af[mt][2], af[mt][3],
                                 bf[nt][0], bf[nt][1]);
            }
            // commit prefetched chunk to other buffer
            if (cch < 23) {
                uint32_t* An = As + ((cch + 1) & 1) * 9216;
#pragma unroll
                for (int p = 0; p < 8; p++) {
                    int row = srow + p * 32;
                    An[row * 36 + sf4 + 0] = f2tf32(stg[p].x);
                    An[row * 36 + sf4 + 1] = f2tf32(stg[p].y);
                    An[row * 36 + sf4 + 2] = f2tf32(stg[p].z);
                    An[row * 36 + sf4 + 3] = f2tf32(stg[p].w);
                }
            }
            __syncthreads();
        }

        // ---- in-register LSTM pointwise ----
        int jcol = nb * 8 + ((lane & 3) << 1);
#pragma unroll
        for (int mt = 0; mt < 2; mt++) {
#pragma unroll
            for (int half = 0; half < 2; half++) {
                int r = w * 32 + mt * 16 + (lane >> 2) + half * 8;
                const float* gp = g_gin + ((size_t)r * T_ + t) * G_ + jcol;
                float2 bi = *(const float2*)(gp + 0);
                float2 bff = *(const float2*)(gp + 768);
                float2 bg = *(const float2*)(gp + 1536);
                float2 bo = *(const float2*)(gp + 2304);
                bool valid = (t < slens[r]);
                float hv0, hv1;
#pragma unroll
                for (int sub = 0; sub < 2; sub++) {
                    int q = half * 2 + sub;
                    float iv = acc[mt][0][q] + (sub ? bi.y : bi.x);
                    float fv = acc[mt][1][q] + (sub ? bff.y : bff.x);
                    float gv = acc[mt][2][q] + (sub ? bg.y : bg.x);
                    float ov = acc[mt][3][q] + (sub ? bo.y : bo.x);
                    float cn = sigf(fv) * c_reg[mt][q] + sigf(iv) * tanhf(gv);
                    float hn = sigf(ov) * tanhf(cn);
                    c_reg[mt][q] = valid ? cn : c_reg[mt][q];
                    float hv = valid ? hn : h_reg[mt][q];
                    h_reg[mt][q] = hv;
                    if (sub == 0) hv0 = hv; else hv1 = hv;
                }
                *(float2*)&hnxt[r * DH_ + jcol] = make_float2(hv0, hv1);
                *(float2*)&g_H[((size_t)r * T_ + t) * DH_ + jcol] = make_float2(hv0, hv1);
            }
        }

        // ---- grid barrier ----
        __threadfence();
        __syncthreads();
        if (tid == 0) {
            atomicAdd(&g_barcnt, 1u);
            epoch++;
            unsigned target = epoch * NBLK;
            unsigned v;
            do {
                asm volatile("ld.acquire.gpu.global.u32 %0, [%1];"
                             : "=r"(v) : "l"(&g_barcnt));
                if (v < target) __nanosleep(64);
            } while (v < target);
        }
        __syncthreads();
    }
}

// ---------------- masked softmax over t (per batch row) ----------------------
__global__ void softmax_kernel(const int* __restrict__ lens) {
    int b = blockIdx.x;
    int t = threadIdx.x;  // 128 threads
    int len = lens[b];
    float s = (t < len) ? g_scores[b * T_ + t] : -1e30f;

    float m = s;
#pragma unroll
    for (int off = 16; off > 0; off >>= 1)
        m = fmaxf(m, __shfl_down_sync(0xffffffffu, m, off));
    __shared__ float sm[4];
    if ((t & 31) == 0) sm[t >> 5] = m;
    __syncthreads();
    if (t == 0) {
        float mm = sm[0];
        mm = fmaxf(mm, sm[1]); mm = fmaxf(mm, sm[2]); mm = fmaxf(mm, sm[3]);
        sm[0] = mm;
    }
    __syncthreads();
    float mx = sm[0];

    float e = (t < len) ? expf(s - mx) : 0.0f;
    float sum = e;
#pragma unroll
    for (int off = 16; off > 0; off >>= 1)
        sum += __shfl_down_sync(0xffffffffu, sum, off);
    __shared__ float ss[4];
    if ((t & 31) == 0) ss[t >> 5] = sum;
    __syncthreads();
    if (t == 0) ss[0] = ss[0] + ss[1] + ss[2] + ss[3];
    __syncthreads();
    g_alpha[b * T_ + t] = e / ss[0];
}

// ---------------- r = sum_t alpha[b,t] * H[b,t,:] ----------------------------
__global__ void rsum_kernel() {
    int b = blockIdx.x;
    int tid = threadIdx.x;  // 256 threads
    __shared__ float al[T_];
    if (tid < T_) al[tid] = g_alpha[b * T_ + tid];
    __syncthreads();
    float a0 = 0.0f, a1 = 0.0f, a2 = 0.0f;
    for (int t = 0; t < T_; t++) {
        float a = al[t];
        const float* Hr = g_H + ((size_t)b * T_ + t) * DH_;
        a0 += a * Hr[tid];
        a1 += a * Hr[tid + 256];
        a2 += a * Hr[tid + 512];
    }
    g_r[b * DH_ + tid] = a0;
    g_r[b * DH_ + tid + 256] = a1;
    g_r[b * DH_ + tid + 512] = a2;
}

// ---------------- logit = h_star @ W_lin + b_lin -----------------------------
__global__ void logit_kernel(const float* __restrict__ Wl,
                             const float* __restrict__ bl,
                             float* __restrict__ out) {
    int b = blockIdx.x;
    int tid = threadIdx.x;  // 128 threads
    float p0 = 0.0f, p1 = 0.0f, p2 = 0.0f;
    for (int j = tid; j < DH_; j += 128) {
        float v = g_hstar[b * DH_ + j];
        p0 += v * Wl[j * 3 + 0];
        p1 += v * Wl[j * 3 + 1];
        p2 += v * Wl[j * 3 + 2];
    }
#pragma unroll
    for (int off = 16; off > 0; off >>= 1) {
        p0 += __shfl_down_sync(0xffffffffu, p0, off);
        p1 += __shfl_down_sync(0xffffffffu, p1, off);
        p2 += __shfl_down_sync(0xffffffffu, p2, off);
    }
    __shared__ float sm[3][4];
    if ((tid & 31) == 0) {
        sm[0][tid >> 5] = p0; sm[1][tid >> 5] = p1; sm[2][tid >> 5] = p2;
    }
    __syncthreads();
    if (tid < 3) {
        float s = sm[tid][0] + sm[tid][1] + sm[tid][2] + sm[tid][3];
        out[b * 3 + tid] = s + bl[tid];
    }
}

// ---------------- launch ------------------------------------------------------
extern "C" void kernel_launch(void* const* d_in, const int* in_sizes, int n_in,
                              void* d_out, int out_size) {
    const int*   sent   = (const int*)d_in[0];
    const int*   target = (const int*)d_in[1];
    const int*   lens   = (const int*)d_in[2];
    const float* emb    = (const float*)d_in[3];
    const float* temb   = (const float*)d_in[4];
    const float* W_ih   = (const float*)d_in[5];   // (1536, 3072)
    const float* W_hh   = (const float*)d_in[6];   // (768, 3072)
    const float* b_lstm = (const float*)d_in[7];   // (3072,)
    const float* Wh     = (const float*)d_in[8];   // (768, 768)
    // d_in[9] = Wv — unused: aspect score term constant over t, cancels in softmax.
    const float* w_att  = (const float*)d_in[10];  // (1536,), first 768 used
    const float* Wp     = (const float*)d_in[11];
    const float* Wx     = (const float*)d_in[12];
    const float* W_lin  = (const float*)d_in[13];  // (768, 3)
    const float* b_lin  = (const float*)d_in[14];
    float* out = (float*)d_out;

    float *px, *ptx, *ptxp, *pgin, *phbuf, *pH, *pscores, *pr, *ptmp, *phstar;
    unsigned* pbar;
    cudaGetSymbolAddress((void**)&px,     g_x);
    cudaGetSymbolAddress((void**)&ptx,    g_tx);
    cudaGetSymbolAddress((void**)&ptxp,   g_txp);
    cudaGetSymbolAddress((void**)&pgin,   g_gin);
    cudaGetSymbolAddress((void**)&phbuf,  g_hbuf);
    cudaGetSymbolAddress((void**)&pH,     g_H);
    cudaGetSymbolAddress((void**)&pscores,g_scores);
    cudaGetSymbolAddress((void**)&pr,     g_r);
    cudaGetSymbolAddress((void**)&ptmp,   g_tmp);
    cudaGetSymbolAddress((void**)&phstar, g_hstar);
    cudaGetSymbolAddress((void**)&pbar,   g_barcnt);

    const int LSTM_SMEM = (24576 + 18432) * 4 + 256 * 4;  // 173,056 B
    cudaFuncSetAttribute(lstm_persist,
                         cudaFuncAttributeMaxDynamicSharedMemorySize, LSTM_SMEM);

    // 1. gather embeddings
    gather_kernel<<<B_ * T_ + B_, 192>>>(sent, target, emb, temb);

    // 2. zero h buffer (t=0 reads buf 0), scores, barrier counter
    zero_kernel<<<(B_ * DH_ + 255) / 256, 256>>>(phbuf, B_ * DH_);
    zero_kernel<<<(B_ * T_ + 255) / 256, 256>>>(pscores, B_ * T_);
    zero_kernel<<<1, 32>>>((float*)pbar, 1);

    // 3. txp = tx @ W_ih[768:,:] + b_lstm      (256 x 3072, K=768)
    mm_k<64, 64, 32, 32, 1><<<dim3(G_ / 64, B_ / 64), 128>>>(
        ptx, W_ih + (size_t)768 * G_, ptxp, B_, G_, DW_,
        b_lstm, 0, nullptr, nullptr);

    // 4. gin = x @ W_ih[:768,:] + txp[b]       (32768 x 3072, K=768)
    mm_k<128, 128, 32, 64, 2><<<dim3(G_ / 128, (B_ * T_) / 128), 256>>>(
        px, W_ih, pgin, B_ * T_, G_, DW_,
        ptxp, G_, nullptr, nullptr);

    // 5. fused persistent LSTM recurrence (one launch, 128 steps)
    lstm_persist<<<NBLK, 256, LSTM_SMEM>>>(lens, W_hh);

    // 6. attention scores
    mm_k<128, 128, 32, 64, 4><<<dim3(DH_ / 128, (B_ * T_) / 128), 256>>>(
        pH, Wh, nullptr, B_ * T_, DH_, DH_,
        nullptr, 0, w_att, pscores);

    // 7. masked softmax
    softmax_kernel<<<B_, T_>>>(lens);

    // 8. r = alpha . H
    rsum_kernel<<<B_, 256>>>();

    // 9. h_star = tanh(r@Wp + h_last@Wx); final h lives in g_hbuf[0] (T even)
    mm_k<64, 64, 32, 32, 0><<<dim3(DH_ / 64, B_ / 64), 128>>>(
        pr, Wp, ptmp, B_, DH_, DH_, nullptr, 0, nullptr, nullptr);
    mm_k<64, 64, 32, 32, 5><<<dim3(DH_ / 64, B_ / 64), 128>>>(
        phbuf, Wx, phstar, B_, DH_, DH_, ptmp, DH_, nullptr, nullptr);

    // 10. logits
    logit_kernel<<<B_, 128>>>(W_lin, b_lin, out);
}

// round 4
// speedup vs baseline: 3.0607x; 1.1915x over previous
#include <cuda_runtime.h>
#include <math.h>
#include <stdint.h>

// Problem constants
#define B_  256
#define T_  128
#define DW_ 768
#define DH_ 768
#define G_  3072   // 4*DH
#define NBLK 96    // persistent LSTM blocks (<=148 SMs, 1 block/SM => co-resident)

// ---------------- scratch (device globals) -----------------------------------
// Sorted space: batch index bs = rank by descending length; perm[bs] = original b.
// t-major activations: row m = t*256 + bs.
__device__ float g_x[(size_t)B_*T_*DW_];      // gathered word embeddings (t-major, sorted)
__device__ float g_tx[B_*DW_];                // gathered target embeddings (sorted)
__device__ float g_txp[B_*G_];                // tx @ W_ih_bot + b_lstm (sorted)
__device__ float g_gin[(size_t)B_*T_*G_];     // x @ W_ih_top + txp (t-major, sorted)
__device__ float g_hbuf[2][B_*DH_];           // double-buffered h exchange (sorted)
__device__ float g_H[(size_t)B_*T_*DH_];      // hidden states (t-major, sorted)
__device__ float g_scores[B_*T_];             // [bs][t]
__device__ float g_alpha[B_*T_];
__device__ float g_r[B_*DH_];
__device__ float g_tmp[B_*DH_];
__device__ float g_hstar[B_*DH_];
__device__ int   g_perm[B_];                  // sorted -> original batch index
__device__ int   g_lens_s[B_];                // lengths, descending
__device__ unsigned g_barcnt;                 // grid barrier (monotonic)

__device__ __forceinline__ float sigf(float x) { return 1.0f / (1.0f + expf(-x)); }

__device__ __forceinline__ uint32_t f2tf32(float f) {
    uint32_t u;
    asm("cvt.rna.tf32.f32 %0, %1;" : "=r"(u) : "f"(f));
    return u;
}

__device__ __forceinline__ void mma_tf32(float* c,
                                         uint32_t a0, uint32_t a1, uint32_t a2, uint32_t a3,
                                         uint32_t b0, uint32_t b1) {
    asm volatile(
        "mma.sync.aligned.m16n8k8.row.col.f32.tf32.tf32.f32 "
        "{%0,%1,%2,%3},{%4,%5,%6,%7},{%8,%9},{%0,%1,%2,%3};"
        : "+f"(c[0]), "+f"(c[1]), "+f"(c[2]), "+f"(c[3])
        : "r"(a0), "r"(a1), "r"(a2), "r"(a3), "r"(b0), "r"(b1));
}

// ---------------- sort batch by length (descending), one block ---------------
__global__ void sort_kernel(const int* __restrict__ lens) {
    __shared__ int key[B_];
    int tid = threadIdx.x;
    // ascending sort of ((128-len)<<8 | idx) => len descending, idx ascending tie
    key[tid] = ((128 - lens[tid]) << 8) | tid;
    __syncthreads();
    for (int k = 2; k <= B_; k <<= 1) {
        for (int j = k >> 1; j > 0; j >>= 1) {
            int ixj = tid ^ j;
            if (ixj > tid) {
                int a = key[tid], b = key[ixj];
                bool up = ((tid & k) == 0);
                if (up ? (a > b) : (a < b)) { key[tid] = b; key[ixj] = a; }
            }
            __syncthreads();
        }
    }
    g_perm[tid] = key[tid] & 255;
    g_lens_s[tid] = 128 - (key[tid] >> 8);
}

// ---------------- gather (sorted, t-major): x = emb[sent], tx = temb[target] -
__global__ void gather_kernel(const int* __restrict__ sent,
                              const int* __restrict__ target,
                              const float* __restrict__ emb,
                              const float* __restrict__ temb) {
    int row = blockIdx.x;
    int tid = threadIdx.x;  // 192 threads, 192 float4 = 768 floats
    const float4* src;
    float4* dst;
    if (row < B_ * T_) {
        int bs = row & 255, t = row >> 8;
        int token = sent[g_perm[bs] * T_ + t];
        src = (const float4*)(emb + (size_t)token * DW_);
        dst = (float4*)(g_x + (size_t)row * DW_);
    } else {
        int rb = row - B_ * T_;
        src = (const float4*)(temb + (size_t)target[g_perm[rb]] * DW_);
        dst = (float4*)(g_tx + (size_t)rb * DW_);
    }
    dst[tid] = src[tid];
}

// zero h (buffer 0), scores, barrier counter in one launch
__global__ void zeroall_kernel() {
    int i = blockIdx.x * 256 + threadIdx.x;
    if (i < B_ * DH_) g_hbuf[0][i] = 0.0f;
    if (i < B_ * T_) g_scores[i] = 0.0f;
    if (i == 0) g_barcnt = 0u;
}

// ---------------- tf32 tensor-core GEMM with fused epilogues -----------------
// MODE 0: C = acc
// MODE 1: C = acc + aux[col]
// MODE 2: C = acc + aux[(row&255)*auxStride + col]   (per-batch bias, t-major rows)
// MODE 4: atomicAdd(sc[(row&255)*T + (row>>8)], sum_col tanh(acc)*wv[col])
// MODE 5: C = tanh(acc + aux[row*auxStride + col])
// EXITP: early-exit whole block if t >= exl[half*128]  (t-major, sorted lens)
template<int BM, int BN, int WM, int WN, int MODE, int EXITP>
__global__ void __launch_bounds__((BM/WM)*(BN/WN)*32)
mm_k(const float* __restrict__ A, const float* __restrict__ Bm,
     float* __restrict__ C, int M, int N, int K,
     const float* __restrict__ aux, long long auxStride,
     const float* __restrict__ wv, float* __restrict__ sc,
     const int* __restrict__ exl) {
    constexpr int BK = 16;
    constexpr int NWARP = (BM / WM) * (BN / WN);
    constexpr int NT = NWARP * 32;
    constexpr int SA = BK + 4;
    constexpr int SB = BN + 8;
    constexpr int MT = WM / 16;
    constexpr int NL = WN / 8;
    constexpr int AQ = (BM * 4) / NT;
    constexpr int BQ = (BN * 4) / NT;

    const int m0 = blockIdx.y * BM;
    if (EXITP) {
        int t = m0 >> 8;
        int half = (m0 >> 7) & 1;
        if (t >= exl[half * 128]) return;
    }

    __shared__ __align__(16) uint32_t As[BM][SA];
    __shared__ __align__(16) uint32_t Bs[BK][SB];

    const int tid = threadIdx.x;
    const int lane = tid & 31;
    const int wid = tid >> 5;
    const int wm = wid % (BM / WM);
    const int wn = wid / (BM / WM);
    const int n0 = blockIdx.x * BN;

    float acc[MT][NL][4];
#pragma unroll
    for (int i = 0; i < MT; i++)
#pragma unroll
        for (int j = 0; j < NL; j++)
#pragma unroll
            for (int q = 0; q < 4; q++) acc[i][j][q] = 0.0f;

    float4 pa[AQ], pb[BQ];
    const int KT = K / BK;

#pragma unroll
    for (int q = 0; q < AQ; q++) {
        int idx = tid + q * NT;
        pa[q] = *(const float4*)(A + (size_t)(m0 + (idx >> 2)) * K + ((idx & 3) << 2));
    }
#pragma unroll
    for (int q = 0; q < BQ; q++) {
        int idx = tid + q * NT;
        pb[q] = *(const float4*)(Bm + (size_t)(idx / (BN / 4)) * N + n0 + ((idx % (BN / 4)) << 2));
    }

    for (int kt = 0; kt < KT; kt++) {
#pragma unroll
        for (int q = 0; q < AQ; q++) {
            int idx = tid + q * NT;
            uint4 v = make_uint4(f2tf32(pa[q].x), f2tf32(pa[q].y),
                                 f2tf32(pa[q].z), f2tf32(pa[q].w));
            *(uint4*)&As[idx >> 2][(idx & 3) << 2] = v;
        }
#pragma unroll
        for (int q = 0; q < BQ; q++) {
            int idx = tid + q * NT;
            uint4 v = make_uint4(f2tf32(pb[q].x), f2tf32(pb[q].y),
                                 f2tf32(pb[q].z), f2tf32(pb[q].w));
            *(uint4*)&Bs[idx / (BN / 4)][(idx % (BN / 4)) << 2] = v;
        }
        __syncthreads();

        if (kt + 1 < KT) {
            int k0 = (kt + 1) * BK;
#pragma unroll
            for (int q = 0; q < AQ; q++) {
                int idx = tid + q * NT;
                pa[q] = *(const float4*)(A + (size_t)(m0 + (idx >> 2)) * K + k0 + ((idx & 3) << 2));
            }
#pragma unroll
            for (int q = 0; q < BQ; q++) {
                int idx = tid + q * NT;
                pb[q] = *(const float4*)(Bm + (size_t)(k0 + idx / (BN / 4)) * N + n0 + ((idx % (BN / 4)) << 2));
            }
        }

#pragma unroll
        for (int ks = 0; ks < 2; ks++) {
            uint32_t af[MT][4];
            uint32_t bf[NL][2];
            int kc = ks * 8 + (lane & 3);
#pragma unroll
            for (int mt = 0; mt < MT; mt++) {
                int r = wm * WM + mt * 16 + (lane >> 2);
                af[mt][0] = As[r][kc];
                af[mt][1] = As[r + 8][kc];
                af[mt][2] = As[r][kc + 4];
                af[mt][3] = As[r + 8][kc + 4];
            }
#pragma unroll
            for (int nt = 0; nt < NL; nt++) {
                int n = wn * WN + nt * 8 + (lane >> 2);
                bf[nt][0] = Bs[kc][n];
                bf[nt][1] = Bs[kc + 4][n];
            }
#pragma unroll
            for (int mt = 0; mt < MT; mt++)
#pragma unroll
                for (int nt = 0; nt < NL; nt++)
                    mma_tf32(acc[mt][nt],
                             af[mt][0], af[mt][1], af[mt][2], af[mt][3],
                             bf[nt][0], bf[nt][1]);
        }
        __syncthreads();
    }

    if (MODE == 4) {
#pragma unroll
        for (int mt = 0; mt < MT; mt++) {
            float pl = 0.0f, ph = 0.0f;
#pragma unroll
            for (int nt = 0; nt < NL; nt++) {
                int col = n0 + wn * WN + nt * 8 + ((lane & 3) << 1);
                float w0 = wv[col], w1 = wv[col + 1];
                pl += tanhf(acc[mt][nt][0]) * w0 + tanhf(acc[mt][nt][1]) * w1;
                ph += tanhf(acc[mt][nt][2]) * w0 + tanhf(acc[mt][nt][3]) * w1;
            }
            pl += __shfl_xor_sync(0xffffffffu, pl, 1);
            pl += __shfl_xor_sync(0xffffffffu, pl, 2);
            ph += __shfl_xor_sync(0xffffffffu, ph, 1);
            ph += __shfl_xor_sync(0xffffffffu, ph, 2);
            if ((lane & 3) == 0) {
                int r = m0 + wm * WM + mt * 16 + (lane >> 2);
                atomicAdd(&sc[(r & 255) * T_ + (r >> 8)], pl);
                atomicAdd(&sc[((r + 8) & 255) * T_ + ((r + 8) >> 8)], ph);
            }
        }
    } else {
#pragma unroll
        for (int mt = 0; mt < MT; mt++) {
#pragma unroll
            for (int nt = 0; nt < NL; nt++) {
                int r = m0 + wm * WM + mt * 16 + (lane >> 2);
                int c = n0 + wn * WN + nt * 8 + ((lane & 3) << 1);
                float v0 = acc[mt][nt][0], v1 = acc[mt][nt][1];
                float v2 = acc[mt][nt][2], v3 = acc[mt][nt][3];
                if (MODE == 1) {
                    v0 += aux[c]; v1 += aux[c + 1];
                    v2 += aux[c]; v3 += aux[c + 1];
                }
                if (MODE == 2) {
                    const float* ar  = aux + (size_t)(r & 255) * auxStride;
                    const float* ar8 = aux + (size_t)((r + 8) & 255) * auxStride;
                    v0 += ar[c];  v1 += ar[c + 1];
                    v2 += ar8[c]; v3 += ar8[c + 1];
                }
                if (MODE == 5) {
                    const float* ar  = aux + (size_t)r * auxStride;
                    const float* ar8 = aux + (size_t)(r + 8) * auxStride;
                    v0 = tanhf(v0 + ar[c]);  v1 = tanhf(v1 + ar[c + 1]);
                    v2 = tanhf(v2 + ar8[c]); v3 = tanhf(v3 + ar8[c + 1]);
                }
                *(float2*)&C[(size_t)r * N + c] = make_float2(v0, v1);
                *(float2*)&C[(size_t)(r + 8) * N + c] = make_float2(v2, v3);
            }
        }
    }
}

// ---------------- persistent fused LSTM recurrence ---------------------------
// Sorted space: active rows at step t form prefix [0, n_t). Warp-level MMA and
// h-staging skipped above n32 = roundup(n_t, 32). gin/H are t-major.
__global__ void __launch_bounds__(256, 1)
lstm_persist(const float* __restrict__ W_hh) {
    extern __shared__ uint32_t sm_[];
    uint32_t* ws = sm_;                      // 768*32 words (swizzled W slice)
    uint32_t* As = sm_ + 24576;              // 2 * 256 * 36 words (h staging)
    int* slens = (int*)(sm_ + 24576 + 18432);       // 256 ints
    int* nact  = (int*)(sm_ + 24576 + 18432 + 256); // 128 ints

    const int tid = threadIdx.x;
    const int lane = tid & 31;
    const int w = tid >> 5;
    const int nb = blockIdx.x;

    for (int idx = tid; idx < 768 * 32; idx += 256) {
        int k = idx >> 5, c5 = idx & 31;
        int nt = c5 >> 3, n = c5 & 7;
        float v = W_hh[(size_t)k * G_ + nt * 768 + nb * 8 + n];
        ws[nt * 6144 + (k >> 2) * 32 + n * 4 + (k & 3)] = f2tf32(v);
    }
    slens[tid] = g_lens_s[tid];
    __syncthreads();
    for (int i = tid; i < T_; i += 256) {
        int c = 0;
        for (int b = 0; b < B_; b++) c += (slens[b] > i) ? 1 : 0;
        int n32 = (c + 31) & ~31;
        nact[i] = n32 > 256 ? 256 : n32;
    }
    __syncthreads();

    float c_reg[2][4], h_reg[2][4];
#pragma unroll
    for (int i = 0; i < 2; i++)
#pragma unroll
        for (int q = 0; q < 4; q++) { c_reg[i][q] = 0.0f; h_reg[i][q] = 0.0f; }

    const int srow = tid >> 3;
    const int sf4 = (tid & 7) << 2;
    unsigned epoch = 0;

    for (int t = 0; t < T_; t++) {
        const float* hcur = g_hbuf[t & 1];
        float* hnxt = g_hbuf[(t + 1) & 1];
        const int n32 = nact[t];

        float acc[2][4][4];
#pragma unroll
        for (int i = 0; i < 2; i++)
#pragma unroll
            for (int j = 0; j < 4; j++)
#pragma unroll
                for (int q = 0; q < 4; q++) acc[i][j][q] = 0.0f;

        // stage chunk 0 (k = 0..31), rows < n32 only
        float4 stg[8];
#pragma unroll
        for (int p = 0; p < 8; p++)
            if (p * 32 < n32)
                stg[p] = *(const float4*)&hcur[(srow + p * 32) * DH_ + sf4];
        {
            uint32_t* A0 = As;
#pragma unroll
            for (int p = 0; p < 8; p++)
                if (p * 32 < n32) {
                    int row = srow + p * 32;
                    A0[row * 36 + sf4 + 0] = f2tf32(stg[p].x);
                    A0[row * 36 + sf4 + 1] = f2tf32(stg[p].y);
                    A0[row * 36 + sf4 + 2] = f2tf32(stg[p].z);
                    A0[row * 36 + sf4 + 3] = f2tf32(stg[p].w);
                }
        }
        __syncthreads();

        for (int cch = 0; cch < 24; cch++) {
            const uint32_t* Ac = As + (cch & 1) * 9216;
            if (cch < 23) {
                int kb = (cch + 1) * 32;
#pragma unroll
                for (int p = 0; p < 8; p++)
                    if (p * 32 < n32)
                        stg[p] = *(const float4*)&hcur[(srow + p * 32) * DH_ + kb + sf4];
            }
            if (w * 32 < n32) {
#pragma unroll
                for (int ks = 0; ks < 4; ks++) {
                    int kl = ks * 8 + (lane & 3);
                    int kg = cch * 32 + kl;
                    int kg4 = kg + 4;
                    uint32_t af[2][4], bf[4][2];
#pragma unroll
                    for (int mt = 0; mt < 2; mt++) {
                        int m = w * 32 + mt * 16 + (lane >> 2);
                        af[mt][0] = Ac[m * 36 + kl];
                        af[mt][1] = Ac[(m + 8) * 36 + kl];
                        af[mt][2] = Ac[m * 36 + kl + 4];
                        af[mt][3] = Ac[(m + 8) * 36 + kl + 4];
                    }
#pragma unroll
                    for (int nt = 0; nt < 4; nt++) {
                        bf[nt][0] = ws[nt * 6144 + (kg  >> 2) * 32 + (lane >> 2) * 4 + (kg  & 3)];
                        bf[nt][1] = ws[nt * 6144 + (kg4 >> 2) * 32 + (lane >> 2) * 4 + (kg4 & 3)];
                    }
#pragma unroll
                    for (int mt = 0; mt < 2; mt++)
#pragma unroll
                        for (int nt = 0; nt < 4; nt++)
                            mma_tf32(acc[mt][nt],
                                     af[mt][0], af[mt][1], af[mt][2], af[mt][3],
                                     bf[nt][0], bf[nt][1]);
                }
            }
            if (cch < 23) {
                uint32_t* An = As + ((cch + 1) & 1) * 9216;
#pragma unroll
                for (int p = 0; p < 8; p++)
                    if (p * 32 < n32) {
                        int row = srow + p * 32;
                        An[row * 36 + sf4 + 0] = f2tf32(stg[p].x);
                        An[row * 36 + sf4 + 1] = f2tf32(stg[p].y);
                        An[row * 36 + sf4 + 2] = f2tf32(stg[p].z);
                        An[row * 36 + sf4 + 3] = f2tf32(stg[p].w);
                    }
            }
            __syncthreads();
        }

        // ---- in-register LSTM pointwise (t-major gin/H) ----
        int jcol = nb * 8 + ((lane & 3) << 1);
#pragma unroll
        for (int mt = 0; mt < 2; mt++) {
#pragma unroll
            for (int half = 0; half < 2; half++) {
                int r = w * 32 + mt * 16 + (lane >> 2) + half * 8;
                bool valid = (t < slens[r]);
                float2 bi = make_float2(0.f, 0.f), bff = bi, bg = bi, bo = bi;
                if (valid) {
                    const float* gp = g_gin + ((size_t)(t * B_ + r)) * G_ + jcol;
                    bi  = *(const float2*)(gp + 0);
                    bff = *(const float2*)(gp + 768);
                    bg  = *(const float2*)(gp + 1536);
                    bo  = *(const float2*)(gp + 2304);
                }
                float hv0, hv1;
#pragma unroll
                for (int sub = 0; sub < 2; sub++) {
                    int q = half * 2 + sub;
                    float iv = acc[mt][0][q] + (sub ? bi.y : bi.x);
                    float fv = acc[mt][1][q] + (sub ? bff.y : bff.x);
                    float gv = acc[mt][2][q] + (sub ? bg.y : bg.x);
                    float ov = acc[mt][3][q] + (sub ? bo.y : bo.x);
                    float cn = sigf(fv) * c_reg[mt][q] + sigf(iv) * tanhf(gv);
                    float hn = sigf(ov) * tanhf(cn);
                    c_reg[mt][q] = valid ? cn : c_reg[mt][q];
                    float hv = valid ? hn : h_reg[mt][q];
                    h_reg[mt][q] = hv;
                    if (sub == 0) hv0 = hv; else hv1 = hv;
                }
                *(float2*)&hnxt[r * DH_ + jcol] = make_float2(hv0, hv1);
                *(float2*)&g_H[((size_t)(t * B_ + r)) * DH_ + jcol] = make_float2(hv0, hv1);
            }
        }

        // ---- grid barrier ----
        __threadfence();
        __syncthreads();
        if (tid == 0) {
            atomicAdd(&g_barcnt, 1u);
            epoch++;
            unsigned target = epoch * NBLK;
            unsigned v;
            do {
                asm volatile("ld.acquire.gpu.global.u32 %0, [%1];"
                             : "=r"(v) : "l"(&g_barcnt));
                if (v < target) __nanosleep(64);
            } while (v < target);
        }
        __syncthreads();
    }
}

// ---------------- masked softmax over t (per sorted batch row) ---------------
__global__ void softmax_kernel() {
    int b = blockIdx.x;
    int t = threadIdx.x;  // 128 threads
    int len = g_lens_s[b];
    float s = (t < len) ? g_scores[b * T_ + t] : -1e30f;

    float m = s;
#pragma unroll
    for (int off = 16; off > 0; off >>= 1)
        m = fmaxf(m, __shfl_down_sync(0xffffffffu, m, off));
    __shared__ float sm[4];
    if ((t & 31) == 0) sm[t >> 5] = m;
    __syncthreads();
    if (t == 0) {
        float mm = sm[0];
        mm = fmaxf(mm, sm[1]); mm = fmaxf(mm, sm[2]); mm = fmaxf(mm, sm[3]);
        sm[0] = mm;
    }
    __syncthreads();
    float mx = sm[0];

    float e = (t < len) ? expf(s - mx) : 0.0f;
    float sum = e;
#pragma unroll
    for (int off = 16; off > 0; off >>= 1)
        sum += __shfl_down_sync(0xffffffffu, sum, off);
    __shared__ float ss[4];
    if ((t & 31) == 0) ss[t >> 5] = sum;
    __syncthreads();
    if (t == 0) ss[0] = ss[0] + ss[1] + ss[2] + ss[3];
    __syncthreads();
    g_alpha[b * T_ + t] = e / ss[0];
}

// ---------------- r = sum_t alpha[b,t] * H[t,b,:]  (t-major H) ---------------
__global__ void rsum_kernel() {
    int b = blockIdx.x;
    int tid = threadIdx.x;  // 256 threads
    __shared__ float al[T_];
    __shared__ int slen;
    if (tid < T_) al[tid] = g_alpha[b * T_ + tid];
    if (tid == 0) slen = g_lens_s[b];
    __syncthreads();
    int len = slen;
    float a0 = 0.0f, a1 = 0.0f, a2 = 0.0f;
    for (int t = 0; t < len; t++) {
        float a = al[t];
        const float* Hr = g_H + ((size_t)(t * B_ + b)) * DH_;
        a0 += a * Hr[tid];
        a1 += a * Hr[tid + 256];
        a2 += a * Hr[tid + 512];
    }
    g_r[b * DH_ + tid] = a0;
    g_r[b * DH_ + tid + 256] = a1;
    g_r[b * DH_ + tid + 512] = a2;
}

// ---------------- logit = h_star @ W_lin + b_lin (unsort at write) -----------
__global__ void logit_kernel(const float* __restrict__ Wl,
                             const float* __restrict__ bl,
                             float* __restrict__ out) {
    int b = blockIdx.x;
    int tid = threadIdx.x;  // 128 threads
    float p0 = 0.0f, p1 = 0.0f, p2 = 0.0f;
    for (int j = tid; j < DH_; j += 128) {
        float v = g_hstar[b * DH_ + j];
        p0 += v * Wl[j * 3 + 0];
        p1 += v * Wl[j * 3 + 1];
        p2 += v * Wl[j * 3 + 2];
    }
#pragma unroll
    for (int off = 16; off > 0; off >>= 1) {
        p0 += __shfl_down_sync(0xffffffffu, p0, off);
        p1 += __shfl_down_sync(0xffffffffu, p1, off);
        p2 += __shfl_down_sync(0xffffffffu, p2, off);
    }
    __shared__ float sm[3][4];
    if ((tid & 31) == 0) {
        sm[0][tid >> 5] = p0; sm[1][tid >> 5] = p1; sm[2][tid >> 5] = p2;
    }
    __syncthreads();
    if (tid < 3) {
        float s = sm[tid][0] + sm[tid][1] + sm[tid][2] + sm[tid][3];
        out[g_perm[b] * 3 + tid] = s + bl[tid];
    }
}

// ---------------- launch ------------------------------------------------------
extern "C" void kernel_launch(void* const* d_in, const int* in_sizes, int n_in,
                              void* d_out, int out_size) {
    const int*   sent   = (const int*)d_in[0];
    const int*   target = (const int*)d_in[1];
    const int*   lens   = (const int*)d_in[2];
    const float* emb    = (const float*)d_in[3];
    const float* temb   = (const float*)d_in[4];
    const float* W_ih   = (const float*)d_in[5];   // (1536, 3072)
    const float* W_hh   = (const float*)d_in[6];   // (768, 3072)
    const float* b_lstm = (const float*)d_in[7];   // (3072,)
    const float* Wh     = (const float*)d_in[8];   // (768, 768)
    // d_in[9] = Wv — unused: aspect score term constant over t, cancels in softmax.
    const float* w_att  = (const float*)d_in[10];  // (1536,), first 768 used
    const float* Wp     = (const float*)d_in[11];
    const float* Wx     = (const float*)d_in[12];
    const float* W_lin  = (const float*)d_in[13];  // (768, 3)
    const float* b_lin  = (const float*)d_in[14];
    float* out = (float*)d_out;

    float *px, *ptx, *ptxp, *pgin, *phbuf, *pH, *pscores, *pr, *ptmp, *phstar;
    int *plens_s;
    cudaGetSymbolAddress((void**)&px,      g_x);
    cudaGetSymbolAddress((void**)&ptx,     g_tx);
    cudaGetSymbolAddress((void**)&ptxp,    g_txp);
    cudaGetSymbolAddress((void**)&pgin,    g_gin);
    cudaGetSymbolAddress((void**)&phbuf,   g_hbuf);
    cudaGetSymbolAddress((void**)&pH,      g_H);
    cudaGetSymbolAddress((void**)&pscores, g_scores);
    cudaGetSymbolAddress((void**)&pr,      g_r);
    cudaGetSymbolAddress((void**)&ptmp,    g_tmp);
    cudaGetSymbolAddress((void**)&phstar,  g_hstar);
    cudaGetSymbolAddress((void**)&plens_s, g_lens_s);

    const int LSTM_SMEM = (24576 + 18432) * 4 + 256 * 4 + 128 * 4;  // 173,568 B
    cudaFuncSetAttribute(lstm_persist,
                         cudaFuncAttributeMaxDynamicSharedMemorySize, LSTM_SMEM);

    // 1. sort batch by length (descending)
    sort_kernel<<<1, B_>>>(lens);

    // 2. gather embeddings (sorted, t-major)
    gather_kernel<<<B_ * T_ + B_, 192>>>(sent, target, emb, temb);

    // 3. zero h buffer, scores, barrier counter
    zeroall_kernel<<<(B_ * DH_ + 255) / 256, 256>>>();

    // 4. txp = tx @ W_ih[768:,:] + b_lstm      (256 x 3072, K=768)
    mm_k<64, 64, 32, 32, 1, 0><<<dim3(G_ / 64, B_ / 64), 128>>>(
        ptx, W_ih + (size_t)768 * G_, ptxp, B_, G_, DW_,
        b_lstm, 0, nullptr, nullptr, nullptr);

    // 5. gin = x @ W_ih[:768,:] + txp[bs]   (t-major, early-exit dead t-blocks)
    mm_k<128, 128, 32, 64, 2, 1><<<dim3(G_ / 128, (B_ * T_) / 128), 256>>>(
        px, W_ih, pgin, B_ * T_, G_, DW_,
        ptxp, G_, nullptr, nullptr, plens_s);

    // 6. fused persistent LSTM recurrence (one launch, 128 steps)
    lstm_persist<<<NBLK, 256, LSTM_SMEM>>>(W_hh);

    // 7. attention scores (t-major, early-exit)
    mm_k<128, 128, 32, 64, 4, 1><<<dim3(DH_ / 128, (B_ * T_) / 128), 256>>>(
        pH, Wh, nullptr, B_ * T_, DH_, DH_,
        nullptr, 0, w_att, pscores, plens_s);

    // 8. masked softmax
    softmax_kernel<<<B_, T_>>>();

    // 9. r = alpha . H
    rsum_kernel<<<B_, 256>>>();

    // 10. h_star = tanh(r@Wp + h_last@Wx); final h lives in g_hbuf[0] (T even)
    mm_k<64, 64, 32, 32, 0, 0><<<dim3(DH_ / 64, B_ / 64), 128>>>(
        pr, Wp, ptmp, B_, DH_, DH_, nullptr, 0, nullptr, nullptr, nullptr);
    mm_k<64, 64, 32, 32, 5, 0><<<dim3(DH_ / 64, B_ / 64), 128>>>(
        phbuf, Wx, phstar, B_, DH_, DH_, ptmp, DH_, nullptr, nullptr, nullptr);

    // 11. logits (unsorted write)
    logit_kernel<<<B_, 128>>>(W_lin, b_lin, out);
}

// round 5
// speedup vs baseline: 3.1311x; 1.0230x over previous
#include <cuda_runtime.h>
#include <math.h>
#include <stdint.h>

// Problem constants
#define B_  256
#define T_  128
#define DW_ 768
#define DH_ 768
#define G_  3072   // 4*DH
#define NBLK 96    // persistent LSTM blocks

// ---------------- scratch (device globals) -----------------------------------
__device__ int   g_tok[B_*T_];                // sorted t-major token ids
__device__ float g_tx[B_*DW_];                // gathered target embeddings (sorted)
__device__ float g_txp[B_*G_];                // tx @ W_ih_bot + b_lstm (sorted)
__device__ float g_gin[(size_t)B_*T_*G_];     // x @ W_ih_top + txp (t-major, sorted)
__device__ float g_hbuf[2][B_*DH_];           // double-buffered h exchange (sorted)
__device__ float g_H[(size_t)B_*T_*DH_];      // hidden states (t-major, sorted)
__device__ float g_scores[B_*T_];             // [bs][t]
__device__ float g_alpha[B_*T_];
__device__ float g_r[B_*DH_];
__device__ float g_tmp[B_*DH_];
__device__ float g_hstar[B_*DH_];
__device__ int   g_perm[B_];                  // sorted -> original batch index
__device__ int   g_lens_s[B_];                // lengths, descending
__device__ unsigned g_barcnt;                 // grid barrier (monotonic)

__device__ __forceinline__ float sigf(float x) { return 1.0f / (1.0f + expf(-x)); }

__device__ __forceinline__ uint32_t f2tf32(float f) {
    uint32_t u;
    asm("cvt.rna.tf32.f32 %0, %1;" : "=r"(u) : "f"(f));
    return u;
}

__device__ __forceinline__ void mma_tf32(float* c,
                                         uint32_t a0, uint32_t a1, uint32_t a2, uint32_t a3,
                                         uint32_t b0, uint32_t b1) {
    asm volatile(
        "mma.sync.aligned.m16n8k8.row.col.f32.tf32.tf32.f32 "
        "{%0,%1,%2,%3},{%4,%5,%6,%7},{%8,%9},{%0,%1,%2,%3};"
        : "+f"(c[0]), "+f"(c[1]), "+f"(c[2]), "+f"(c[3])
        : "r"(a0), "r"(a1), "r"(a2), "r"(a3), "r"(b0), "r"(b1));
}

__device__ __forceinline__ void cpa16(uint32_t dst, const void* src) {
    asm volatile("cp.async.ca.shared.global [%0], [%1], 16;"
                 :: "r"(dst), "l"(src));
}
__device__ __forceinline__ void cpa_commit() {
    asm volatile("cp.async.commit_group;" ::: "memory");
}
template<int N>
__device__ __forceinline__ void cpa_wait() {
    asm volatile("cp.async.wait_group %0;" :: "n"(N) : "memory");
}

// ---------------- sort batch by length (descending), one block ---------------
__global__ void sort_kernel(const int* __restrict__ lens) {
    __shared__ int key[B_];
    int tid = threadIdx.x;
    key[tid] = ((128 - lens[tid]) << 8) | tid;
    __syncthreads();
    for (int k = 2; k <= B_; k <<= 1) {
        for (int j = k >> 1; j > 0; j >>= 1) {
            int ixj = tid ^ j;
            if (ixj > tid) {
                int a = key[tid], b = key[ixj];
                bool up = ((tid & k) == 0);
                if (up ? (a > b) : (a < b)) { key[tid] = b; key[ixj] = a; }
            }
            __syncthreads();
        }
    }
    g_perm[tid] = key[tid] & 255;
    g_lens_s[tid] = 128 - (key[tid] >> 8);
}

// ---------------- tokens (sorted t-major) + gather tx ------------------------
__global__ void tok_kernel(const int* __restrict__ sent,
                           const int* __restrict__ target,
                           const float* __restrict__ temb) {
    int blk = blockIdx.x;
    if (blk < T_) {
        int bs = threadIdx.x;  // 256
        g_tok[blk * B_ + bs] = sent[g_perm[bs] * T_ + blk];
    } else {
        int bs = blk - T_;
        if (threadIdx.x < 192) {
            const float4* src = (const float4*)(temb + (size_t)target[g_perm[bs]] * DW_);
            ((float4*)(g_tx + (size_t)bs * DW_))[threadIdx.x] = src[threadIdx.x];
        }
    }
}

// zero h (buffer 0), scores, barrier counter in one launch
__global__ void zeroall_kernel() {
    int i = blockIdx.x * 256 + threadIdx.x;
    if (i < B_ * DH_) g_hbuf[0][i] = 0.0f;
    if (i < B_ * T_) g_scores[i] = 0.0f;
    if (i == 0) g_barcnt = 0u;
}

// ---------------- cp.async pipelined 128x128 tf32 GEMM -----------------------
// K=768 fixed. A row-major (or gathered from emb via g_tok), B row-major [K,N].
// 256 threads, warp grid 2(m) x 4(n): WM=64, WN=32. 4-stage LDGSTS pipeline.
// MODE 2: C = acc + aux[(row&255)*auxStride + col]   (gin epilogue)
// MODE 4: atomicAdd(sc[(row&255)*T + (row>>8)], sum_col tanh(acc)*wv[col])
// EXITP:  early-exit block if t >= exl[half*128]
// GATHER: A rows fetched from Asrc[tok[row]*768 + k]
template<int MODE, int EXITP, int GATHER>
__global__ void __launch_bounds__(256)
mm2(const float* __restrict__ Asrc, const float* __restrict__ Bm,
    float* __restrict__ C, int N,
    const float* __restrict__ aux, long long auxStride,
    const float* __restrict__ wv, float* __restrict__ sc,
    const int* __restrict__ exl, const int* __restrict__ tok) {
    constexpr int BM = 128, BN = 128, BK = 16, S = 4;
    constexpr int SA = 20, SB = 136;
    constexpr int K = 768, KT = K / BK;   // 48

    const int m0 = blockIdx.y * BM;
    if (EXITP) {
        int t = m0 >> 8;
        int half = (m0 >> 7) & 1;
        if (t >= exl[half * 128]) return;
    }

    extern __shared__ float smem[];
    float* As = smem;                     // S * BM * SA floats
    float* Bs = smem + S * BM * SA;       // S * BK * SB floats

    const int tid = threadIdx.x;
    const int lane = tid & 31;
    const int wid = tid >> 5;
    const int wm = wid & 1;               // 0..1
    const int wn = wid >> 1;              // 0..3
    const int n0 = blockIdx.x * BN;

    // per-thread copy assignments (fixed across stages)
    const int arow0 = tid >> 2;           // 0..63
    const int arow1 = 64 + (tid >> 2);    // 64..127
    const int ak = (tid & 3) << 2;        // 0,4,8,12
    const float *aptr0, *aptr1;
    if (GATHER) {
        aptr0 = Asrc + (size_t)tok[m0 + arow0] * K + ak;
        aptr1 = Asrc + (size_t)tok[m0 + arow1] * K + ak;
    } else {
        aptr0 = Asrc + (size_t)(m0 + arow0) * K + ak;
        aptr1 = Asrc + (size_t)(m0 + arow1) * K + ak;
    }
    const int brow0 = tid >> 5;           // 0..7
    const int brow1 = 8 + (tid >> 5);     // 8..15
    const int bn4 = (tid & 31) << 2;      // 0..124
    const float* bptr0 = Bm + (size_t)brow0 * N + n0 + bn4;
    const float* bptr1 = Bm + (size_t)brow1 * N + n0 + bn4;

    float acc[4][4][4];
#pragma unroll
    for (int i = 0; i < 4; i++)
#pragma unroll
        for (int j = 0; j < 4; j++)
#pragma unroll
            for (int q = 0; q < 4; q++) acc[i][j][q] = 0.0f;

    // issue copies for stage kt
    auto issue = [&](int kt) {
        int koff = kt * BK;
        float* as = As + (kt & (S - 1)) * BM * SA;
        float* bs = Bs + (kt & (S - 1)) * BK * SB;
        cpa16((uint32_t)__cvta_generic_to_shared(as + arow0 * SA + ak), aptr0 + koff);
        cpa16((uint32_t)__cvta_generic_to_shared(as + arow1 * SA + ak), aptr1 + koff);
        cpa16((uint32_t)__cvta_generic_to_shared(bs + brow0 * SB + bn4), bptr0 + (size_t)koff * N);
        cpa16((uint32_t)__cvta_generic_to_shared(bs + brow1 * SB + bn4), bptr1 + (size_t)koff * N);
    };

#pragma unroll
    for (int s = 0; s < S - 1; s++) { issue(s); cpa_commit(); }

    for (int kt = 0; kt < KT; kt++) {
        cpa_wait<S - 2>();
        __syncthreads();
        if (kt + S - 1 < KT) issue(kt + S - 1);
        cpa_commit();

        const uint32_t* asU = (const uint32_t*)(As + (kt & (S - 1)) * BM * SA);
        const uint32_t* bsU = (const uint32_t*)(Bs + (kt & (S - 1)) * BK * SB);
#pragma unroll
        for (int ks = 0; ks < 2; ks++) {
            int kc = ks * 8 + (lane & 3);
            uint32_t af[4][4], bf[4][2];
#pragma unroll
            for (int mt = 0; mt < 4; mt++) {
                int m = wm * 64 + mt * 16 + (lane >> 2);
                af[mt][0] = asU[m * SA + kc];
                af[mt][1] = asU[(m + 8) * SA + kc];
                af[mt][2] = asU[m * SA + kc + 4];
                af[mt][3] = asU[(m + 8) * SA + kc + 4];
            }
#pragma unroll
            for (int nt = 0; nt < 4; nt++) {
                int n = wn * 32 + nt * 8 + (lane >> 2);
                bf[nt][0] = bsU[kc * SB + n];
                bf[nt][1] = bsU[(kc + 4) * SB + n];
            }
#pragma unroll
            for (int mt = 0; mt < 4; mt++)
#pragma unroll
                for (int nt = 0; nt < 4; nt++)
                    mma_tf32(acc[mt][nt],
                             af[mt][0], af[mt][1], af[mt][2], af[mt][3],
                             bf[nt][0], bf[nt][1]);
        }
    }

    if (MODE == 4) {
#pragma unroll
        for (int mt = 0; mt < 4; mt++) {
            float pl = 0.0f, ph = 0.0f;
#pragma unroll
            for (int nt = 0; nt < 4; nt++) {
                int col = n0 + wn * 32 + nt * 8 + ((lane & 3) << 1);
                float w0 = wv[col], w1 = wv[col + 1];
                pl += tanhf(acc[mt][nt][0]) * w0 + tanhf(acc[mt][nt][1]) * w1;
                ph += tanhf(acc[mt][nt][2]) * w0 + tanhf(acc[mt][nt][3]) * w1;
            }
            pl += __shfl_xor_sync(0xffffffffu, pl, 1);
            pl += __shfl_xor_sync(0xffffffffu, pl, 2);
            ph += __shfl_xor_sync(0xffffffffu, ph, 1);
            ph += __shfl_xor_sync(0xffffffffu, ph, 2);
            if ((lane & 3) == 0) {
                int r = m0 + wm * 64 + mt * 16 + (lane >> 2);
                atomicAdd(&sc[(r & 255) * T_ + (r >> 8)], pl);
                atomicAdd(&sc[((r + 8) & 255) * T_ + ((r + 8) >> 8)], ph);
            }
        }
    } else {
#pragma unroll
        for (int mt = 0; mt < 4; mt++) {
#pragma unroll
            for (int nt = 0; nt < 4; nt++) {
                int r = m0 + wm * 64 + mt * 16 + (lane >> 2);
                int c = n0 + wn * 32 + nt * 8 + ((lane & 3) << 1);
                float v0 = acc[mt][nt][0], v1 = acc[mt][nt][1];
                float v2 = acc[mt][nt][2], v3 = acc[mt][nt][3];
                const float* ar  = aux + (size_t)(r & 255) * auxStride;
                const float* ar8 = aux + (size_t)((r + 8) & 255) * auxStride;
                v0 += ar[c];  v1 += ar[c + 1];
                v2 += ar8[c]; v3 += ar8[c + 1];
                *(float2*)&C[(size_t)r * N + c] = make_float2(v0, v1);
                *(float2*)&C[(size_t)(r + 8) * N + c] = make_float2(v2, v3);
            }
        }
    }
}

// ---------------- small tf32 GEMM (64x64 tiles, register prefetch) -----------
// MODE 0: C = acc
// MODE 1: C = acc + aux[col]
// MODE 5: C = tanh(acc + aux[row*auxStride + col])
template<int BM, int BN, int WM, int WN, int MODE>
__global__ void __launch_bounds__((BM/WM)*(BN/WN)*32)
mm_k(const float* __restrict__ A, const float* __restrict__ Bm,
     float* __restrict__ C, int M, int N, int K,
     const float* __restrict__ aux, long long auxStride) {
    constexpr int BK = 16;
    constexpr int NWARP = (BM / WM) * (BN / WN);
    constexpr int NT = NWARP * 32;
    constexpr int SA = BK + 4;
    constexpr int SB = BN + 8;
    constexpr int MT = WM / 16;
    constexpr int NL = WN / 8;
    constexpr int AQ = (BM * 4) / NT;
    constexpr int BQ = (BN * 4) / NT;

    __shared__ __align__(16) uint32_t As[BM][SA];
    __shared__ __align__(16) uint32_t Bs[BK][SB];

    const int tid = threadIdx.x;
    const int lane = tid & 31;
    const int wid = tid >> 5;
    const int wm = wid % (BM / WM);
    const int wn = wid / (BM / WM);
    const int m0 = blockIdx.y * BM;
    const int n0 = blockIdx.x * BN;

    float acc[MT][NL][4];
#pragma unroll
    for (int i = 0; i < MT; i++)
#pragma unroll
        for (int j = 0; j < NL; j++)
#pragma unroll
            for (int q = 0; q < 4; q++) acc[i][j][q] = 0.0f;

    float4 pa[AQ], pb[BQ];
    const int KT = K / BK;

#pragma unroll
    for (int q = 0; q < AQ; q++) {
        int idx = tid + q * NT;
        pa[q] = *(const float4*)(A + (size_t)(m0 + (idx >> 2)) * K + ((idx & 3) << 2));
    }
#pragma unroll
    for (int q = 0; q < BQ; q++) {
        int idx = tid + q * NT;
        pb[q] = *(const float4*)(Bm + (size_t)(idx / (BN / 4)) * N + n0 + ((idx % (BN / 4)) << 2));
    }

    for (int kt = 0; kt < KT; kt++) {
#pragma unroll
        for (int q = 0; q < AQ; q++) {
            int idx = tid + q * NT;
            uint4 v = make_uint4(f2tf32(pa[q].x), f2tf32(pa[q].y),
                                 f2tf32(pa[q].z), f2tf32(pa[q].w));
            *(uint4*)&As[idx >> 2][(idx & 3) << 2] = v;
        }
#pragma unroll
        for (int q = 0; q < BQ; q++) {
            int idx = tid + q * NT;
            uint4 v = make_uint4(f2tf32(pb[q].x), f2tf32(pb[q].y),
                                 f2tf32(pb[q].z), f2tf32(pb[q].w));
            *(uint4*)&Bs[idx / (BN / 4)][(idx % (BN / 4)) << 2] = v;
        }
        __syncthreads();

        if (kt + 1 < KT) {
            int k0 = (kt + 1) * BK;
#pragma unroll
            for (int q = 0; q < AQ; q++) {
                int idx = tid + q * NT;
                pa[q] = *(const float4*)(A + (size_t)(m0 + (idx >> 2)) * K + k0 + ((idx & 3) << 2));
            }
#pragma unroll
            for (int q = 0; q < BQ; q++) {
                int idx = tid + q * NT;
                pb[q] = *(const float4*)(Bm + (size_t)(k0 + idx / (BN / 4)) * N + n0 + ((idx % (BN / 4)) << 2));
            }
        }

#pragma unroll
        for (int ks = 0; ks < 2; ks++) {
            uint32_t af[MT][4];
            uint32_t bf[NL][2];
            int kc = ks * 8 + (lane & 3);
#pragma unroll
            for (int mt = 0; mt < MT; mt++) {
                int r = wm * WM + mt * 16 + (lane >> 2);
                af[mt][0] = As[r][kc];
                af[mt][1] = As[r + 8][kc];
                af[mt][2] = As[r][kc + 4];
                af[mt][3] = As[r + 8][kc + 4];
            }
#pragma unroll
            for (int nt = 0; nt < NL; nt++) {
                int n = wn * WN + nt * 8 + (lane >> 2);
                bf[nt][0] = Bs[kc][n];
                bf[nt][1] = Bs[kc + 4][n];
            }
#pragma unroll
            for (int mt = 0; mt < MT; mt++)
#pragma unroll
                for (int nt = 0; nt < NL; nt++)
                    mma_tf32(acc[mt][nt],
                             af[mt][0], af[mt][1], af[mt][2], af[mt][3],
                             bf[nt][0], bf[nt][1]);
        }
        __syncthreads();
    }

#pragma unroll
    for (int mt = 0; mt < MT; mt++) {
#pragma unroll
        for (int nt = 0; nt < NL; nt++) {
            int r = m0 + wm * WM + mt * 16 + (lane >> 2);
            int c = n0 + wn * WN + nt * 8 + ((lane & 3) << 1);
            float v0 = acc[mt][nt][0], v1 = acc[mt][nt][1];
            float v2 = acc[mt][nt][2], v3 = acc[mt][nt][3];
            if (MODE == 1) {
                v0 += aux[c]; v1 += aux[c + 1];
                v2 += aux[c]; v3 += aux[c + 1];
            }
            if (MODE == 5) {
                const float* ar  = aux + (size_t)r * auxStride;
                const float* ar8 = aux + (size_t)(r + 8) * auxStride;
                v0 = tanhf(v0 + ar[c]);  v1 = tanhf(v1 + ar[c + 1]);
                v2 = tanhf(v2 + ar8[c]); v3 = tanhf(v3 + ar8[c + 1]);
            }
            *(float2*)&C[(size_t)r * N + c] = make_float2(v0, v1);
            *(float2*)&C[(size_t)(r + 8) * N + c] = make_float2(v2, v3);
        }
    }
}

// ---------------- persistent fused LSTM recurrence ---------------------------
__global__ void __launch_bounds__(256, 1)
lstm_persist(const float* __restrict__ W_hh) {
    extern __shared__ uint32_t sm_[];
    uint32_t* ws = sm_;                      // 768*32 words (swizzled W slice)
    uint32_t* As = sm_ + 24576;              // 2 * 256 * 36 words (h staging)
    int* slens = (int*)(sm_ + 24576 + 18432);       // 256 ints
    int* nact  = (int*)(sm_ + 24576 + 18432 + 256); // 128 ints

    const int tid = threadIdx.x;
    const int lane = tid & 31;
    const int w = tid >> 5;
    const int nb = blockIdx.x;

    for (int idx = tid; idx < 768 * 32; idx += 256) {
        int k = idx >> 5, c5 = idx & 31;
        int nt = c5 >> 3, n = c5 & 7;
        float v = W_hh[(size_t)k * G_ + nt * 768 + nb * 8 + n];
        ws[nt * 6144 + (k >> 2) * 32 + n * 4 + (k & 3)] = f2tf32(v);
    }
    slens[tid] = g_lens_s[tid];
    __syncthreads();
    for (int i = tid; i < T_; i += 256) {
        int c = 0;
        for (int b = 0; b < B_; b++) c += (slens[b] > i) ? 1 : 0;
        int n32 = (c + 31) & ~31;
        nact[i] = n32 > 256 ? 256 : n32;
    }
    __syncthreads();

    float c_reg[2][4], h_reg[2][4];
#pragma unroll
    for (int i = 0; i < 2; i++)
#pragma unroll
        for (int q = 0; q < 4; q++) { c_reg[i][q] = 0.0f; h_reg[i][q] = 0.0f; }

    const int srow = tid >> 3;
    const int sf4 = (tid & 7) << 2;
    unsigned epoch = 0;

    for (int t = 0; t < T_; t++) {
        const float* hcur = g_hbuf[t & 1];
        float* hnxt = g_hbuf[(t + 1) & 1];
        const int n32 = nact[t];

        float acc[2][4][4];
#pragma unroll
        for (int i = 0; i < 2; i++)
#pragma unroll
            for (int j = 0; j < 4; j++)
#pragma unroll
                for (int q = 0; q < 4; q++) acc[i][j][q] = 0.0f;

        float4 stg[8];
#pragma unroll
        for (int p = 0; p < 8; p++)
            if (p * 32 < n32)
                stg[p] = *(const float4*)&hcur[(srow + p * 32) * DH_ + sf4];
        {
            uint32_t* A0 = As;
#pragma unroll
            for (int p = 0; p < 8; p++)
                if (p * 32 < n32) {
                    int row = srow + p * 32;
                    A0[row * 36 + sf4 + 0] = f2tf32(stg[p].x);
                    A0[row * 36 + sf4 + 1] = f2tf32(stg[p].y);
                    A0[row * 36 + sf4 + 2] = f2tf32(stg[p].z);
                    A0[row * 36 + sf4 + 3] = f2tf32(stg[p].w);
                }
        }
        __syncthreads();

        for (int cch = 0; cch < 24; cch++) {
            const uint32_t* Ac = As + (cch & 1) * 9216;
            if (cch < 23) {
                int kb = (cch + 1) * 32;
#pragma unroll
                for (int p = 0; p < 8; p++)
                    if (p * 32 < n32)
                        stg[p] = *(const float4*)&hcur[(srow + p * 32) * DH_ + kb + sf4];
            }
            if (w * 32 < n32) {
#pragma unroll
                for (int ks = 0; ks < 4; ks++) {
                    int kl = ks * 8 + (lane & 3);
                    int kg = cch * 32 + kl;
                    int kg4 = kg + 4;
                    uint32_t af[2][4], bf[4][2];
#pragma unroll
                    for (int mt = 0; mt < 2; mt++) {
                        int m = w * 32 + mt * 16 + (lane >> 2);
                        af[mt][0] = Ac[m * 36 + kl];
                        af[mt][1] = Ac[(m + 8) * 36 + kl];
                        af[mt][2] = Ac[m * 36 + kl + 4];
                        af[mt][3] = Ac[(m + 8) * 36 + kl + 4];
                    }
#pragma unroll
                    for (int nt = 0; nt < 4; nt++) {
                        bf[nt][0] = ws[nt * 6144 + (kg  >> 2) * 32 + (lane >> 2) * 4 + (kg  & 3)];
                        bf[nt][1] = ws[nt * 6144 + (kg4 >> 2) * 32 + (lane >> 2) * 4 + (kg4 & 3)];
                    }
#pragma unroll
                    for (int mt = 0; mt < 2; mt++)
#pragma unroll
                        for (int nt = 0; nt < 4; nt++)
                            mma_tf32(acc[mt][nt],
                                     af[mt][0], af[mt][1], af[mt][2], af[mt][3],
                                     bf[nt][0], bf[nt][1]);
                }
            }
            if (cch < 23) {
                uint32_t* An = As + ((cch + 1) & 1) * 9216;
#pragma unroll
                for (int p = 0; p < 8; p++)
                    if (p * 32 < n32) {
                        int row = srow + p * 32;
                        An[row * 36 + sf4 + 0] = f2tf32(stg[p].x);
                        An[row * 36 + sf4 + 1] = f2tf32(stg[p].y);
                        An[row * 36 + sf4 + 2] = f2tf32(stg[p].z);
                        An[row * 36 + sf4 + 3] = f2tf32(stg[p].w);
                    }
            }
            __syncthreads();
        }

        int jcol = nb * 8 + ((lane & 3) << 1);
#pragma unroll
        for (int mt = 0; mt < 2; mt++) {
#pragma unroll
            for (int half = 0; half < 2; half++) {
                int r = w * 32 + mt * 16 + (lane >> 2) + half * 8;
                bool valid = (t < slens[r]);
                float2 bi = make_float2(0.f, 0.f), bff = bi, bg = bi, bo = bi;
                if (valid) {
                    const float* gp = g_gin + ((size_t)(t * B_ + r)) * G_ + jcol;
                    bi  = *(const float2*)(gp + 0);
                    bff = *(const float2*)(gp + 768);
                    bg  = *(const float2*)(gp + 1536);
                    bo  = *(const float2*)(gp + 2304);
                }
                float hv0, hv1;
#pragma unroll
                for (int sub = 0; sub < 2; sub++) {
                    int q = half * 2 + sub;
                    float iv = acc[mt][0][q] + (sub ? bi.y : bi.x);
                    float fv = acc[mt][1][q] + (sub ? bff.y : bff.x);
                    float gv = acc[mt][2][q] + (sub ? bg.y : bg.x);
                    float ov = acc[mt][3][q] + (sub ? bo.y : bo.x);
                    float cn = sigf(fv) * c_reg[mt][q] + sigf(iv) * tanhf(gv);
                    float hn = sigf(ov) * tanhf(cn);
                    c_reg[mt][q] = valid ? cn : c_reg[mt][q];
                    float hv = valid ? hn : h_reg[mt][q];
                    h_reg[mt][q] = hv;
                    if (sub == 0) hv0 = hv; else hv1 = hv;
                }
                *(float2*)&hnxt[r * DH_ + jcol] = make_float2(hv0, hv1);
                *(float2*)&g_H[((size_t)(t * B_ + r)) * DH_ + jcol] = make_float2(hv0, hv1);
            }
        }

        __threadfence();
        __syncthreads();
        if (tid == 0) {
            atomicAdd(&g_barcnt, 1u);
            epoch++;
            unsigned target = epoch * NBLK;
            unsigned v;
            do {
                asm volatile("ld.acquire.gpu.global.u32 %0, [%1];"
                             : "=r"(v) : "l"(&g_barcnt));
                if (v < target) __nanosleep(64);
            } while (v < target);
        }
        __syncthreads();
    }
}

// ---------------- masked softmax over t (per sorted batch row) ---------------
__global__ void softmax_kernel() {
    int b = blockIdx.x;
    int t = threadIdx.x;  // 128 threads
    int len = g_lens_s[b];
    float s = (t < len) ? g_scores[b * T_ + t] : -1e30f;

    float m = s;
#pragma unroll
    for (int off = 16; off > 0; off >>= 1)
        m = fmaxf(m, __shfl_down_sync(0xffffffffu, m, off));
    __shared__ float sm[4];
    if ((t & 31) == 0) sm[t >> 5] = m;
    __syncthreads();
    if (t == 0) {
        float mm = sm[0];
        mm = fmaxf(mm, sm[1]); mm = fmaxf(mm, sm[2]); mm = fmaxf(mm, sm[3]);
        sm[0] = mm;
    }
    __syncthreads();
    float mx = sm[0];

    float e = (t < len) ? expf(s - mx) : 0.0f;
    float sum = e;
#pragma unroll
    for (int off = 16; off > 0; off >>= 1)
        sum += __shfl_down_sync(0xffffffffu, sum, off);
    __shared__ float ss[4];
    if ((t & 31) == 0) ss[t >> 5] = sum;
    __syncthreads();
    if (t == 0) ss[0] = ss[0] + ss[1] + ss[2] + ss[3];
    __syncthreads();
    g_alpha[b * T_ + t] = e / ss[0];
}

// ---------------- r = sum_t alpha[b,t] * H[t,b,:]  (t-major H) ---------------
__global__ void rsum_kernel() {
    int b = blockIdx.x;
    int tid = threadIdx.x;  // 256 threads
    __shared__ float al[T_];
    __shared__ int slen;
    if (tid < T_) al[tid] = g_alpha[b * T_ + tid];
    if (tid == 0) slen = g_lens_s[b];
    __syncthreads();
    int len = slen;
    float a0 = 0.0f, a1 = 0.0f, a2 = 0.0f;
    for (int t = 0; t < len; t++) {
        float a = al[t];
        const float* Hr = g_H + ((size_t)(t * B_ + b)) * DH_;
        a0 += a * Hr[tid];
        a1 += a * Hr[tid + 256];
        a2 += a * Hr[tid + 512];
    }
    g_r[b * DH_ + tid] = a0;
    g_r[b * DH_ + tid + 256] = a1;
    g_r[b * DH_ + tid + 512] = a2;
}

// ---------------- logit = h_star @ W_lin + b_lin (unsort at write) -----------
__global__ void logit_kernel(const float* __restrict__ Wl,
                             const float* __restrict__ bl,
                             float* __restrict__ out) {
    int b = blockIdx.x;
    int tid = threadIdx.x;  // 128 threads
    float p0 = 0.0f, p1 = 0.0f, p2 = 0.0f;
    for (int j = tid; j < DH_; j += 128) {
        float v = g_hstar[b * DH_ + j];
        p0 += v * Wl[j * 3 + 0];
        p1 += v * Wl[j * 3 + 1];
        p2 += v * Wl[j * 3 + 2];
    }
#pragma unroll
    for (int off = 16; off > 0; off >>= 1) {
        p0 += __shfl_down_sync(0xffffffffu, p0, off);
        p1 += __shfl_down_sync(0xffffffffu, p1, off);
        p2 += __shfl_down_sync(0xffffffffu, p2, off);
    }
    __shared__ float sm[3][4];
    if ((tid & 31) == 0) {
        sm[0][tid >> 5] = p0; sm[1][tid >> 5] = p1; sm[2][tid >> 5] = p2;
    }
    __syncthreads();
    if (tid < 3) {
        float s = sm[tid][0] + sm[tid][1] + sm[tid][2] + sm[tid][3];
        out[g_perm[b] * 3 + tid] = s + bl[tid];
    }
}

// ---------------- launch ------------------------------------------------------
extern "C" void kernel_launch(void* const* d_in, const int* in_sizes, int n_in,
                              void* d_out, int out_size) {
    const int*   sent   = (const int*)d_in[0];
    const int*   target = (const int*)d_in[1];
    const int*   lens   = (const int*)d_in[2];
    const float* emb    = (const float*)d_in[3];
    const float* temb   = (const float*)d_in[4];
    const float* W_ih   = (const float*)d_in[5];   // (1536, 3072)
    const float* W_hh   = (const float*)d_in[6];   // (768, 3072)
    const float* b_lstm = (const float*)d_in[7];   // (3072,)
    const float* Wh     = (const float*)d_in[8];   // (768, 768)
    // d_in[9] = Wv — unused: aspect score term constant over t, cancels in softmax.
    const float* w_att  = (const float*)d_in[10];  // (1536,), first 768 used
    const float* Wp     = (const float*)d_in[11];
    const float* Wx     = (const float*)d_in[12];
    const float* W_lin  = (const float*)d_in[13];  // (768, 3)
    const float* b_lin  = (const float*)d_in[14];
    float* out = (float*)d_out;

    float *ptx, *ptxp, *pgin, *phbuf, *pH, *pscores, *pr, *ptmp, *phstar;
    int *plens_s, *ptok;
    cudaGetSymbolAddress((void**)&ptx,     g_tx);
    cudaGetSymbolAddress((void**)&ptxp,    g_txp);
    cudaGetSymbolAddress((void**)&pgin,    g_gin);
    cudaGetSymbolAddress((void**)&phbuf,   g_hbuf);
    cudaGetSymbolAddress((void**)&pH,      g_H);
    cudaGetSymbolAddress((void**)&pscores, g_scores);
    cudaGetSymbolAddress((void**)&pr,      g_r);
    cudaGetSymbolAddress((void**)&ptmp,    g_tmp);
    cudaGetSymbolAddress((void**)&phstar,  g_hstar);
    cudaGetSymbolAddress((void**)&plens_s, g_lens_s);
    cudaGetSymbolAddress((void**)&ptok,    g_tok);

    const int LSTM_SMEM = (24576 + 18432) * 4 + 256 * 4 + 128 * 4;  // 173,568 B
    cudaFuncSetAttribute(lstm_persist,
                         cudaFuncAttributeMaxDynamicSharedMemorySize, LSTM_SMEM);
    const int MM2_SMEM = (4 * 128 * 20 + 4 * 16 * 136) * 4;  // 75,776 B
    cudaFuncSetAttribute(mm2<2, 1, 1>,
                         cudaFuncAttributeMaxDynamicSharedMemorySize, MM2_SMEM);
    cudaFuncSetAttribute(mm2<4, 1, 0>,
                         cudaFuncAttributeMaxDynamicSharedMemorySize, MM2_SMEM);

    // 1. sort batch by length (descending)
    sort_kernel<<<1, B_>>>(lens);

    // 2. tokens (sorted t-major) + gather tx
    tok_kernel<<<T_ + B_, 256>>>(sent, target, temb);

    // 3. zero h buffer, scores, barrier counter
    zeroall_kernel<<<(B_ * DH_ + 255) / 256, 256>>>();

    // 4. txp = tx @ W_ih[768:,:] + b_lstm      (256 x 3072, K=768)
    mm_k<64, 64, 32, 32, 1><<<dim3(G_ / 64, B_ / 64), 128>>>(
        ptx, W_ih + (size_t)768 * G_, ptxp, B_, G_, DW_,
        b_lstm, 0);

    // 5. gin = emb[tok] @ W_ih[:768,:] + txp[bs]  (fused gather, early-exit)
    mm2<2, 1, 1><<<dim3(G_ / 128, (B_ * T_) / 128), 256, MM2_SMEM>>>(
        emb, W_ih, pgin, G_,
        ptxp, G_, nullptr, nullptr, plens_s, ptok);

    // 6. fused persistent LSTM recurrence (one launch, 128 steps)
    lstm_persist<<<NBLK, 256, LSTM_SMEM>>>(W_hh);

    // 7. attention scores (t-major, early-exit)
    mm2<4, 1, 0><<<dim3(DH_ / 128, (B_ * T_) / 128), 256, MM2_SMEM>>>(
        pH, Wh, nullptr, DH_,
        nullptr, 0, w_att, pscores, plens_s, nullptr);

    // 8. masked softmax
    softmax_kernel<<<B_, T_>>>();

    // 9. r = alpha . H
    rsum_kernel<<<B_, 256>>>();

    // 10. h_star = tanh(r@Wp + h_last@Wx); final h lives in g_hbuf[0] (T even)
    mm_k<64, 64, 32, 32, 0><<<dim3(DH_ / 64, B_ / 64), 128>>>(
        pr, Wp, ptmp, B_, DH_, DH_, nullptr, 0);
    mm_k<64, 64, 32, 32, 5><<<dim3(DH_ / 64, B_ / 64), 128>>>(
        phbuf, Wx, phstar, B_, DH_, DH_, ptmp, DH_);

    // 11. logits (unsorted write)
    logit_kernel<<<B_, 128>>>(W_lin, b_lin, out);
}

// round 6
// speedup vs baseline: 3.1690x; 1.0121x over previous
#include <cuda_runtime.h>
#include <cuda_bf16.h>
#include <math.h>
#include <stdint.h>

// Problem constants
#define B_  256
#define T_  128
#define DW_ 768
#define DH_ 768
#define G_  3072   // 4*DH
#define NBLK 96    // persistent LSTM blocks

// ---------------- scratch (device globals) -----------------------------------
__device__ int   g_tok[B_*T_];                   // sorted t-major token ids
__device__ float g_tx[B_*DW_];                   // gathered target embeddings (sorted)
__device__ float g_txp[B_*G_];                   // tx @ W_ih_bot + b_lstm (sorted)
__device__ float g_gin[(size_t)B_*T_*G_];        // x @ W_ih_top + txp (t-major, sorted)
__device__ __nv_bfloat16 g_hbuf[2][B_*DH_];      // bf16 double-buffered h exchange
__device__ float g_hlast[B_*DH_];                // final h (fp32)
__device__ float g_H[(size_t)B_*T_*DH_];         // hidden states (t-major, sorted, fp32)
__device__ float g_scores[B_*T_];                // [bs][t]
__device__ float g_alpha[B_*T_];
__device__ float g_r[B_*DH_];
__device__ float g_tmp[B_*DH_];
__device__ float g_hstar[B_*DH_];
__device__ int   g_perm[B_];                     // sorted -> original batch index
__device__ int   g_lens_s[B_];                   // lengths, descending
__device__ unsigned g_barcnt;                    // grid barrier (monotonic)

__device__ __forceinline__ float sigf(float x) { return 1.0f / (1.0f + expf(-x)); }

__device__ __forceinline__ uint32_t f2tf32(float f) {
    uint32_t u;
    asm("cvt.rna.tf32.f32 %0, %1;" : "=r"(u) : "f"(f));
    return u;
}

__device__ __forceinline__ uint32_t pack_bf16(float lo, float hi) {
    uint32_t r;
    asm("cvt.rn.bf16x2.f32 %0, %1, %2;" : "=r"(r) : "f"(hi), "f"(lo));
    return r;
}

__device__ __forceinline__ void mma_tf32(float* c,
                                         uint32_t a0, uint32_t a1, uint32_t a2, uint32_t a3,
                                         uint32_t b0, uint32_t b1) {
    asm volatile(
        "mma.sync.aligned.m16n8k8.row.col.f32.tf32.tf32.f32 "
        "{%0,%1,%2,%3},{%4,%5,%6,%7},{%8,%9},{%0,%1,%2,%3};"
        : "+f"(c[0]), "+f"(c[1]), "+f"(c[2]), "+f"(c[3])
        : "r"(a0), "r"(a1), "r"(a2), "r"(a3), "r"(b0), "r"(b1));
}

__device__ __forceinline__ void mma_bf16(float* c,
                                         uint32_t a0, uint32_t a1, uint32_t a2, uint32_t a3,
                                         uint32_t b0, uint32_t b1) {
    asm volatile(
        "mma.sync.aligned.m16n8k16.row.col.f32.bf16.bf16.f32 "
        "{%0,%1,%2,%3},{%4,%5,%6,%7},{%8,%9},{%0,%1,%2,%3};"
        : "+f"(c[0]), "+f"(c[1]), "+f"(c[2]), "+f"(c[3])
        : "r"(a0), "r"(a1), "r"(a2), "r"(a3), "r"(b0), "r"(b1));
}

__device__ __forceinline__ void cpa16(uint32_t dst, const void* src) {
    asm volatile("cp.async.ca.shared.global [%0], [%1], 16;"
                 :: "r"(dst), "l"(src));
}
__device__ __forceinline__ void cpa_commit() {
    asm volatile("cp.async.commit_group;" ::: "memory");
}
template<int N>
__device__ __forceinline__ void cpa_wait() {
    asm volatile("cp.async.wait_group %0;" :: "n"(N) : "memory");
}

// ---------------- sort batch by length (descending), one block ---------------
__global__ void sort_kernel(const int* __restrict__ lens) {
    __shared__ int key[B_];
    int tid = threadIdx.x;
    key[tid] = ((128 - lens[tid]) << 8) | tid;
    __syncthreads();
    for (int k = 2; k <= B_; k <<= 1) {
        for (int j = k >> 1; j > 0; j >>= 1) {
            int ixj = tid ^ j;
            if (ixj > tid) {
                int a = key[tid], b = key[ixj];
                bool up = ((tid & k) == 0);
                if (up ? (a > b) : (a < b)) { key[tid] = b; key[ixj] = a; }
            }
            __syncthreads();
        }
    }
    g_perm[tid] = key[tid] & 255;
    g_lens_s[tid] = 128 - (key[tid] >> 8);
}

// ---------------- tokens (sorted t-major) + gather tx ------------------------
__global__ void tok_kernel(const int* __restrict__ sent,
                           const int* __restrict__ target,
                           const float* __restrict__ temb) {
    int blk = blockIdx.x;
    if (blk < T_) {
        int bs = threadIdx.x;  // 256
        g_tok[blk * B_ + bs] = sent[g_perm[bs] * T_ + blk];
    } else {
        int bs = blk - T_;
        if (threadIdx.x < 192) {
            const float4* src = (const float4*)(temb + (size_t)target[g_perm[bs]] * DW_);
            ((float4*)(g_tx + (size_t)bs * DW_))[threadIdx.x] = src[threadIdx.x];
        }
    }
}

// zero bf16 h (buffer 0), scores, barrier counter
__global__ void zeroall_kernel() {
    int i = blockIdx.x * 256 + threadIdx.x;
    if (i < B_ * DH_ / 2) ((uint32_t*)g_hbuf)[i] = 0u;   // buffer 0
    if (i < B_ * T_) g_scores[i] = 0.0f;
    if (i == 0) g_barcnt = 0u;
}

// ---------------- cp.async pipelined 128x128 tf32 GEMM -----------------------
// MODE 2: C = acc + aux[(row&255)*auxStride + col]   (gin epilogue)
// MODE 4: atomicAdd(sc[(row&255)*T + (row>>8)], sum_col tanh(acc)*wv[col])
// EXITP:  early-exit block if t >= exl[half*128]
// GATHER: A rows fetched from Asrc[tok[row]*768 + k]
template<int MODE, int EXITP, int GATHER>
__global__ void __launch_bounds__(256)
mm2(const float* __restrict__ Asrc, const float* __restrict__ Bm,
    float* __restrict__ C, int N,
    const float* __restrict__ aux, long long auxStride,
    const float* __restrict__ wv, float* __restrict__ sc,
    const int* __restrict__ exl, const int* __restrict__ tok) {
    constexpr int BM = 128, BN = 128, BK = 16, S = 4;
    constexpr int SA = 20, SB = 136;
    constexpr int K = 768, KT = K / BK;   // 48

    const int m0 = blockIdx.y * BM;
    if (EXITP) {
        int t = m0 >> 8;
        int half = (m0 >> 7) & 1;
        if (t >= exl[half * 128]) return;
    }

    extern __shared__ float smem[];
    float* As = smem;
    float* Bs = smem + S * BM * SA;

    const int tid = threadIdx.x;
    const int lane = tid & 31;
    const int wid = tid >> 5;
    const int wm = wid & 1;
    const int wn = wid >> 1;
    const int n0 = blockIdx.x * BN;

    const int arow0 = tid >> 2;
    const int arow1 = 64 + (tid >> 2);
    const int ak = (tid & 3) << 2;
    const float *aptr0, *aptr1;
    if (GATHER) {
        aptr0 = Asrc + (size_t)tok[m0 + arow0] * K + ak;
        aptr1 = Asrc + (size_t)tok[m0 + arow1] * K + ak;
    } else {
        aptr0 = Asrc + (size_t)(m0 + arow0) * K + ak;
        aptr1 = Asrc + (size_t)(m0 + arow1) * K + ak;
    }
    const int brow0 = tid >> 5;
    const int brow1 = 8 + (tid >> 5);
    const int bn4 = (tid & 31) << 2;
    const float* bptr0 = Bm + (size_t)brow0 * N + n0 + bn4;
    const float* bptr1 = Bm + (size_t)brow1 * N + n0 + bn4;

    float acc[4][4][4];
#pragma unroll
    for (int i = 0; i < 4; i++)
#pragma unroll
        for (int j = 0; j < 4; j++)
#pragma unroll
            for (int q = 0; q < 4; q++) acc[i][j][q] = 0.0f;

    auto issue = [&](int kt) {
        int koff = kt * BK;
        float* as = As + (kt & (S - 1)) * BM * SA;
        float* bs = Bs + (kt & (S - 1)) * BK * SB;
        cpa16((uint32_t)__cvta_generic_to_shared(as + arow0 * SA + ak), aptr0 + koff);
        cpa16((uint32_t)__cvta_generic_to_shared(as + arow1 * SA + ak), aptr1 + koff);
        cpa16((uint32_t)__cvta_generic_to_shared(bs + brow0 * SB + bn4), bptr0 + (size_t)koff * N);
        cpa16((uint32_t)__cvta_generic_to_shared(bs + brow1 * SB + bn4), bptr1 + (size_t)koff * N);
    };

#pragma unroll
    for (int s = 0; s < S - 1; s++) { issue(s); cpa_commit(); }

    for (int kt = 0; kt < KT; kt++) {
        cpa_wait<S - 2>();
        __syncthreads();
        if (kt + S - 1 < KT) issue(kt + S - 1);
        cpa_commit();

        const uint32_t* asU = (const uint32_t*)(As + (kt & (S - 1)) * BM * SA);
        const uint32_t* bsU = (const uint32_t*)(Bs + (kt & (S - 1)) * BK * SB);
#pragma unroll
        for (int ks = 0; ks < 2; ks++) {
            int kc = ks * 8 + (lane & 3);
            uint32_t af[4][4], bf[4][2];
#pragma unroll
            for (int mt = 0; mt < 4; mt++) {
                int m = wm * 64 + mt * 16 + (lane >> 2);
                af[mt][0] = asU[m * SA + kc];
                af[mt][1] = asU[(m + 8) * SA + kc];
                af[mt][2] = asU[m * SA + kc + 4];
                af[mt][3] = asU[(m + 8) * SA + kc + 4];
            }
#pragma unroll
            for (int nt = 0; nt < 4; nt++) {
                int n = wn * 32 + nt * 8 + (lane >> 2);
                bf[nt][0] = bsU[kc * SB + n];
                bf[nt][1] = bsU[(kc + 4) * SB + n];
            }
#pragma unroll
            for (int mt = 0; mt < 4; mt++)
#pragma unroll
                for (int nt = 0; nt < 4; nt++)
                    mma_tf32(acc[mt][nt],
                             af[mt][0], af[mt][1], af[mt][2], af[mt][3],
                             bf[nt][0], bf[nt][1]);
        }
    }

    if (MODE == 4) {
#pragma unroll
        for (int mt = 0; mt < 4; mt++) {
            float pl = 0.0f, ph = 0.0f;
#pragma unroll
            for (int nt = 0; nt < 4; nt++) {
                int col = n0 + wn * 32 + nt * 8 + ((lane & 3) << 1);
                float w0 = wv[col], w1 = wv[col + 1];
                pl += tanhf(acc[mt][nt][0]) * w0 + tanhf(acc[mt][nt][1]) * w1;
                ph += tanhf(acc[mt][nt][2]) * w0 + tanhf(acc[mt][nt][3]) * w1;
            }
            pl += __shfl_xor_sync(0xffffffffu, pl, 1);
            pl += __shfl_xor_sync(0xffffffffu, pl, 2);
            ph += __shfl_xor_sync(0xffffffffu, ph, 1);
            ph += __shfl_xor_sync(0xffffffffu, ph, 2);
            if ((lane & 3) == 0) {
                int r = m0 + wm * 64 + mt * 16 + (lane >> 2);
                atomicAdd(&sc[(r & 255) * T_ + (r >> 8)], pl);
                atomicAdd(&sc[((r + 8) & 255) * T_ + ((r + 8) >> 8)], ph);
            }
        }
    } else {
#pragma unroll
        for (int mt = 0; mt < 4; mt++) {
#pragma unroll
            for (int nt = 0; nt < 4; nt++) {
                int r = m0 + wm * 64 + mt * 16 + (lane >> 2);
                int c = n0 + wn * 32 + nt * 8 + ((lane & 3) << 1);
                float v0 = acc[mt][nt][0], v1 = acc[mt][nt][1];
                float v2 = acc[mt][nt][2], v3 = acc[mt][nt][3];
                const float* ar  = aux + (size_t)(r & 255) * auxStride;
                const float* ar8 = aux + (size_t)((r + 8) & 255) * auxStride;
                v0 += ar[c];  v1 += ar[c + 1];
                v2 += ar8[c]; v3 += ar8[c + 1];
                *(float2*)&C[(size_t)r * N + c] = make_float2(v0, v1);
                *(float2*)&C[(size_t)(r + 8) * N + c] = make_float2(v2, v3);
            }
        }
    }
}

// ---------------- small tf32 GEMM (64x64 tiles, register prefetch) -----------
// MODE 0: C = acc;  MODE 1: C = acc + aux[col];  MODE 5: C = tanh(acc + aux[row*S+col])
template<int BM, int BN, int WM, int WN, int MODE>
__global__ void __launch_bounds__((BM/WM)*(BN/WN)*32)
mm_k(const float* __restrict__ A, const float* __restrict__ Bm,
     float* __restrict__ C, int M, int N, int K,
     const float* __restrict__ aux, long long auxStride) {
    constexpr int BK = 16;
    constexpr int NWARP = (BM / WM) * (BN / WN);
    constexpr int NT = NWARP * 32;
    constexpr int SA = BK + 4;
    constexpr int SB = BN + 8;
    constexpr int MT = WM / 16;
    constexpr int NL = WN / 8;
    constexpr int AQ = (BM * 4) / NT;
    constexpr int BQ = (BN * 4) / NT;

    __shared__ __align__(16) uint32_t As[BM][SA];
    __shared__ __align__(16) uint32_t Bs[BK][SB];

    const int tid = threadIdx.x;
    const int lane = tid & 31;
    const int wid = tid >> 5;
    const int wm = wid % (BM / WM);
    const int wn = wid / (BM / WM);
    const int m0 = blockIdx.y * BM;
    const int n0 = blockIdx.x * BN;

    float acc[MT][NL][4];
#pragma unroll
    for (int i = 0; i < MT; i++)
#pragma unroll
        for (int j = 0; j < NL; j++)
#pragma unroll
            for (int q = 0; q < 4; q++) acc[i][j][q] = 0.0f;

    float4 pa[AQ], pb[BQ];
    const int KT = K / BK;

#pragma unroll
    for (int q = 0; q < AQ; q++) {
        int idx = tid + q * NT;
        pa[q] = *(const float4*)(A + (size_t)(m0 + (idx >> 2)) * K + ((idx & 3) << 2));
    }
#pragma unroll
    for (int q = 0; q < BQ; q++) {
        int idx = tid + q * NT;
        pb[q] = *(const float4*)(Bm + (size_t)(idx / (BN / 4)) * N + n0 + ((idx % (BN / 4)) << 2));
    }

    for (int kt = 0; kt < KT; kt++) {
#pragma unroll
        for (int q = 0; q < AQ; q++) {
            int idx = tid + q * NT;
            uint4 v = make_uint4(f2tf32(pa[q].x), f2tf32(pa[q].y),
                                 f2tf32(pa[q].z), f2tf32(pa[q].w));
            *(uint4*)&As[idx >> 2][(idx & 3) << 2] = v;
        }
#pragma unroll
        for (int q = 0; q < BQ; q++) {
            int idx = tid + q * NT;
            uint4 v = make_uint4(f2tf32(pb[q].x), f2tf32(pb[q].y),
                                 f2tf32(pb[q].z), f2tf32(pb[q].w));
            *(uint4*)&Bs[idx / (BN / 4)][(idx % (BN / 4)) << 2] = v;
        }
        __syncthreads();

        if (kt + 1 < KT) {
            int k0 = (kt + 1) * BK;
#pragma unroll
            for (int q = 0; q < AQ; q++) {
                int idx = tid + q * NT;
                pa[q] = *(const float4*)(A + (size_t)(m0 + (idx >> 2)) * K + k0 + ((idx & 3) << 2));
            }
#pragma unroll
            for (int q = 0; q < BQ; q++) {
                int idx = tid + q * NT;
                pb[q] = *(const float4*)(Bm + (size_t)(k0 + idx / (BN / 4)) * N + n0 + ((idx % (BN / 4)) << 2));
            }
        }

#pragma unroll
        for (int ks = 0; ks < 2; ks++) {
            uint32_t af[MT][4];
            uint32_t bf[NL][2];
            int kc = ks * 8 + (lane & 3);
#pragma unroll
            for (int mt = 0; mt < MT; mt++) {
                int r = wm * WM + mt * 16 + (lane >> 2);
                af[mt][0] = As[r][kc];
                af[mt][1] = As[r + 8][kc];
                af[mt][2] = As[r][kc + 4];
                af[mt][3] = As[r + 8][kc + 4];
            }
#pragma unroll
            for (int nt = 0; nt < NL; nt++) {
                int n = wn * WN + nt * 8 + (lane >> 2);
                bf[nt][0] = Bs[kc][n];
                bf[nt][1] = Bs[kc + 4][n];
            }
#pragma unroll
            for (int mt = 0; mt < MT; mt++)
#pragma unroll
                for (int nt = 0; nt < NL; nt++)
                    mma_tf32(acc[mt][nt],
                             af[mt][0], af[mt][1], af[mt][2], af[mt][3],
                             bf[nt][0], bf[nt][1]);
        }
        __syncthreads();
    }

#pragma unroll
    for (int mt = 0; mt < MT; mt++) {
#pragma unroll
        for (int nt = 0; nt < NL; nt++) {
            int r = m0 + wm * WM + mt * 16 + (lane >> 2);
            int c = n0 + wn * WN + nt * 8 + ((lane & 3) << 1);
            float v0 = acc[mt][nt][0], v1 = acc[mt][nt][1];
            float v2 = acc[mt][nt][2], v3 = acc[mt][nt][3];
            if (MODE == 1) {
                v0 += aux[c]; v1 += aux[c + 1];
                v2 += aux[c]; v3 += aux[c + 1];
            }
            if (MODE == 5) {
                const float* ar  = aux + (size_t)r * auxStride;
                const float* ar8 = aux + (size_t)(r + 8) * auxStride;
                v0 = tanhf(v0 + ar[c]);  v1 = tanhf(v1 + ar[c + 1]);
                v2 = tanhf(v2 + ar8[c]); v3 = tanhf(v3 + ar8[c + 1]);
            }
            *(float2*)&C[(size_t)r * N + c] = make_float2(v0, v1);
            *(float2*)&C[(size_t)(r + 8) * N + c] = make_float2(v2, v3);
        }
    }
}

// ---------------- persistent fused LSTM recurrence (bf16 MMA) ----------------
// Block nb owns 8 h-cols => 32 gate cols (4 sections x 8). W_hh slice resident
// in smem as packed bf16x2. h exchanged via bf16 double buffers. c/h in regs.
// Smem (u32 words): ws 12288 | As 2*5120 | slens 256 | nact 128.
__global__ void __launch_bounds__(256, 1)
lstm_persist(const float* __restrict__ W_hh) {
    extern __shared__ uint32_t sm_[];
    uint32_t* ws = sm_;                        // 4 nt * 384 k2 * 8 nn
    uint32_t* Ab = sm_ + 12288;                // 2 * 256 * 20
    int* slens = (int*)(sm_ + 12288 + 10240);
    int* nact  = (int*)(sm_ + 12288 + 10240 + 256);

    const int tid = threadIdx.x;
    const int lane = tid & 31;
    const int w = tid >> 5;
    const int nb = blockIdx.x;

    // W_hh slice -> packed bf16x2: ws[nt*3072 + k2*8 + nn] = {W[2k2][col], W[2k2+1][col]}
    for (int i = tid; i < 12288; i += 256) {
        int nt = i / 3072;
        int rem = i - nt * 3072;
        int k2 = rem >> 3, nn = rem & 7;
        int col = nt * 768 + nb * 8 + nn;
        float w0 = W_hh[(size_t)(2 * k2) * G_ + col];
        float w1 = W_hh[(size_t)(2 * k2 + 1) * G_ + col];
        ws[i] = pack_bf16(w0, w1);
    }
    slens[tid] = g_lens_s[tid];
    __syncthreads();
    for (int i = tid; i < T_; i += 256) {
        int c = 0;
        for (int b = 0; b < B_; b++) c += (slens[b] > i) ? 1 : 0;
        int n32 = (c + 31) & ~31;
        nact[i] = n32 > 256 ? 256 : n32;
    }
    __syncthreads();

    float c_reg[2][4], h_reg[2][4];
#pragma unroll
    for (int i = 0; i < 2; i++)
#pragma unroll
        for (int q = 0; q < 4; q++) { c_reg[i][q] = 0.0f; h_reg[i][q] = 0.0f; }

    const int srow = tid;   // one h row per thread for staging
    unsigned epoch = 0;

    for (int t = 0; t < T_; t++) {
        const __nv_bfloat16* hcur = g_hbuf[t & 1];
        __nv_bfloat16* hnxt = g_hbuf[(t + 1) & 1];
        const int n32 = nact[t];
        const bool sact = (srow < n32);
        const bool wact = (w * 32 < n32);

        float acc[2][4][4];
#pragma unroll
        for (int i = 0; i < 2; i++)
#pragma unroll
            for (int j = 0; j < 4; j++)
#pragma unroll
                for (int q = 0; q < 4; q++) acc[i][j][q] = 0.0f;

        // stage chunk 0 (k = 0..31 bf16 = 64B per row)
        uint4 stg[4];
        if (sact) {
            const uint4* s = (const uint4*)(hcur + (size_t)srow * DH_);
            stg[0] = s[0]; stg[1] = s[1]; stg[2] = s[2]; stg[3] = s[3];
            uint32_t* d = Ab + srow * 20;
            *(uint4*)(d + 0) = stg[0]; *(uint4*)(d + 4) = stg[1];
            *(uint4*)(d + 8) = stg[2]; *(uint4*)(d + 12) = stg[3];
        }
        __syncthreads();

        for (int cch = 0; cch < 24; cch++) {
            const uint32_t* Ac = Ab + (cch & 1) * 5120;
            if (cch < 23 && sact) {
                const uint4* s = (const uint4*)(hcur + (size_t)srow * DH_ + (cch + 1) * 32);
                stg[0] = s[0]; stg[1] = s[1]; stg[2] = s[2]; stg[3] = s[3];
            }
            if (wact) {
#pragma unroll
                for (int ks = 0; ks < 2; ks++) {        // two k16 steps per chunk
                    int kc = ks * 8 + (lane & 3);       // u32 index within row
                    int k2 = cch * 16 + ks * 8 + (lane & 3);
                    uint32_t af[2][4], bf[4][2];
#pragma unroll
                    for (int mt = 0; mt < 2; mt++) {
                        int m = w * 32 + mt * 16 + (lane >> 2);
                        af[mt][0] = Ac[m * 20 + kc];
                        af[mt][1] = Ac[(m + 8) * 20 + kc];
                        af[mt][2] = Ac[m * 20 + kc + 4];
                        af[mt][3] = Ac[(m + 8) * 20 + kc + 4];
                    }
#pragma unroll
                    for (int nt = 0; nt < 4; nt++) {
                        bf[nt][0] = ws[nt * 3072 + k2 * 8 + (lane >> 2)];
                        bf[nt][1] = ws[nt * 3072 + (k2 + 4) * 8 + (lane >> 2)];
                    }
#pragma unroll
                    for (int mt = 0; mt < 2; mt++)
#pragma unroll
                        for (int nt = 0; nt < 4; nt++)
                            mma_bf16(acc[mt][nt],
                                     af[mt][0], af[mt][1], af[mt][2], af[mt][3],
                                     bf[nt][0], bf[nt][1]);
                }
            }
            if (cch < 23 && sact) {
                uint32_t* d = Ab + ((cch + 1) & 1) * 5120 + srow * 20;
                *(uint4*)(d + 0) = stg[0]; *(uint4*)(d + 4) = stg[1];
                *(uint4*)(d + 8) = stg[2]; *(uint4*)(d + 12) = stg[3];
            }
            __syncthreads();
        }

        // ---- in-register LSTM pointwise ----
        int jcol = nb * 8 + ((lane & 3) << 1);
#pragma unroll
        for (int mt = 0; mt < 2; mt++) {
#pragma unroll
            for (int half = 0; half < 2; half++) {
                int r = w * 32 + mt * 16 + (lane >> 2) + half * 8;
                bool valid = (t < slens[r]);
                float2 bi = make_float2(0.f, 0.f), bff = bi, bg = bi, bo = bi;
                if (valid) {
                    const float* gp = g_gin + ((size_t)(t * B_ + r)) * G_ + jcol;
                    bi  = *(const float2*)(gp + 0);
                    bff = *(const float2*)(gp + 768);
                    bg  = *(const float2*)(gp + 1536);
                    bo  = *(const float2*)(gp + 2304);
                }
                float hv0, hv1;
#pragma unroll
                for (int sub = 0; sub < 2; sub++) {
                    int q = half * 2 + sub;
                    float iv = acc[mt][0][q] + (sub ? bi.y : bi.x);
                    float fv = acc[mt][1][q] + (sub ? bff.y : bff.x);
                    float gv = acc[mt][2][q] + (sub ? bg.y : bg.x);
                    float ov = acc[mt][3][q] + (sub ? bo.y : bo.x);
                    float cn = sigf(fv) * c_reg[mt][q] + sigf(iv) * tanhf(gv);
                    float hn = sigf(ov) * tanhf(cn);
                    c_reg[mt][q] = valid ? cn : c_reg[mt][q];
                    float hv = valid ? hn : h_reg[mt][q];
                    h_reg[mt][q] = hv;
                    if (sub == 0) hv0 = hv; else hv1 = hv;
                }
                *(uint32_t*)&hnxt[(size_t)r * DH_ + jcol] = pack_bf16(hv0, hv1);
                *(float2*)&g_H[((size_t)(t * B_ + r)) * DH_ + jcol] = make_float2(hv0, hv1);
                if (t == T_ - 1)
                    *(float2*)&g_hlast[(size_t)r * DH_ + jcol] = make_float2(hv0, hv1);
            }
        }

        // ---- grid barrier ----
        __threadfence();
        __syncthreads();
        if (tid == 0) {
            atomicAdd(&g_barcnt, 1u);
            epoch++;
            unsigned target = epoch * NBLK;
            unsigned v;
            do {
                asm volatile("ld.acquire.gpu.global.u32 %0, [%1];"
                             : "=r"(v) : "l"(&g_barcnt));
                if (v < target) __nanosleep(64);
            } while (v < target);
        }
        __syncthreads();
    }
}

// ---------------- masked softmax over t (per sorted batch row) ---------------
__global__ void softmax_kernel() {
    int b = blockIdx.x;
    int t = threadIdx.x;  // 128 threads
    int len = g_lens_s[b];
    float s = (t < len) ? g_scores[b * T_ + t] : -1e30f;

    float m = s;
#pragma unroll
    for (int off = 16; off > 0; off >>= 1)
        m = fmaxf(m, __shfl_down_sync(0xffffffffu, m, off));
    __shared__ float sm[4];
    if ((t & 31) == 0) sm[t >> 5] = m;
    __syncthreads();
    if (t == 0) {
        float mm = sm[0];
        mm = fmaxf(mm, sm[1]); mm = fmaxf(mm, sm[2]); mm = fmaxf(mm, sm[3]);
        sm[0] = mm;
    }
    __syncthreads();
    float mx = sm[0];

    float e = (t < len) ? expf(s - mx) : 0.0f;
    float sum = e;
#pragma unroll
    for (int off = 16; off > 0; off >>= 1)
        sum += __shfl_down_sync(0xffffffffu, sum, off);
    __shared__ float ss[4];
    if ((t & 31) == 0) ss[t >> 5] = sum;
    __syncthreads();
    if (t == 0) ss[0] = ss[0] + ss[1] + ss[2] + ss[3];
    __syncthreads();
    g_alpha[b * T_ + t] = e / ss[0];
}

// ---------------- r = sum_t alpha[b,t] * H[t,b,:]  (t-major H) ---------------
__global__ void rsum_kernel() {
    int b = blockIdx.x;
    int tid = threadIdx.x;  // 256 threads
    __shared__ float al[T_];
    __shared__ int slen;
    if (tid < T_) al[tid] = g_alpha[b * T_ + tid];
    if (tid == 0) slen = g_lens_s[b];
    __syncthreads();
    int len = slen;
    float a0 = 0.0f, a1 = 0.0f, a2 = 0.0f;
    for (int t = 0; t < len; t++) {
        float a = al[t];
        const float* Hr = g_H + ((size_t)(t * B_ + b)) * DH_;
        a0 += a * Hr[tid];
        a1 += a * Hr[tid + 256];
        a2 += a * Hr[tid + 512];
    }
    g_r[b * DH_ + tid] = a0;
    g_r[b * DH_ + tid + 256] = a1;
    g_r[b * DH_ + tid + 512] = a2;
}

// ---------------- logit = h_star @ W_lin + b_lin (unsort at write) -----------
__global__ void logit_kernel(const float* __restrict__ Wl,
                             const float* __restrict__ bl,
                             float* __restrict__ out) {
    int b = blockIdx.x;
    int tid = threadIdx.x;  // 128 threads
    float p0 = 0.0f, p1 = 0.0f, p2 = 0.0f;
    for (int j = tid; j < DH_; j += 128) {
        float v = g_hstar[b * DH_ + j];
        p0 += v * Wl[j * 3 + 0];
        p1 += v * Wl[j * 3 + 1];
        p2 += v * Wl[j * 3 + 2];
    }
#pragma unroll
    for (int off = 16; off > 0; off >>= 1) {
        p0 += __shfl_down_sync(0xffffffffu, p0, off);
        p1 += __shfl_down_sync(0xffffffffu, p1, off);
        p2 += __shfl_down_sync(0xffffffffu, p2, off);
    }
    __shared__ float sm[3][4];
    if ((tid & 31) == 0) {
        sm[0][tid >> 5] = p0; sm[1][tid >> 5] = p1; sm[2][tid >> 5] = p2;
    }
    __syncthreads();
    if (tid < 3) {
        float s = sm[tid][0] + sm[tid][1] + sm[tid][2] + sm[tid][3];
        out[g_perm[b] * 3 + tid] = s + bl[tid];
    }
}

// ---------------- launch ------------------------------------------------------
extern "C" void kernel_launch(void* const* d_in, const int* in_sizes, int n_in,
                              void* d_out, int out_size) {
    const int*   sent   = (const int*)d_in[0];
    const int*   target = (const int*)d_in[1];
    const int*   lens   = (const int*)d_in[2];
    const float* emb    = (const float*)d_in[3];
    const float* temb   = (const float*)d_in[4];
    const float* W_ih   = (const float*)d_in[5];   // (1536, 3072)
    const float* W_hh   = (const float*)d_in[6];   // (768, 3072)
    const float* b_lstm = (const float*)d_in[7];   // (3072,)
    const float* Wh     = (const float*)d_in[8];   // (768, 768)
    // d_in[9] = Wv — unused: aspect score term constant over t, cancels in softmax.
    const float* w_att  = (const float*)d_in[10];  // (1536,), first 768 used
    const float* Wp     = (const float*)d_in[11];
    const float* Wx     = (const float*)d_in[12];
    const float* W_lin  = (const float*)d_in[13];  // (768, 3)
    const float* b_lin  = (const float*)d_in[14];
    float* out = (float*)d_out;

    float *ptx, *ptxp, *pgin, *phlast, *pH, *pscores, *pr, *ptmp, *phstar;
    int *plens_s, *ptok;
    cudaGetSymbolAddress((void**)&ptx,     g_tx);
    cudaGetSymbolAddress((void**)&ptxp,    g_txp);
    cudaGetSymbolAddress((void**)&pgin,    g_gin);
    cudaGetSymbolAddress((void**)&phlast,  g_hlast);
    cudaGetSymbolAddress((void**)&pH,      g_H);
    cudaGetSymbolAddress((void**)&pscores, g_scores);
    cudaGetSymbolAddress((void**)&pr,      g_r);
    cudaGetSymbolAddress((void**)&ptmp,    g_tmp);
    cudaGetSymbolAddress((void**)&phstar,  g_hstar);
    cudaGetSymbolAddress((void**)&plens_s, g_lens_s);
    cudaGetSymbolAddress((void**)&ptok,    g_tok);

    const int LSTM_SMEM = (12288 + 10240) * 4 + 256 * 4 + 128 * 4;  // 91,648 B
    cudaFuncSetAttribute(lstm_persist,
                         cudaFuncAttributeMaxDynamicSharedMemorySize, LSTM_SMEM);
    const int MM2_SMEM = (4 * 128 * 20 + 4 * 16 * 136) * 4;  // 75,776 B
    cudaFuncSetAttribute(mm2<2, 1, 1>,
                         cudaFuncAttributeMaxDynamicSharedMemorySize, MM2_SMEM);
    cudaFuncSetAttribute(mm2<4, 1, 0>,
                         cudaFuncAttributeMaxDynamicSharedMemorySize, MM2_SMEM);

    // 1. sort batch by length (descending)
    sort_kernel<<<1, B_>>>(lens);

    // 2. tokens (sorted t-major) + gather tx
    tok_kernel<<<T_ + B_, 256>>>(sent, target, temb);

    // 3. zero h buffer (bf16), scores, barrier counter
    zeroall_kernel<<<(B_ * DH_ / 2 + 255) / 256, 256>>>();

    // 4. txp = tx @ W_ih[768:,:] + b_lstm      (256 x 3072, K=768)
    mm_k<64, 64, 32, 32, 1><<<dim3(G_ / 64, B_ / 64), 128>>>(
        ptx, W_ih + (size_t)768 * G_, ptxp, B_, G_, DW_,
        b_lstm, 0);

    // 5. gin = emb[tok] @ W_ih[:768,:] + txp[bs]  (fused gather, early-exit)
    mm2<2, 1, 1><<<dim3(G_ / 128, (B_ * T_) / 128), 256, MM2_SMEM>>>(
        emb, W_ih, pgin, G_,
        ptxp, G_, nullptr, nullptr, plens_s, ptok);

    // 6. fused persistent LSTM recurrence (bf16 MMA, one launch, 128 steps)
    lstm_persist<<<NBLK, 256, LSTM_SMEM>>>(W_hh);

    // 7. attention scores (t-major, early-exit)
    mm2<4, 1, 0><<<dim3(DH_ / 128, (B_ * T_) / 128), 256, MM2_SMEM>>>(
        pH, Wh, nullptr, DH_,
        nullptr, 0, w_att, pscores, plens_s, nullptr);

    // 8. masked softmax
    softmax_kernel<<<B_, T_>>>();

    // 9. r = alpha . H
    rsum_kernel<<<B_, 256>>>();

    // 10. h_star = tanh(r@Wp + h_last@Wx)
    mm_k<64, 64, 32, 32, 0><<<dim3(DH_ / 64, B_ / 64), 128>>>(
        pr, Wp, ptmp, B_, DH_, DH_, nullptr, 0);
    mm_k<64, 64, 32, 32, 5><<<dim3(DH_ / 64, B_ / 64), 128>>>(
        phlast, Wx, phstar, B_, DH_, DH_, ptmp, DH_);

    // 11. logits (unsorted write)
    logit_kernel<<<B_, 128>>>(W_lin, b_lin, out);
}

// round 7
// speedup vs baseline: 3.4922x; 1.1020x over previous
#include <cuda_runtime.h>
#include <cuda_bf16.h>
#include <cuda_fp16.h>
#include <math.h>
#include <stdint.h>

// Problem constants
#define B_  256
#define T_  128
#define DW_ 768
#define DH_ 768
#define G_  3072   // 4*DH
#define NBLK 96    // persistent LSTM blocks

// ---------------- scratch (device globals) -----------------------------------
__device__ uint32_t g_x16[(size_t)B_*T_*DW_/2];      // fp16x2 embeddings (t-major, sorted)
__device__ uint32_t g_wih16[384*G_];                 // W_ih top, k-pair packed fp16x2
__device__ uint32_t g_wh16[384*DH_];                 // Wh, k-pair packed fp16x2
__device__ float g_tx[B_*DW_];                       // target embeddings (sorted, fp32)
__device__ float g_txp[B_*G_];                       // tx @ W_ih_bot + b_lstm
__device__ uint32_t g_gin16[(size_t)B_*T_*G_/2];     // gate preacts fp16x2 (t-major)
__device__ __nv_bfloat16 g_hbuf[2][B_*DH_];          // bf16 h exchange (recurrence)
__device__ float g_hlast[B_*DH_];                    // final h (fp32)
__device__ float g_H[(size_t)B_*T_*DH_];             // H fp32 (for rsum)
__device__ uint32_t g_H16[(size_t)B_*T_*DH_/2];      // H fp16x2 (for attention GEMM)
__device__ float g_scores[B_*T_];
__device__ float g_alpha[B_*T_];
__device__ float g_r[B_*DH_];
__device__ float g_tmp[B_*DH_];
__device__ float g_hstar[B_*DH_];
__device__ int   g_perm[B_];
__device__ int   g_lens_s[B_];
__device__ unsigned g_barcnt;

__device__ __forceinline__ float sigf(float x) { return 1.0f / (1.0f + expf(-x)); }

__device__ __forceinline__ uint32_t f2tf32(float f) {
    uint32_t u;
    asm("cvt.rna.tf32.f32 %0, %1;" : "=r"(u) : "f"(f));
    return u;
}
__device__ __forceinline__ uint32_t pack_bf16(float lo, float hi) {
    uint32_t r;
    asm("cvt.rn.bf16x2.f32 %0, %1, %2;" : "=r"(r) : "f"(hi), "f"(lo));
    return r;
}
__device__ __forceinline__ uint32_t pack_h2(float lo, float hi) {
    uint32_t r;
    asm("cvt.rn.f16x2.f32 %0, %1, %2;" : "=r"(r) : "f"(hi), "f"(lo));
    return r;
}

__device__ __forceinline__ void mma_tf32(float* c,
                                         uint32_t a0, uint32_t a1, uint32_t a2, uint32_t a3,
                                         uint32_t b0, uint32_t b1) {
    asm volatile(
        "mma.sync.aligned.m16n8k8.row.col.f32.tf32.tf32.f32 "
        "{%0,%1,%2,%3},{%4,%5,%6,%7},{%8,%9},{%0,%1,%2,%3};"
        : "+f"(c[0]), "+f"(c[1]), "+f"(c[2]), "+f"(c[3])
        : "r"(a0), "r"(a1), "r"(a2), "r"(a3), "r"(b0), "r"(b1));
}
__device__ __forceinline__ void mma_f16(float* c,
                                        uint32_t a0, uint32_t a1, uint32_t a2, uint32_t a3,
                                        uint32_t b0, uint32_t b1) {
    asm volatile(
        "mma.sync.aligned.m16n8k16.row.col.f32.f16.f16.f32 "
        "{%0,%1,%2,%3},{%4,%5,%6,%7},{%8,%9},{%0,%1,%2,%3};"
        : "+f"(c[0]), "+f"(c[1]), "+f"(c[2]), "+f"(c[3])
        : "r"(a0), "r"(a1), "r"(a2), "r"(a3), "r"(b0), "r"(b1));
}
__device__ __forceinline__ void mma_bf16(float* c,
                                         uint32_t a0, uint32_t a1, uint32_t a2, uint32_t a3,
                                         uint32_t b0, uint32_t b1) {
    asm volatile(
        "mma.sync.aligned.m16n8k16.row.col.f32.bf16.bf16.f32 "
        "{%0,%1,%2,%3},{%4,%5,%6,%7},{%8,%9},{%0,%1,%2,%3};"
        : "+f"(c[0]), "+f"(c[1]), "+f"(c[2]), "+f"(c[3])
        : "r"(a0), "r"(a1), "r"(a2), "r"(a3), "r"(b0), "r"(b1));
}

__device__ __forceinline__ void cpa16(uint32_t dst, const void* src) {
    asm volatile("cp.async.ca.shared.global [%0], [%1], 16;"
                 :: "r"(dst), "l"(src));
}
__device__ __forceinline__ void cpa_commit() {
    asm volatile("cp.async.commit_group;" ::: "memory");
}
template<int N>
__device__ __forceinline__ void cpa_wait() {
    asm volatile("cp.async.wait_group %0;" :: "n"(N) : "memory");
}

// ---------------- sort batch by length (descending), one block ---------------
__global__ void sort_kernel(const int* __restrict__ lens) {
    __shared__ int key[B_];
    int tid = threadIdx.x;
    key[tid] = ((128 - lens[tid]) << 8) | tid;
    __syncthreads();
    for (int k = 2; k <= B_; k <<= 1) {
        for (int j = k >> 1; j > 0; j >>= 1) {
            int ixj = tid ^ j;
            if (ixj > tid) {
                int a = key[tid], b = key[ixj];
                bool up = ((tid & k) == 0);
                if (up ? (a > b) : (a < b)) { key[tid] = b; key[ixj] = a; }
            }
            __syncthreads();
        }
    }
    g_perm[tid] = key[tid] & 255;
    g_lens_s[tid] = 128 - (key[tid] >> 8);
}

// ---------------- gather+convert x -> fp16 (t-major); gather tx fp32 ---------
__global__ void gatherx_kernel(const int* __restrict__ sent,
                               const int* __restrict__ target,
                               const float* __restrict__ emb,
                               const float* __restrict__ temb) {
    int row = blockIdx.x;
    int tid = threadIdx.x;  // 192
    if (row < B_ * T_) {
        int bs = row & 255, t = row >> 8;
        int token = sent[g_perm[bs] * T_ + t];
        const float2* src = (const float2*)(emb + (size_t)token * DW_);
        uint32_t* dst = g_x16 + (size_t)row * (DW_ / 2);
        float2 v0 = src[tid];
        float2 v1 = src[tid + 192];
        dst[tid] = pack_h2(v0.x, v0.y);
        dst[tid + 192] = pack_h2(v1.x, v1.y);
    } else {
        int bs = row - B_ * T_;
        const float4* src = (const float4*)(temb + (size_t)target[g_perm[bs]] * DW_);
        ((float4*)(g_tx + (size_t)bs * DW_))[tid] = src[tid];
    }
}

// ---------------- pack weights to k-pair fp16x2 ------------------------------
__global__ void convw_kernel(const float* __restrict__ W_ih,
                             const float* __restrict__ Wh) {
    int i = blockIdx.x * 256 + threadIdx.x;
    if (i < 384 * G_) {
        int k2 = i / G_, n = i - k2 * G_;
        g_wih16[i] = pack_h2(W_ih[(size_t)(2 * k2) * G_ + n],
                             W_ih[(size_t)(2 * k2 + 1) * G_ + n]);
    } else if (i < 384 * G_ + 384 * DH_) {
        int j = i - 384 * G_;
        int k2 = j / DH_, n = j - k2 * DH_;
        g_wh16[j] = pack_h2(Wh[(size_t)(2 * k2) * DH_ + n],
                            Wh[(size_t)(2 * k2 + 1) * DH_ + n]);
    }
}

// zero bf16 h (buffer 0), scores, barrier counter
__global__ void zeroall_kernel() {
    int i = blockIdx.x * 256 + threadIdx.x;
    if (i < B_ * DH_ / 2) ((uint32_t*)g_hbuf)[i] = 0u;
    if (i < B_ * T_) g_scores[i] = 0.0f;
    if (i == 0) g_barcnt = 0u;
}

// ---------------- fp16 cp.async pipelined 128x128 GEMM -----------------------
// A: fp16x2 rows (384 u32/row, K=768). B: k-pair packed fp16x2 [384][N] u32.
// MODE 2: gin: C16 = fp16(acc + aux[(row&255)*auxStride + col])
// MODE 4: attn: atomicAdd(sc[(row&255)*T + (row>>8)], sum_col tanh(acc)*wv[col])
// EXITP:  early-exit block if t >= exl[half*128]
template<int MODE, int EXITP>
__global__ void __launch_bounds__(256)
mm2h(const uint32_t* __restrict__ Au, const uint32_t* __restrict__ Bp,
     uint32_t* __restrict__ C16, int N,
     const float* __restrict__ aux, long long auxStride,
     const float* __restrict__ wv, float* __restrict__ sc,
     const int* __restrict__ exl) {
    constexpr int BM = 128, BN = 128, BK = 32, S = 4;
    constexpr int SA = 20;            // u32/row (16 data + 4 pad)
    constexpr int SB = 136;           // u32/row (128 data + 8 pad)
    constexpr int ASTG = BM * SA;     // 2560
    constexpr int BSTG = 16 * SB;     // 2176
    constexpr int KT = 768 / BK;      // 24

    const int m0 = blockIdx.y * BM;
    if (EXITP) {
        int t = m0 >> 8;
        int half = (m0 >> 7) & 1;
        if (t >= exl[half * 128]) return;
    }

    extern __shared__ uint32_t smu[];
    uint32_t* As = smu;
    uint32_t* Bs = smu + S * ASTG;

    const int tid = threadIdx.x;
    const int lane = tid & 31;
    const int wid = tid >> 5;
    const int wm = wid & 1;
    const int wn = wid >> 1;
    const int n0 = blockIdx.x * BN;

    const int arow = tid >> 1;
    const int abase = (tid & 1) * 8;
    const uint32_t* aptr = Au + (size_t)(m0 + arow) * 384 + abase;
    const int brow = tid >> 4;
    const int bbase = (tid & 15) * 8;
    const uint32_t* bptr = Bp + (size_t)brow * N + n0 + bbase;

    float acc[4][4][4];
#pragma unroll
    for (int i = 0; i < 4; i++)
#pragma unroll
        for (int j = 0; j < 4; j++)
#pragma unroll
            for (int q = 0; q < 4; q++) acc[i][j][q] = 0.0f;

    auto issue = [&](int kt) {
        uint32_t* as = As + (kt & (S - 1)) * ASTG;
        uint32_t* bs = Bs + (kt & (S - 1)) * BSTG;
        const uint32_t* ap = aptr + kt * 16;
        const uint32_t* bp = bptr + (size_t)kt * 16 * N;
        cpa16((uint32_t)__cvta_generic_to_shared(as + arow * SA + abase), ap);
        cpa16((uint32_t)__cvta_generic_to_shared(as + arow * SA + abase + 4), ap + 4);
        cpa16((uint32_t)__cvta_generic_to_shared(bs + brow * SB + bbase), bp);
        cpa16((uint32_t)__cvta_generic_to_shared(bs + brow * SB + bbase + 4), bp + 4);
    };

#pragma unroll
    for (int s = 0; s < S - 1; s++) { issue(s); cpa_commit(); }

    for (int kt = 0; kt < KT; kt++) {
        cpa_wait<S - 2>();
        __syncthreads();
        if (kt + S - 1 < KT) issue(kt + S - 1);
        cpa_commit();

        const uint32_t* asU = As + (kt & (S - 1)) * ASTG;
        const uint32_t* bsU = Bs + (kt & (S - 1)) * BSTG;
#pragma unroll
        for (int ks = 0; ks < 2; ks++) {          // two k16 steps per BK=32
            int kq = ks * 8 + (lane & 3);
            uint32_t af[4][4], bf[4][2];
#pragma unroll
            for (int mt = 0; mt < 4; mt++) {
                int m = wm * 64 + mt * 16 + (lane >> 2);
                af[mt][0] = asU[m * SA + kq];
                af[mt][1] = asU[(m + 8) * SA + kq];
                af[mt][2] = asU[m * SA + kq + 4];
                af[mt][3] = asU[(m + 8) * SA + kq + 4];
            }
#pragma unroll
            for (int nt = 0; nt < 4; nt++) {
                int n = wn * 32 + nt * 8 + (lane >> 2);
                bf[nt][0] = bsU[kq * SB + n];
                bf[nt][1] = bsU[(kq + 4) * SB + n];
            }
#pragma unroll
            for (int mt = 0; mt < 4; mt++)
#pragma unroll
                for (int nt = 0; nt < 4; nt++)
                    mma_f16(acc[mt][nt],
                            af[mt][0], af[mt][1], af[mt][2], af[mt][3],
                            bf[nt][0], bf[nt][1]);
        }
    }

    if (MODE == 4) {
#pragma unroll
        for (int mt = 0; mt < 4; mt++) {
            float pl = 0.0f, ph = 0.0f;
#pragma unroll
            for (int nt = 0; nt < 4; nt++) {
                int col = n0 + wn * 32 + nt * 8 + ((lane & 3) << 1);
                float w0 = wv[col], w1 = wv[col + 1];
                pl += tanhf(acc[mt][nt][0]) * w0 + tanhf(acc[mt][nt][1]) * w1;
                ph += tanhf(acc[mt][nt][2]) * w0 + tanhf(acc[mt][nt][3]) * w1;
            }
            pl += __shfl_xor_sync(0xffffffffu, pl, 1);
            pl += __shfl_xor_sync(0xffffffffu, pl, 2);
            ph += __shfl_xor_sync(0xffffffffu, ph, 1);
            ph += __shfl_xor_sync(0xffffffffu, ph, 2);
            if ((lane & 3) == 0) {
                int r = m0 + wm * 64 + mt * 16 + (lane >> 2);
                atomicAdd(&sc[(r & 255) * T_ + (r >> 8)], pl);
                atomicAdd(&sc[((r + 8) & 255) * T_ + ((r + 8) >> 8)], ph);
            }
        }
    } else {
        const int N2 = N >> 1;
#pragma unroll
        for (int mt = 0; mt < 4; mt++) {
#pragma unroll
            for (int nt = 0; nt < 4; nt++) {
                int r = m0 + wm * 64 + mt * 16 + (lane >> 2);
                int c = n0 + wn * 32 + nt * 8 + ((lane & 3) << 1);
                float v0 = acc[mt][nt][0], v1 = acc[mt][nt][1];
                float v2 = acc[mt][nt][2], v3 = acc[mt][nt][3];
                const float* ar  = aux + (size_t)(r & 255) * auxStride;
                const float* ar8 = aux + (size_t)((r + 8) & 255) * auxStride;
                v0 += ar[c];  v1 += ar[c + 1];
                v2 += ar8[c]; v3 += ar8[c + 1];
                C16[(size_t)r * N2 + (c >> 1)] = pack_h2(v0, v1);
                C16[(size_t)(r + 8) * N2 + (c >> 1)] = pack_h2(v2, v3);
            }
        }
    }
}

// ---------------- small tf32 GEMM (64x64 tiles) -------------------------------
// MODE 0: C = acc;  MODE 1: C = acc + aux[col];  MODE 5: C = tanh(acc + aux[row*S+col])
template<int BM, int BN, int WM, int WN, int MODE>
__global__ void __launch_bounds__((BM/WM)*(BN/WN)*32)
mm_k(const float* __restrict__ A, const float* __restrict__ Bm,
     float* __restrict__ C, int M, int N, int K,
     const float* __restrict__ aux, long long auxStride) {
    constexpr int BK = 16;
    constexpr int NWARP = (BM / WM) * (BN / WN);
    constexpr int NT = NWARP * 32;
    constexpr int SA = BK + 4;
    constexpr int SB = BN + 8;
    constexpr int MT = WM / 16;
    constexpr int NL = WN / 8;
    constexpr int AQ = (BM * 4) / NT;
    constexpr int BQ = (BN * 4) / NT;

    __shared__ __align__(16) uint32_t As[BM][SA];
    __shared__ __align__(16) uint32_t Bs[BK][SB];

    const int tid = threadIdx.x;
    const int lane = tid & 31;
    const int wid = tid >> 5;
    const int wm = wid % (BM / WM);
    const int wn = wid / (BM / WM);
    const int m0 = blockIdx.y * BM;
    const int n0 = blockIdx.x * BN;

    float acc[MT][NL][4];
#pragma unroll
    for (int i = 0; i < MT; i++)
#pragma unroll
        for (int j = 0; j < NL; j++)
#pragma unroll
            for (int q = 0; q < 4; q++) acc[i][j][q] = 0.0f;

    float4 pa[AQ], pb[BQ];
    const int KT = K / BK;

#pragma unroll
    for (int q = 0; q < AQ; q++) {
        int idx = tid + q * NT;
        pa[q] = *(const float4*)(A + (size_t)(m0 + (idx >> 2)) * K + ((idx & 3) << 2));
    }
#pragma unroll
    for (int q = 0; q < BQ; q++) {
        int idx = tid + q * NT;
        pb[q] = *(const float4*)(Bm + (size_t)(idx / (BN / 4)) * N + n0 + ((idx % (BN / 4)) << 2));
    }

    for (int kt = 0; kt < KT; kt++) {
#pragma unroll
        for (int q = 0; q < AQ; q++) {
            int idx = tid + q * NT;
            uint4 v = make_uint4(f2tf32(pa[q].x), f2tf32(pa[q].y),
                                 f2tf32(pa[q].z), f2tf32(pa[q].w));
            *(uint4*)&As[idx >> 2][(idx & 3) << 2] = v;
        }
#pragma unroll
        for (int q = 0; q < BQ; q++) {
            int idx = tid + q * NT;
            uint4 v = make_uint4(f2tf32(pb[q].x), f2tf32(pb[q].y),
                                 f2tf32(pb[q].z), f2tf32(pb[q].w));
            *(uint4*)&Bs[idx / (BN / 4)][(idx % (BN / 4)) << 2] = v;
        }
        __syncthreads();

        if (kt + 1 < KT) {
            int k0 = (kt + 1) * BK;
#pragma unroll
            for (int q = 0; q < AQ; q++) {
                int idx = tid + q * NT;
                pa[q] = *(const float4*)(A + (size_t)(m0 + (idx >> 2)) * K + k0 + ((idx & 3) << 2));
            }
#pragma unroll
            for (int q = 0; q < BQ; q++) {
                int idx = tid + q * NT;
                pb[q] = *(const float4*)(Bm + (size_t)(k0 + idx / (BN / 4)) * N + n0 + ((idx % (BN / 4)) << 2));
            }
        }

#pragma unroll
        for (int ks = 0; ks < 2; ks++) {
            uint32_t af[MT][4];
            uint32_t bf[NL][2];
            int kc = ks * 8 + (lane & 3);
#pragma unroll
            for (int mt = 0; mt < MT; mt++) {
                int r = wm * WM + mt * 16 + (lane >> 2);
                af[mt][0] = As[r][kc];
                af[mt][1] = As[r + 8][kc];
                af[mt][2] = As[r][kc + 4];
                af[mt][3] = As[r + 8][kc + 4];
            }
#pragma unroll
            for (int nt = 0; nt < NL; nt++) {
                int n = wn * WN + nt * 8 + (lane >> 2);
                bf[nt][0] = Bs[kc][n];
                bf[nt][1] = Bs[kc + 4][n];
            }
#pragma unroll
            for (int mt = 0; mt < MT; mt++)
#pragma unroll
                for (int nt = 0; nt < NL; nt++)
                    mma_tf32(acc[mt][nt],
                             af[mt][0], af[mt][1], af[mt][2], af[mt][3],
                             bf[nt][0], bf[nt][1]);
        }
        __syncthreads();
    }

#pragma unroll
    for (int mt = 0; mt < MT; mt++) {
#pragma unroll
        for (int nt = 0; nt < NL; nt++) {
            int r = m0 + wm * WM + mt * 16 + (lane >> 2);
            int c = n0 + wn * WN + nt * 8 + ((lane & 3) << 1);
            float v0 = acc[mt][nt][0], v1 = acc[mt][nt][1];
            float v2 = acc[mt][nt][2], v3 = acc[mt][nt][3];
            if (MODE == 1) {
                v0 += aux[c]; v1 += aux[c + 1];
                v2 += aux[c]; v3 += aux[c + 1];
            }
            if (MODE == 5) {
                const float* ar  = aux + (size_t)r * auxStride;
                const float* ar8 = aux + (size_t)(r + 8) * auxStride;
                v0 = tanhf(v0 + ar[c]);  v1 = tanhf(v1 + ar[c + 1]);
                v2 = tanhf(v2 + ar8[c]); v3 = tanhf(v3 + ar8[c + 1]);
            }
            *(float2*)&C[(size_t)r * N + c] = make_float2(v0, v1);
            *(float2*)&C[(size_t)(r + 8) * N + c] = make_float2(v2, v3);
        }
    }
}

// ---------------- persistent fused LSTM recurrence (bf16 MMA) ----------------
__global__ void __launch_bounds__(256, 1)
lstm_persist(const float* __restrict__ W_hh) {
    extern __shared__ uint32_t sm_[];
    uint32_t* ws = sm_;                        // 4 nt * 384 k2 * 8 nn
    uint32_t* Ab = sm_ + 12288;                // 2 * 256 * 20
    int* slens = (int*)(sm_ + 12288 + 10240);
    int* nact  = (int*)(sm_ + 12288 + 10240 + 256);

    const int tid = threadIdx.x;
    const int lane = tid & 31;
    const int w = tid >> 5;
    const int nb = blockIdx.x;

    for (int i = tid; i < 12288; i += 256) {
        int nt = i / 3072;
        int rem = i - nt * 3072;
        int k2 = rem >> 3, nn = rem & 7;
        int col = nt * 768 + nb * 8 + nn;
        float w0 = W_hh[(size_t)(2 * k2) * G_ + col];
        float w1 = W_hh[(size_t)(2 * k2 + 1) * G_ + col];
        ws[i] = pack_bf16(w0, w1);
    }
    slens[tid] = g_lens_s[tid];
    __syncthreads();
    for (int i = tid; i < T_; i += 256) {
        int c = 0;
        for (int b = 0; b < B_; b++) c += (slens[b] > i) ? 1 : 0;
        int n32 = (c + 31) & ~31;
        nact[i] = n32 > 256 ? 256 : n32;
    }
    __syncthreads();

    float c_reg[2][4], h_reg[2][4];
#pragma unroll
    for (int i = 0; i < 2; i++)
#pragma unroll
        for (int q = 0; q < 4; q++) { c_reg[i][q] = 0.0f; h_reg[i][q] = 0.0f; }

    const int srow = tid;
    unsigned epoch = 0;

    for (int t = 0; t < T_; t++) {
        const __nv_bfloat16* hcur = g_hbuf[t & 1];
        __nv_bfloat16* hnxt = g_hbuf[(t + 1) & 1];
        const int n32 = nact[t];
        const bool sact = (srow < n32);
        const bool wact = (w * 32 < n32);

        float acc[2][4][4];
#pragma unroll
        for (int i = 0; i < 2; i++)
#pragma unroll
            for (int j = 0; j < 4; j++)
#pragma unroll
                for (int q = 0; q < 4; q++) acc[i][j][q] = 0.0f;

        uint4 stg[4];
        if (sact) {
            const uint4* s = (const uint4*)(hcur + (size_t)srow * DH_);
            stg[0] = s[0]; stg[1] = s[1]; stg[2] = s[2]; stg[3] = s[3];
            uint32_t* d = Ab + srow * 20;
            *(uint4*)(d + 0) = stg[0]; *(uint4*)(d + 4) = stg[1];
            *(uint4*)(d + 8) = stg[2]; *(uint4*)(d + 12) = stg[3];
        }
        __syncthreads();

        for (int cch = 0; cch < 24; cch++) {
            const uint32_t* Ac = Ab + (cch & 1) * 5120;
            if (cch < 23 && sact) {
                const uint4* s = (const uint4*)(hcur + (size_t)srow * DH_ + (cch + 1) * 32);
                stg[0] = s[0]; stg[1] = s[1]; stg[2] = s[2]; stg[3] = s[3];
            }
            if (wact) {
#pragma unroll
                for (int ks = 0; ks < 2; ks++) {
                    int kc = ks * 8 + (lane & 3);
                    int k2 = cch * 16 + ks * 8 + (lane & 3);
                    uint32_t af[2][4], bf[4][2];
#pragma unroll
                    for (int mt = 0; mt < 2; mt++) {
                        int m = w * 32 + mt * 16 + (lane >> 2);
                        af[mt][0] = Ac[m * 20 + kc];
                        af[mt][1] = Ac[(m + 8) * 20 + kc];
                        af[mt][2] = Ac[m * 20 + kc + 4];
                        af[mt][3] = Ac[(m + 8) * 20 + kc + 4];
                    }
#pragma unroll
                    for (int nt = 0; nt < 4; nt++) {
                        bf[nt][0] = ws[nt * 3072 + k2 * 8 + (lane >> 2)];
                        bf[nt][1] = ws[nt * 3072 + (k2 + 4) * 8 + (lane >> 2)];
                    }
#pragma unroll
                    for (int mt = 0; mt < 2; mt++)
#pragma unroll
                        for (int nt = 0; nt < 4; nt++)
                            mma_bf16(acc[mt][nt],
                                     af[mt][0], af[mt][1], af[mt][2], af[mt][3],
                                     bf[nt][0], bf[nt][1]);
                }
            }
            if (cch < 23 && sact) {
                uint32_t* d = Ab + ((cch + 1) & 1) * 5120 + srow * 20;
                *(uint4*)(d + 0) = stg[0]; *(uint4*)(d + 4) = stg[1];
                *(uint4*)(d + 8) = stg[2]; *(uint4*)(d + 12) = stg[3];
            }
            __syncthreads();
        }

        // ---- in-register LSTM pointwise (fp16 gin) ----
        int jcol = nb * 8 + ((lane & 3) << 1);
#pragma unroll
        for (int mt = 0; mt < 2; mt++) {
#pragma unroll
            for (int half = 0; half < 2; half++) {
                int r = w * 32 + mt * 16 + (lane >> 2) + half * 8;
                bool valid = (t < slens[r]);
                float2 bi = make_float2(0.f, 0.f), bff = bi, bg = bi, bo = bi;
                if (valid) {
                    const uint32_t* gp = g_gin16 + ((size_t)(t * B_ + r)) * (G_ / 2) + (jcol >> 1);
                    bi  = __half22float2(*(const __half2*)&gp[0]);
                    bff = __half22float2(*(const __half2*)&gp[384]);
                    bg  = __half22float2(*(const __half2*)&gp[768]);
                    bo  = __half22float2(*(const __half2*)&gp[1152]);
                }
                float hv0, hv1;
#pragma unroll
                for (int sub = 0; sub < 2; sub++) {
                    int q = half * 2 + sub;
                    float iv = acc[mt][0][q] + (sub ? bi.y : bi.x);
                    float fv = acc[mt][1][q] + (sub ? bff.y : bff.x);
                    float gv = acc[mt][2][q] + (sub ? bg.y : bg.x);
                    float ov = acc[mt][3][q] + (sub ? bo.y : bo.x);
                    float cn = sigf(fv) * c_reg[mt][q] + sigf(iv) * tanhf(gv);
                    float hn = sigf(ov) * tanhf(cn);
                    c_reg[mt][q] = valid ? cn : c_reg[mt][q];
                    float hv = valid ? hn : h_reg[mt][q];
                    h_reg[mt][q] = hv;
                    if (sub == 0) hv0 = hv; else hv1 = hv;
                }
                *(uint32_t*)&hnxt[(size_t)r * DH_ + jcol] = pack_bf16(hv0, hv1);
                *(float2*)&g_H[((size_t)(t * B_ + r)) * DH_ + jcol] = make_float2(hv0, hv1);
                g_H16[((size_t)(t * B_ + r)) * (DH_ / 2) + (jcol >> 1)] = pack_h2(hv0, hv1);
                if (t == T_ - 1)
                    *(float2*)&g_hlast[(size_t)r * DH_ + jcol] = make_float2(hv0, hv1);
            }
        }

        // ---- grid barrier ----
        __threadfence();
        __syncthreads();
        if (tid == 0) {
            atomicAdd(&g_barcnt, 1u);
            epoch++;
            unsigned target = epoch * NBLK;
            unsigned v;
            do {
                asm volatile("ld.acquire.gpu.global.u32 %0, [%1];"
                             : "=r"(v) : "l"(&g_barcnt));
                if (v < target) __nanosleep(64);
            } while (v < target);
        }
        __syncthreads();
    }
}

// ---------------- masked softmax over t (per sorted batch row) ---------------
__global__ void softmax_kernel() {
    int b = blockIdx.x;
    int t = threadIdx.x;
    int len = g_lens_s[b];
    float s = (t < len) ? g_scores[b * T_ + t] : -1e30f;

    float m = s;
#pragma unroll
    for (int off = 16; off > 0; off >>= 1)
        m = fmaxf(m, __shfl_down_sync(0xffffffffu, m, off));
    __shared__ float sm[4];
    if ((t & 31) == 0) sm[t >> 5] = m;
    __syncthreads();
    if (t == 0) {
        float mm = sm[0];
        mm = fmaxf(mm, sm[1]); mm = fmaxf(mm, sm[2]); mm = fmaxf(mm, sm[3]);
        sm[0] = mm;
    }
    __syncthreads();
    float mx = sm[0];

    float e = (t < len) ? expf(s - mx) : 0.0f;
    float sum = e;
#pragma unroll
    for (int off = 16; off > 0; off >>= 1)
        sum += __shfl_down_sync(0xffffffffu, sum, off);
    __shared__ float ss[4];
    if ((t & 31) == 0) ss[t >> 5] = sum;
    __syncthreads();
    if (t == 0) ss[0] = ss[0] + ss[1] + ss[2] + ss[3];
    __syncthreads();
    g_alpha[b * T_ + t] = e / ss[0];
}

// ---------------- r = sum_t alpha[b,t] * H[t,b,:]  (fp32 H) ------------------
__global__ void rsum_kernel() {
    int b = blockIdx.x;
    int tid = threadIdx.x;
    __shared__ float al[T_];
    __shared__ int slen;
    if (tid < T_) al[tid] = g_alpha[b * T_ + tid];
    if (tid == 0) slen = g_lens_s[b];
    __syncthreads();
    int len = slen;
    float a0 = 0.0f, a1 = 0.0f, a2 = 0.0f;
    for (int t = 0; t < len; t++) {
        float a = al[t];
        const float* Hr = g_H + ((size_t)(t * B_ + b)) * DH_;
        a0 += a * Hr[tid];
        a1 += a * Hr[tid + 256];
        a2 += a * Hr[tid + 512];
    }
    g_r[b * DH_ + tid] = a0;
    g_r[b * DH_ + tid + 256] = a1;
    g_r[b * DH_ + tid + 512] = a2;
}

// ---------------- logit = h_star @ W_lin + b_lin (unsort at write) -----------
__global__ void logit_kernel(const float* __restrict__ Wl,
                             const float* __restrict__ bl,
                             float* __restrict__ out) {
    int b = blockIdx.x;
    int tid = threadIdx.x;
    float p0 = 0.0f, p1 = 0.0f, p2 = 0.0f;
    for (int j = tid; j < DH_; j += 128) {
        float v = g_hstar[b * DH_ + j];
        p0 += v * Wl[j * 3 + 0];
        p1 += v * Wl[j * 3 + 1];
        p2 += v * Wl[j * 3 + 2];
    }
#pragma unroll
    for (int off = 16; off > 0; off >>= 1) {
        p0 += __shfl_down_sync(0xffffffffu, p0, off);
        p1 += __shfl_down_sync(0xffffffffu, p1, off);
        p2 += __shfl_down_sync(0xffffffffu, p2, off);
    }
    __shared__ float sm[3][4];
    if ((tid & 31) == 0) {
        sm[0][tid >> 5] = p0; sm[1][tid >> 5] = p1; sm[2][tid >> 5] = p2;
    }
    __syncthreads();
    if (tid < 3) {
        float s = sm[tid][0] + sm[tid][1] + sm[tid][2] + sm[tid][3];
        out[g_perm[b] * 3 + tid] = s + bl[tid];
    }
}

// ---------------- launch ------------------------------------------------------
extern "C" void kernel_launch(void* const* d_in, const int* in_sizes, int n_in,
                              void* d_out, int out_size) {
    const int*   sent   = (const int*)d_in[0];
    const int*   target = (const int*)d_in[1];
    const int*   lens   = (const int*)d_in[2];
    const float* emb    = (const float*)d_in[3];
    const float* temb   = (const float*)d_in[4];
    const float* W_ih   = (const float*)d_in[5];   // (1536, 3072)
    const float* W_hh   = (const float*)d_in[6];   // (768, 3072)
    const float* b_lstm = (const float*)d_in[7];   // (3072,)
    const float* Wh     = (const float*)d_in[8];   // (768, 768)
    // d_in[9] = Wv — unused: aspect score term constant over t, cancels in softmax.
    const float* w_att  = (const float*)d_in[10];  // (1536,), first 768 used
    const float* Wp     = (const float*)d_in[11];
    const float* Wx     = (const float*)d_in[12];
    const float* W_lin  = (const float*)d_in[13];  // (768, 3)
    const float* b_lin  = (const float*)d_in[14];
    float* out = (float*)d_out;

    float *ptx, *ptxp, *phlast, *pscores, *pr, *ptmp, *phstar;
    uint32_t *px16, *pwih16, *pwh16, *pgin16, *pH16;
    int *plens_s;
    cudaGetSymbolAddress((void**)&ptx,     g_tx);
    cudaGetSymbolAddress((void**)&ptxp,    g_txp);
    cudaGetSymbolAddress((void**)&phlast,  g_hlast);
    cudaGetSymbolAddress((void**)&pscores, g_scores);
    cudaGetSymbolAddress((void**)&pr,      g_r);
    cudaGetSymbolAddress((void**)&ptmp,    g_tmp);
    cudaGetSymbolAddress((void**)&phstar,  g_hstar);
    cudaGetSymbolAddress((void**)&plens_s, g_lens_s);
    cudaGetSymbolAddress((void**)&px16,    g_x16);
    cudaGetSymbolAddress((void**)&pwih16,  g_wih16);
    cudaGetSymbolAddress((void**)&pwh16,   g_wh16);
    cudaGetSymbolAddress((void**)&pgin16,  g_gin16);
    cudaGetSymbolAddress((void**)&pH16,    g_H16);

    const int LSTM_SMEM = (12288 + 10240) * 4 + 256 * 4 + 128 * 4;  // 91,648 B
    cudaFuncSetAttribute(lstm_persist,
                         cudaFuncAttributeMaxDynamicSharedMemorySize, LSTM_SMEM);
    const int MM2H_SMEM = 4 * (2560 + 2176) * 4;  // 75,776 B
    cudaFuncSetAttribute(mm2h<2, 1>,
                         cudaFuncAttributeMaxDynamicSharedMemorySize, MM2H_SMEM);
    cudaFuncSetAttribute(mm2h<4, 1>,
                         cudaFuncAttributeMaxDynamicSharedMemorySize, MM2H_SMEM);

    // 1. sort batch by length (descending)
    sort_kernel<<<1, B_>>>(lens);

    // 2. gather+convert x -> fp16 (t-major), gather tx (fp32)
    gatherx_kernel<<<B_ * T_ + B_, 192>>>(sent, target, emb, temb);

    // 3. pack W_ih_top / Wh to fp16 pairs
    convw_kernel<<<(384 * G_ + 384 * DH_ + 255) / 256, 256>>>(W_ih, Wh);

    // 4. zero h buffer (bf16), scores, barrier counter
    zeroall_kernel<<<(B_ * DH_ / 2 + 255) / 256, 256>>>();

    // 5. txp = tx @ W_ih[768:,:] + b_lstm      (256 x 3072, K=768, tf32)
    mm_k<64, 64, 32, 32, 1><<<dim3(G_ / 64, B_ / 64), 128>>>(
        ptx, W_ih + (size_t)768 * G_, ptxp, B_, G_, DW_,
        b_lstm, 0);

    // 6. gin = x16 @ Wih16 + txp[bs]   (fp16 MMA, early-exit, fp16 output)
    mm2h<2, 1><<<dim3(G_ / 128, (B_ * T_) / 128), 256, MM2H_SMEM>>>(
        px16, pwih16, pgin16, G_,
        ptxp, G_, nullptr, nullptr, plens_s);

    // 7. fused persistent LSTM recurrence
    lstm_persist<<<NBLK, 256, LSTM_SMEM>>>(W_hh);

    // 8. attention scores (fp16 MMA, early-exit)
    mm2h<4, 1><<<dim3(DH_ / 128, (B_ * T_) / 128), 256, MM2H_SMEM>>>(
        pH16, pwh16, nullptr, DH_,
        nullptr, 0, w_att, pscores, plens_s);

    // 9. masked softmax
    softmax_kernel<<<B_, T_>>>();

    // 10. r = alpha . H
    rsum_kernel<<<B_, 256>>>();

    // 11. h_star = tanh(r@Wp + h_last@Wx)
    mm_k<64, 64, 32, 32, 0><<<dim3(DH_ / 64, B_ / 64), 128>>>(
        pr, Wp, ptmp, B_, DH_, DH_, nullptr, 0);
    mm_k<64, 64, 32, 32, 5><<<dim3(DH_ / 64, B_ / 64), 128>>>(
        phlast, Wx, phstar, B_, DH_, DH_, ptmp, DH_);

    // 12. logits (unsorted write)
    logit_kernel<<<B_, 128>>>(W_lin, b_lin, out);
}

// round 8
// speedup vs baseline: 4.0132x; 1.1492x over previous
#include <cuda_runtime.h>
#include <cuda_bf16.h>
#include <cuda_fp16.h>
#include <math.h>
#include <stdint.h>

// Problem constants
#define B_  256
#define T_  128
#define DW_ 768
#define DH_ 768
#define G_  3072   // 4*DH
#define NBLK 96    // persistent LSTM blocks

// ---------------- scratch (device globals) -----------------------------------
__device__ uint32_t g_x16[(size_t)B_*T_*DW_/2];      // fp16x2 embeddings (t-major, sorted)
__device__ uint32_t g_wih16[384*G_];                 // W_ih top, k-pair packed fp16x2
__device__ uint32_t g_wh16[384*DH_];                 // Wh, k-pair packed fp16x2
__device__ float g_tx[B_*DW_];                       // target embeddings (sorted, fp32)
__device__ float g_txp[B_*G_];                       // tx @ W_ih_bot + b_lstm
__device__ uint32_t g_gin16[(size_t)B_*T_*G_/2];     // gate preacts fp16x2 (t-major)
__device__ __nv_bfloat16 g_hbuf[2][B_*DH_];          // bf16 h exchange (recurrence)
__device__ float g_hlast[B_*DH_];                    // final h (fp32)
__device__ float g_H[(size_t)B_*T_*DH_];             // H fp32 (for rsum)
__device__ uint32_t g_H16[(size_t)B_*T_*DH_/2];      // H fp16x2 (for attention GEMM)
__device__ float g_scores[B_*T_];
__device__ float g_alpha[B_*T_];
__device__ float g_r[B_*DH_];
__device__ float g_tmp[B_*DH_];
__device__ float g_hstar[B_*DH_];
__device__ int   g_perm[B_];
__device__ int   g_lens_s[B_];
__device__ unsigned g_barcnt;

__device__ __forceinline__ float sigf(float x) { return 1.0f / (1.0f + expf(-x)); }

__device__ __forceinline__ uint32_t f2tf32(float f) {
    uint32_t u;
    asm("cvt.rna.tf32.f32 %0, %1;" : "=r"(u) : "f"(f));
    return u;
}
__device__ __forceinline__ uint32_t pack_bf16(float lo, float hi) {
    uint32_t r;
    asm("cvt.rn.bf16x2.f32 %0, %1, %2;" : "=r"(r) : "f"(hi), "f"(lo));
    return r;
}
__device__ __forceinline__ uint32_t pack_h2(float lo, float hi) {
    uint32_t r;
    asm("cvt.rn.f16x2.f32 %0, %1, %2;" : "=r"(r) : "f"(hi), "f"(lo));
    return r;
}

__device__ __forceinline__ void mma_tf32(float* c,
                                         uint32_t a0, uint32_t a1, uint32_t a2, uint32_t a3,
                                         uint32_t b0, uint32_t b1) {
    asm volatile(
        "mma.sync.aligned.m16n8k8.row.col.f32.tf32.tf32.f32 "
        "{%0,%1,%2,%3},{%4,%5,%6,%7},{%8,%9},{%0,%1,%2,%3};"
        : "+f"(c[0]), "+f"(c[1]), "+f"(c[2]), "+f"(c[3])
        : "r"(a0), "r"(a1), "r"(a2), "r"(a3), "r"(b0), "r"(b1));
}
__device__ __forceinline__ void mma_f16(float* c,
                                        uint32_t a0, uint32_t a1, uint32_t a2, uint32_t a3,
                                        uint32_t b0, uint32_t b1) {
    asm volatile(
        "mma.sync.aligned.m16n8k16.row.col.f32.f16.f16.f32 "
        "{%0,%1,%2,%3},{%4,%5,%6,%7},{%8,%9},{%0,%1,%2,%3};"
        : "+f"(c[0]), "+f"(c[1]), "+f"(c[2]), "+f"(c[3])
        : "r"(a0), "r"(a1), "r"(a2), "r"(a3), "r"(b0), "r"(b1));
}
__device__ __forceinline__ void mma_bf16(float* c,
                                         uint32_t a0, uint32_t a1, uint32_t a2, uint32_t a3,
                                         uint32_t b0, uint32_t b1) {
    asm volatile(
        "mma.sync.aligned.m16n8k16.row.col.f32.bf16.bf16.f32 "
        "{%0,%1,%2,%3},{%4,%5,%6,%7},{%8,%9},{%0,%1,%2,%3};"
        : "+f"(c[0]), "+f"(c[1]), "+f"(c[2]), "+f"(c[3])
        : "r"(a0), "r"(a1), "r"(a2), "r"(a3), "r"(b0), "r"(b1));
}
__device__ __forceinline__ void ldsm4(uint32_t& r0, uint32_t& r1,
                                      uint32_t& r2, uint32_t& r3, uint32_t addr) {
    asm volatile("ldmatrix.sync.aligned.m8n8.x4.shared.b16 {%0,%1,%2,%3}, [%4];"
                 : "=r"(r0), "=r"(r1), "=r"(r2), "=r"(r3) : "r"(addr));
}

__device__ __forceinline__ void cpa16(uint32_t dst, const void* src) {
    asm volatile("cp.async.ca.shared.global [%0], [%1], 16;"
                 :: "r"(dst), "l"(src));
}
__device__ __forceinline__ void cpa_commit() {
    asm volatile("cp.async.commit_group;" ::: "memory");
}
template<int N>
__device__ __forceinline__ void cpa_wait() {
    asm volatile("cp.async.wait_group %0;" :: "n"(N) : "memory");
}

// ---------------- sort batch by length (descending), one block ---------------
__global__ void sort_kernel(const int* __restrict__ lens) {
    __shared__ int key[B_];
    int tid = threadIdx.x;
    key[tid] = ((128 - lens[tid]) << 8) | tid;
    __syncthreads();
    for (int k = 2; k <= B_; k <<= 1) {
        for (int j = k >> 1; j > 0; j >>= 1) {
            int ixj = tid ^ j;
            if (ixj > tid) {
                int a = key[tid], b = key[ixj];
                bool up = ((tid & k) == 0);
                if (up ? (a > b) : (a < b)) { key[tid] = b; key[ixj] = a; }
            }
            __syncthreads();
        }
    }
    g_perm[tid] = key[tid] & 255;
    g_lens_s[tid] = 128 - (key[tid] >> 8);
}

// ---------------- gather+convert x -> fp16 (t-major); gather tx fp32 ---------
__global__ void gatherx_kernel(const int* __restrict__ sent,
                               const int* __restrict__ target,
                               const float* __restrict__ emb,
                               const float* __restrict__ temb) {
    int row = blockIdx.x;
    int tid = threadIdx.x;  // 192
    if (row < B_ * T_) {
        int bs = row & 255, t = row >> 8;
        int token = sent[g_perm[bs] * T_ + t];
        const float2* src = (const float2*)(emb + (size_t)token * DW_);
        uint32_t* dst = g_x16 + (size_t)row * (DW_ / 2);
        float2 v0 = src[tid];
        float2 v1 = src[tid + 192];
        dst[tid] = pack_h2(v0.x, v0.y);
        dst[tid + 192] = pack_h2(v1.x, v1.y);
    } else {
        int bs = row - B_ * T_;
        const float4* src = (const float4*)(temb + (size_t)target[g_perm[bs]] * DW_);
        ((float4*)(g_tx + (size_t)bs * DW_))[tid] = src[tid];
    }
}

// ---------------- pack weights to k-pair fp16x2 ------------------------------
__global__ void convw_kernel(const float* __restrict__ W_ih,
                             const float* __restrict__ Wh) {
    int i = blockIdx.x * 256 + threadIdx.x;
    if (i < 384 * G_) {
        int k2 = i / G_, n = i - k2 * G_;
        g_wih16[i] = pack_h2(W_ih[(size_t)(2 * k2) * G_ + n],
                             W_ih[(size_t)(2 * k2 + 1) * G_ + n]);
    } else if (i < 384 * G_ + 384 * DH_) {
        int j = i - 384 * G_;
        int k2 = j / DH_, n = j - k2 * DH_;
        g_wh16[j] = pack_h2(Wh[(size_t)(2 * k2) * DH_ + n],
                            Wh[(size_t)(2 * k2 + 1) * DH_ + n]);
    }
}

// zero bf16 h (buffer 0), scores, barrier counter
__global__ void zeroall_kernel() {
    int i = blockIdx.x * 256 + threadIdx.x;
    if (i < B_ * DH_ / 2) ((uint32_t*)g_hbuf)[i] = 0u;
    if (i < B_ * T_) g_scores[i] = 0.0f;
    if (i == 0) g_barcnt = 0u;
}

// ---------------- fp16 cp.async pipelined 128x128 GEMM (ldmatrix A) ----------
// A: fp16x2 rows (384 u32/row, K=768). B: k-pair packed fp16x2 [384][N] u32.
// MODE 2: gin: C16 = fp16(acc + aux[(row&255)*auxStride + col])
// MODE 4: attn: atomicAdd(sc[(row&255)*T + (row>>8)], sum_col tanh(acc)*wv[col])
// EXITP:  early-exit block if t >= exl[half*128]
template<int MODE, int EXITP>
__global__ void __launch_bounds__(256)
mm2h(const uint32_t* __restrict__ Au, const uint32_t* __restrict__ Bp,
     uint32_t* __restrict__ C16, int N,
     const float* __restrict__ aux, long long auxStride,
     const float* __restrict__ wv, float* __restrict__ sc,
     const int* __restrict__ exl) {
    constexpr int BM = 128, BN = 128, BK = 32, S = 4;
    constexpr int SA = 20;            // u32/row (16 data + 4 pad)
    constexpr int SB = 136;           // u32/row (128 data + 8 pad)
    constexpr int ASTG = BM * SA;     // 2560
    constexpr int BSTG = 16 * SB;     // 2176
    constexpr int KT = 768 / BK;      // 24

    const int m0 = blockIdx.y * BM;
    if (EXITP) {
        int t = m0 >> 8;
        int half = (m0 >> 7) & 1;
        if (t >= exl[half * 128]) return;
    }

    extern __shared__ uint32_t smu[];
    uint32_t* As = smu;
    uint32_t* Bs = smu + S * ASTG;

    const int tid = threadIdx.x;
    const int lane = tid & 31;
    const int wid = tid >> 5;
    const int wm = wid & 1;
    const int wn = wid >> 1;
    const int n0 = blockIdx.x * BN;

    const int arow = tid >> 1;
    const int abase = (tid & 1) * 8;
    const uint32_t* aptr = Au + (size_t)(m0 + arow) * 384 + abase;
    const int brow = tid >> 4;
    const int bbase = (tid & 15) * 8;
    const uint32_t* bptr = Bp + (size_t)brow * N + n0 + bbase;

    // ldmatrix per-thread byte offsets for the 4 m-tiles of this warp
    const uint32_t As_sh = (uint32_t)__cvta_generic_to_shared(As);
    uint32_t rowoffA[4];
#pragma unroll
    for (int mt = 0; mt < 4; mt++)
        rowoffA[mt] = ((wm * 64 + mt * 16 + (lane & 15)) * SA + (lane >> 4) * 4) * 4;

    float acc[4][4][4];
#pragma unroll
    for (int i = 0; i < 4; i++)
#pragma unroll
        for (int j = 0; j < 4; j++)
#pragma unroll
            for (int q = 0; q < 4; q++) acc[i][j][q] = 0.0f;

    auto issue = [&](int kt) {
        uint32_t* as = As + (kt & (S - 1)) * ASTG;
        uint32_t* bs = Bs + (kt & (S - 1)) * BSTG;
        const uint32_t* ap = aptr + kt * 16;
        const uint32_t* bp = bptr + (size_t)kt * 16 * N;
        cpa16((uint32_t)__cvta_generic_to_shared(as + arow * SA + abase), ap);
        cpa16((uint32_t)__cvta_generic_to_shared(as + arow * SA + abase + 4), ap + 4);
        cpa16((uint32_t)__cvta_generic_to_shared(bs + brow * SB + bbase), bp);
        cpa16((uint32_t)__cvta_generic_to_shared(bs + brow * SB + bbase + 4), bp + 4);
    };

#pragma unroll
    for (int s = 0; s < S - 1; s++) { issue(s); cpa_commit(); }

    for (int kt = 0; kt < KT; kt++) {
        cpa_wait<S - 2>();
        __syncthreads();
        if (kt + S - 1 < KT) issue(kt + S - 1);
        cpa_commit();

        const uint32_t abyte = As_sh + ((kt & (S - 1)) * ASTG) * 4;
        const uint32_t* bsU = Bs + (kt & (S - 1)) * BSTG;
#pragma unroll
        for (int ks = 0; ks < 2; ks++) {          // two k16 steps per BK=32
            int kq = ks * 8 + (lane & 3);
            uint32_t af[4][4], bf[4][2];
#pragma unroll
            for (int mt = 0; mt < 4; mt++)
                ldsm4(af[mt][0], af[mt][1], af[mt][2], af[mt][3],
                      abyte + rowoffA[mt] + ks * 32);
#pragma unroll
            for (int nt = 0; nt < 4; nt++) {
                int n = wn * 32 + nt * 8 + (lane >> 2);
                bf[nt][0] = bsU[kq * SB + n];
                bf[nt][1] = bsU[(kq + 4) * SB + n];
            }
#pragma unroll
            for (int mt = 0; mt < 4; mt++)
#pragma unroll
                for (int nt = 0; nt < 4; nt++)
                    mma_f16(acc[mt][nt],
                            af[mt][0], af[mt][1], af[mt][2], af[mt][3],
                            bf[nt][0], bf[nt][1]);
        }
    }

    if (MODE == 4) {
#pragma unroll
        for (int mt = 0; mt < 4; mt++) {
            float pl = 0.0f, ph = 0.0f;
#pragma unroll
            for (int nt = 0; nt < 4; nt++) {
                int col = n0 + wn * 32 + nt * 8 + ((lane & 3) << 1);
                float w0 = wv[col], w1 = wv[col + 1];
                pl += tanhf(acc[mt][nt][0]) * w0 + tanhf(acc[mt][nt][1]) * w1;
                ph += tanhf(acc[mt][nt][2]) * w0 + tanhf(acc[mt][nt][3]) * w1;
            }
            pl += __shfl_xor_sync(0xffffffffu, pl, 1);
            pl += __shfl_xor_sync(0xffffffffu, pl, 2);
            ph += __shfl_xor_sync(0xffffffffu, ph, 1);
            ph += __shfl_xor_sync(0xffffffffu, ph, 2);
            if ((lane & 3) == 0) {
                int r = m0 + wm * 64 + mt * 16 + (lane >> 2);
                atomicAdd(&sc[(r & 255) * T_ + (r >> 8)], pl);
                atomicAdd(&sc[((r + 8) & 255) * T_ + ((r + 8) >> 8)], ph);
            }
        }
    } else {
        const int N2 = N >> 1;
#pragma unroll
        for (int mt = 0; mt < 4; mt++) {
#pragma unroll
            for (int nt = 0; nt < 4; nt++) {
                int r = m0 + wm * 64 + mt * 16 + (lane >> 2);
                int c = n0 + wn * 32 + nt * 8 + ((lane & 3) << 1);
                float v0 = acc[mt][nt][0], v1 = acc[mt][nt][1];
                float v2 = acc[mt][nt][2], v3 = acc[mt][nt][3];
                const float* ar  = aux + (size_t)(r & 255) * auxStride;
                const float* ar8 = aux + (size_t)((r + 8) & 255) * auxStride;
                v0 += ar[c];  v1 += ar[c + 1];
                v2 += ar8[c]; v3 += ar8[c + 1];
                C16[(size_t)r * N2 + (c >> 1)] = pack_h2(v0, v1);
                C16[(size_t)(r + 8) * N2 + (c >> 1)] = pack_h2(v2, v3);
            }
        }
    }
}

// ---------------- small tf32 GEMM (64x64 tiles) -------------------------------
// MODE 0: C = acc;  MODE 1: C = acc + aux[col];  MODE 5: C = tanh(acc + aux[row*S+col])
template<int BM, int BN, int WM, int WN, int MODE>
__global__ void __launch_bounds__((BM/WM)*(BN/WN)*32)
mm_k(const float* __restrict__ A, const float* __restrict__ Bm,
     float* __restrict__ C, int M, int N, int K,
     const float* __restrict__ aux, long long auxStride) {
    constexpr int BK = 16;
    constexpr int NWARP = (BM / WM) * (BN / WN);
    constexpr int NT = NWARP * 32;
    constexpr int SA = BK + 4;
    constexpr int SB = BN + 8;
    constexpr int MT = WM / 16;
    constexpr int NL = WN / 8;
    constexpr int AQ = (BM * 4) / NT;
    constexpr int BQ = (BN * 4) / NT;

    __shared__ __align__(16) uint32_t As[BM][SA];
    __shared__ __align__(16) uint32_t Bs[BK][SB];

    const int tid = threadIdx.x;
    const int lane = tid & 31;
    const int wid = tid >> 5;
    const int wm = wid % (BM / WM);
    const int wn = wid / (BM / WM);
    const int m0 = blockIdx.y * BM;
    const int n0 = blockIdx.x * BN;

    float acc[MT][NL][4];
#pragma unroll
    for (int i = 0; i < MT; i++)
#pragma unroll
        for (int j = 0; j < NL; j++)
#pragma unroll
            for (int q = 0; q < 4; q++) acc[i][j][q] = 0.0f;

    float4 pa[AQ], pb[BQ];
    const int KT = K / BK;

#pragma unroll
    for (int q = 0; q < AQ; q++) {
        int idx = tid + q * NT;
        pa[q] = *(const float4*)(A + (size_t)(m0 + (idx >> 2)) * K + ((idx & 3) << 2));
    }
#pragma unroll
    for (int q = 0; q < BQ; q++) {
        int idx = tid + q * NT;
        pb[q] = *(const float4*)(Bm + (size_t)(idx / (BN / 4)) * N + n0 + ((idx % (BN / 4)) << 2));
    }

    for (int kt = 0; kt < KT; kt++) {
#pragma unroll
        for (int q = 0; q < AQ; q++) {
            int idx = tid + q * NT;
            uint4 v = make_uint4(f2tf32(pa[q].x), f2tf32(pa[q].y),
                                 f2tf32(pa[q].z), f2tf32(pa[q].w));
            *(uint4*)&As[idx >> 2][(idx & 3) << 2] = v;
        }
#pragma unroll
        for (int q = 0; q < BQ; q++) {
            int idx = tid + q * NT;
            uint4 v = make_uint4(f2tf32(pb[q].x), f2tf32(pb[q].y),
                                 f2tf32(pb[q].z), f2tf32(pb[q].w));
            *(uint4*)&Bs[idx / (BN / 4)][(idx % (BN / 4)) << 2] = v;
        }
        __syncthreads();

        if (kt + 1 < KT) {
            int k0 = (kt + 1) * BK;
#pragma unroll
            for (int q = 0; q < AQ; q++) {
                int idx = tid + q * NT;
                pa[q] = *(const float4*)(A + (size_t)(m0 + (idx >> 2)) * K + k0 + ((idx & 3) << 2));
            }
#pragma unroll
            for (int q = 0; q < BQ; q++) {
                int idx = tid + q * NT;
                pb[q] = *(const float4*)(Bm + (size_t)(k0 + idx / (BN / 4)) * N + n0 + ((idx % (BN / 4)) << 2));
            }
        }

#pragma unroll
        for (int ks = 0; ks < 2; ks++) {
            uint32_t af[MT][4];
            uint32_t bf[NL][2];
            int kc = ks * 8 + (lane & 3);
#pragma unroll
            for (int mt = 0; mt < MT; mt++) {
                int r = wm * WM + mt * 16 + (lane >> 2);
                af[mt][0] = As[r][kc];
                af[mt][1] = As[r + 8][kc];
                af[mt][2] = As[r][kc + 4];
                af[mt][3] = As[r + 8][kc + 4];
            }
#pragma unroll
            for (int nt = 0; nt < NL; nt++) {
                int n = wn * WN + nt * 8 + (lane >> 2);
                bf[nt][0] = Bs[kc][n];
                bf[nt][1] = Bs[kc + 4][n];
            }
#pragma unroll
            for (int mt = 0; mt < MT; mt++)
#pragma unroll
                for (int nt = 0; nt < NL; nt++)
                    mma_tf32(acc[mt][nt],
                             af[mt][0], af[mt][1], af[mt][2], af[mt][3],
                             bf[nt][0], bf[nt][1]);
        }
        __syncthreads();
    }

#pragma unroll
    for (int mt = 0; mt < MT; mt++) {
#pragma unroll
        for (int nt = 0; nt < NL; nt++) {
            int r = m0 + wm * WM + mt * 16 + (lane >> 2);
            int c = n0 + wn * WN + nt * 8 + ((lane & 3) << 1);
            float v0 = acc[mt][nt][0], v1 = acc[mt][nt][1];
            float v2 = acc[mt][nt][2], v3 = acc[mt][nt][3];
            if (MODE == 1) {
                v0 += aux[c]; v1 += aux[c + 1];
                v2 += aux[c]; v3 += aux[c + 1];
            }
            if (MODE == 5) {
                const float* ar  = aux + (size_t)r * auxStride;
                const float* ar8 = aux + (size_t)(r + 8) * auxStride;
                v0 = tanhf(v0 + ar[c]);  v1 = tanhf(v1 + ar[c + 1]);
                v2 = tanhf(v2 + ar8[c]); v3 = tanhf(v3 + ar8[c + 1]);
            }
            *(float2*)&C[(size_t)r * N + c] = make_float2(v0, v1);
            *(float2*)&C[(size_t)(r + 8) * N + c] = make_float2(v2, v3);
        }
    }
}

// ---------------- persistent fused LSTM recurrence (bf16 MMA, cp.async) ------
// 6 chunks of k=128 per step, cp.async staged, ldmatrix fragments, 1 sync/chunk.
// Smem (u32): ws 12288 | Ab 2*256*68 = 34816 | slens 256 | nact 128.
__global__ void __launch_bounds__(256, 1)
lstm_persist(const float* __restrict__ W_hh) {
    extern __shared__ uint32_t sm_[];
    uint32_t* ws = sm_;                        // 12288
    uint32_t* Ab = sm_ + 12288;                // 34816
    int* slens = (int*)(sm_ + 12288 + 34816);
    int* nact  = (int*)(sm_ + 12288 + 34816 + 256);

    const int tid = threadIdx.x;
    const int lane = tid & 31;
    const int w = tid >> 5;
    const int nb = blockIdx.x;

    for (int i = tid; i < 12288; i += 256) {
        int nt = i / 3072;
        int rem = i - nt * 3072;
        int k2 = rem >> 3, nn = rem & 7;
        int col = nt * 768 + nb * 8 + nn;
        float w0 = W_hh[(size_t)(2 * k2) * G_ + col];
        float w1 = W_hh[(size_t)(2 * k2 + 1) * G_ + col];
        ws[i] = pack_bf16(w0, w1);
    }
    slens[tid] = g_lens_s[tid];
    __syncthreads();
    for (int i = tid; i < T_; i += 256) {
        int c = 0;
        for (int b = 0; b < B_; b++) c += (slens[b] > i) ? 1 : 0;
        int n32 = (c + 31) & ~31;
        nact[i] = n32 > 256 ? 256 : n32;
    }
    __syncthreads();

    const uint32_t Ab_sh = (uint32_t)__cvta_generic_to_shared(Ab);
    uint32_t rowoffA[2];
#pragma unroll
    for (int mt = 0; mt < 2; mt++)
        rowoffA[mt] = ((w * 32 + mt * 16 + (lane & 15)) * 68 + (lane >> 4) * 4) * 4;

    float c_reg[2][4], h_reg[2][4];
#pragma unroll
    for (int i = 0; i < 2; i++)
#pragma unroll
        for (int q = 0; q < 4; q++) { c_reg[i][q] = 0.0f; h_reg[i][q] = 0.0f; }

    unsigned epoch = 0;

    for (int t = 0; t < T_; t++) {
        const uint32_t* hcur = (const uint32_t*)g_hbuf[t & 1];
        __nv_bfloat16* hnxt = g_hbuf[(t + 1) & 1];
        const int n32 = nact[t];
        const bool sact = (tid < n32);
        const bool wact = (w * 32 < n32);

        float acc[2][4][4];
#pragma unroll
        for (int i = 0; i < 2; i++)
#pragma unroll
            for (int j = 0; j < 4; j++)
#pragma unroll
                for (int q = 0; q < 4; q++) acc[i][j][q] = 0.0f;

        const uint32_t* hrow = hcur + (size_t)tid * 384;
        const uint32_t dstrow = Ab_sh + tid * 68 * 4;

        // stage chunk 0 (64 u32 = 128 bf16 of this thread's row)
        if (sact) {
#pragma unroll
            for (int j = 0; j < 16; j++)
                cpa16(dstrow + j * 16, hrow + j * 4);
        }
        cpa_commit();

        for (int cch = 0; cch < 6; cch++) {
            cpa_wait<0>();
            __syncthreads();       // chunk cch visible; prev compute done
            if (cch < 5) {         // stage chunk cch+1 into other buffer
                if (sact) {
                    uint32_t d = dstrow + (((cch + 1) & 1) ? 17408u * 4u : 0u);
                    const uint32_t* s = hrow + (cch + 1) * 64;
#pragma unroll
                    for (int j = 0; j < 16; j++)
                        cpa16(d + j * 16, s + j * 4);
                }
                cpa_commit();
            }
            if (wact) {
                const uint32_t abyte = Ab_sh + (cch & 1) * 17408 * 4;
#pragma unroll
                for (int s = 0; s < 8; s++) {      // 8 k16 steps per chunk
                    int k2 = cch * 64 + s * 8 + (lane & 3);
                    uint32_t af[2][4], bf[4][2];
#pragma unroll
                    for (int mt = 0; mt < 2; mt++)
                        ldsm4(af[mt][0], af[mt][1], af[mt][2], af[mt][3],
                              abyte + rowoffA[mt] + s * 32);
#pragma unroll
                    for (int nt = 0; nt < 4; nt++) {
                        bf[nt][0] = ws[nt * 3072 + k2 * 8 + (lane >> 2)];
                        bf[nt][1] = ws[nt * 3072 + (k2 + 4) * 8 + (lane >> 2)];
                    }
#pragma unroll
                    for (int mt = 0; mt < 2; mt++)
#pragma unroll
                        for (int nt = 0; nt < 4; nt++)
                            mma_bf16(acc[mt][nt],
                                     af[mt][0], af[mt][1], af[mt][2], af[mt][3],
                                     bf[nt][0], bf[nt][1]);
                }
            }
        }

        // ---- in-register LSTM pointwise (fp16 gin) ----
        int jcol = nb * 8 + ((lane & 3) << 1);
#pragma unroll
        for (int mt = 0; mt < 2; mt++) {
#pragma unroll
            for (int half = 0; half < 2; half++) {
                int r = w * 32 + mt * 16 + (lane >> 2) + half * 8;
                bool valid = (t < slens[r]);
                float2 bi = make_float2(0.f, 0.f), bff = bi, bg = bi, bo = bi;
                if (valid) {
                    const uint32_t* gp = g_gin16 + ((size_t)(t * B_ + r)) * (G_ / 2) + (jcol >> 1);
                    bi  = __half22float2(*(const __half2*)&gp[0]);
                    bff = __half22float2(*(const __half2*)&gp[384]);
                    bg  = __half22float2(*(const __half2*)&gp[768]);
                    bo  = __half22float2(*(const __half2*)&gp[1152]);
                }
                float hv0, hv1;
#pragma unroll
                for (int sub = 0; sub < 2; sub++) {
                    int q = half * 2 + sub;
                    float iv = acc[mt][0][q] + (sub ? bi.y : bi.x);
                    float fv = acc[mt][1][q] + (sub ? bff.y : bff.x);
                    float gv = acc[mt][2][q] + (sub ? bg.y : bg.x);
                    float ov = acc[mt][3][q] + (sub ? bo.y : bo.x);
                    float cn = sigf(fv) * c_reg[mt][q] + sigf(iv) * tanhf(gv);
                    float hn = sigf(ov) * tanhf(cn);
                    c_reg[mt][q] = valid ? cn : c_reg[mt][q];
                    float hv = valid ? hn : h_reg[mt][q];
                    h_reg[mt][q] = hv;
                    if (sub == 0) hv0 = hv; else hv1 = hv;
                }
                *(uint32_t*)&hnxt[(size_t)r * DH_ + jcol] = pack_bf16(hv0, hv1);
                *(float2*)&g_H[((size_t)(t * B_ + r)) * DH_ + jcol] = make_float2(hv0, hv1);
                g_H16[((size_t)(t * B_ + r)) * (DH_ / 2) + (jcol >> 1)] = pack_h2(hv0, hv1);
                if (t == T_ - 1)
                    *(float2*)&g_hlast[(size_t)r * DH_ + jcol] = make_float2(hv0, hv1);
            }
        }

        // ---- grid barrier ----
        __threadfence();
        __syncthreads();
        if (tid == 0) {
            atomicAdd(&g_barcnt, 1u);
            epoch++;
            unsigned target = epoch * NBLK;
            unsigned v;
            do {
                asm volatile("ld.acquire.gpu.global.u32 %0, [%1];"
                             : "=r"(v) : "l"(&g_barcnt));
                if (v < target) __nanosleep(64);
            } while (v < target);
        }
        __syncthreads();
    }
}

// ---------------- masked softmax over t (per sorted batch row) ---------------
__global__ void softmax_kernel() {
    int b = blockIdx.x;
    int t = threadIdx.x;
    int len = g_lens_s[b];
    float s = (t < len) ? g_scores[b * T_ + t] : -1e30f;

    float m = s;
#pragma unroll
    for (int off = 16; off > 0; off >>= 1)
        m = fmaxf(m, __shfl_down_sync(0xffffffffu, m, off));
    __shared__ float sm[4];
    if ((t & 31) == 0) sm[t >> 5] = m;
    __syncthreads();
    if (t == 0) {
        float mm = sm[0];
        mm = fmaxf(mm, sm[1]); mm = fmaxf(mm, sm[2]); mm = fmaxf(mm, sm[3]);
        sm[0] = mm;
    }
    __syncthreads();
    float mx = sm[0];

    float e = (t < len) ? expf(s - mx) : 0.0f;
    float sum = e;
#pragma unroll
    for (int off = 16; off > 0; off >>= 1)
        sum += __shfl_down_sync(0xffffffffu, sum, off);
    __shared__ float ss[4];
    if ((t & 31) == 0) ss[t >> 5] = sum;
    __syncthreads();
    if (t == 0) ss[0] = ss[0] + ss[1] + ss[2] + ss[3];
    __syncthreads();
    g_alpha[b * T_ + t] = e / ss[0];
}

// ---------------- r = sum_t alpha[b,t] * H[t,b,:]  (fp32 H) ------------------
__global__ void rsum_kernel() {
    int b = blockIdx.x;
    int tid = threadIdx.x;
    __shared__ float al[T_];
    __shared__ int slen;
    if (tid < T_) al[tid] = g_alpha[b * T_ + tid];
    if (tid == 0) slen = g_lens_s[b];
    __syncthreads();
    int len = slen;
    float a0 = 0.0f, a1 = 0.0f, a2 = 0.0f;
#pragma unroll 4
    for (int t = 0; t < len; t++) {
        float a = al[t];
        const float* Hr = g_H + ((size_t)(t * B_ + b)) * DH_;
        a0 += a * Hr[tid];
        a1 += a * Hr[tid + 256];
        a2 += a * Hr[tid + 512];
    }
    g_r[b * DH_ + tid] = a0;
    g_r[b * DH_ + tid + 256] = a1;
    g_r[b * DH_ + tid + 512] = a2;
}

// ---------------- logit = h_star @ W_lin + b_lin (unsort at write) -----------
__global__ void logit_kernel(const float* __restrict__ Wl,
                             const float* __restrict__ bl,
                             float* __restrict__ out) {
    int b = blockIdx.x;
    int tid = threadIdx.x;
    float p0 = 0.0f, p1 = 0.0f, p2 = 0.0f;
    for (int j = tid; j < DH_; j += 128) {
        float v = g_hstar[b * DH_ + j];
        p0 += v * Wl[j * 3 + 0];
        p1 += v * Wl[j * 3 + 1];
        p2 += v * Wl[j * 3 + 2];
    }
#pragma unroll
    for (int off = 16; off > 0; off >>= 1) {
        p0 += __shfl_down_sync(0xffffffffu, p0, off);
        p1 += __shfl_down_sync(0xffffffffu, p1, off);
        p2 += __shfl_down_sync(0xffffffffu, p2, off);
    }
    __shared__ float sm[3][4];
    if ((tid & 31) == 0) {
        sm[0][tid >> 5] = p0; sm[1][tid >> 5] = p1; sm[2][tid >> 5] = p2;
    }
    __syncthreads();
    if (tid < 3) {
        float s = sm[tid][0] + sm[tid][1] + sm[tid][2] + sm[tid][3];
        out[g_perm[b] * 3 + tid] = s + bl[tid];
    }
}

// ---------------- launch ------------------------------------------------------
extern "C" void kernel_launch(void* const* d_in, const int* in_sizes, int n_in,
                              void* d_out, int out_size) {
    const int*   sent   = (const int*)d_in[0];
    const int*   target = (const int*)d_in[1];
    const int*   lens   = (const int*)d_in[2];
    const float* emb    = (const float*)d_in[3];
    const float* temb   = (const float*)d_in[4];
    const float* W_ih   = (const float*)d_in[5];   // (1536, 3072)
    const float* W_hh   = (const float*)d_in[6];   // (768, 3072)
    const float* b_lstm = (const float*)d_in[7];   // (3072,)
    const float* Wh     = (const float*)d_in[8];   // (768, 768)
    // d_in[9] = Wv — unused: aspect score term constant over t, cancels in softmax.
    const float* w_att  = (const float*)d_in[10];  // (1536,), first 768 used
    const float* Wp     = (const float*)d_in[11];
    const float* Wx     = (const float*)d_in[12];
    const float* W_lin  = (const float*)d_in[13];  // (768, 3)
    const float* b_lin  = (const float*)d_in[14];
    float* out = (float*)d_out;

    float *ptx, *ptxp, *phlast, *pscores, *pr, *ptmp, *phstar;
    uint32_t *px16, *pwih16, *pwh16, *pgin16, *pH16;
    int *plens_s;
    cudaGetSymbolAddress((void**)&ptx,     g_tx);
    cudaGetSymbolAddress((void**)&ptxp,    g_txp);
    cudaGetSymbolAddress((void**)&phlast,  g_hlast);
    cudaGetSymbolAddress((void**)&pscores, g_scores);
    cudaGetSymbolAddress((void**)&pr,      g_r);
    cudaGetSymbolAddress((void**)&ptmp,    g_tmp);
    cudaGetSymbolAddress((void**)&phstar,  g_hstar);
    cudaGetSymbolAddress((void**)&plens_s, g_lens_s);
    cudaGetSymbolAddress((void**)&px16,    g_x16);
    cudaGetSymbolAddress((void**)&pwih16,  g_wih16);
    cudaGetSymbolAddress((void**)&pwh16,   g_wh16);
    cudaGetSymbolAddress((void**)&pgin16,  g_gin16);
    cudaGetSymbolAddress((void**)&pH16,    g_H16);

    const int LSTM_SMEM = (12288 + 34816) * 4 + 256 * 4 + 128 * 4;  // 189,952 B
    cudaFuncSetAttribute(lstm_persist,
                         cudaFuncAttributeMaxDynamicSharedMemorySize, LSTM_SMEM);
    const int MM2H_SMEM = 4 * (2560 + 2176) * 4;  // 75,776 B
    cudaFuncSetAttribute(mm2h<2, 1>,
                         cudaFuncAttributeMaxDynamicSharedMemorySize, MM2H_SMEM);
    cudaFuncSetAttribute(mm2h<4, 1>,
                         cudaFuncAttributeMaxDynamicSharedMemorySize, MM2H_SMEM);

    // 1. sort batch by length (descending)
    sort_kernel<<<1, B_>>>(lens);

    // 2. gather+convert x -> fp16 (t-major), gather tx (fp32)
    gatherx_kernel<<<B_ * T_ + B_, 192>>>(sent, target, emb, temb);

    // 3. pack W_ih_top / Wh to fp16 pairs
    convw_kernel<<<(384 * G_ + 384 * DH_ + 255) / 256, 256>>>(W_ih, Wh);

    // 4. zero h buffer (bf16), scores, barrier counter
    zeroall_kernel<<<(B_ * DH_ / 2 + 255) / 256, 256>>>();

    // 5. txp = tx @ W_ih[768:,:] + b_lstm      (256 x 3072, K=768, tf32)
    mm_k<64, 64, 32, 32, 1><<<dim3(G_ / 64, B_ / 64), 128>>>(
        ptx, W_ih + (size_t)768 * G_, ptxp, B_, G_, DW_,
        b_lstm, 0);

    // 6. gin = x16 @ Wih16 + txp[bs]   (fp16 MMA, ldmatrix, early-exit)
    mm2h<2, 1><<<dim3(G_ / 128, (B_ * T_) / 128), 256, MM2H_SMEM>>>(
        px16, pwih16, pgin16, G_,
        ptxp, G_, nullptr, nullptr, plens_s);

    // 7. fused persistent LSTM recurrence
    lstm_persist<<<NBLK, 256, LSTM_SMEM>>>(W_hh);

    // 8. attention scores (fp16 MMA, ldmatrix, early-exit)
    mm2h<4, 1><<<dim3(DH_ / 128, (B_ * T_) / 128), 256, MM2H_SMEM>>>(
        pH16, pwh16, nullptr, DH_,
        nullptr, 0, w_att, pscores, plens_s);

    // 9. masked softmax
    softmax_kernel<<<B_, T_>>>();

    // 10. r = alpha . H
    rsum_kernel<<<B_, 256>>>();

    // 11. h_star = tanh(r@Wp + h_last@Wx)
    mm_k<64, 64, 32, 32, 0><<<dim3(DH_ / 64, B_ / 64), 128>>>(
        pr, Wp, ptmp, B_, DH_, DH_, nullptr, 0);
    mm_k<64, 64, 32, 32, 5><<<dim3(DH_ / 64, B_ / 64), 128>>>(
        phlast, Wx, phstar, B_, DH_, DH_, ptmp, DH_);

    // 12. logits (unsorted write)
    logit_kernel<<<B_, 128>>>(W_lin, b_lin, out);
}